// round 2
// baseline (speedup 1.0000x reference)
#include <cuda_runtime.h>
#include <math.h>

#define BB 8
#define TT 1024
#define DD 1024
#define HH 16
#define HS 64
#define NE 8
#define NTOK (BB*TT)        // 8192
#define DFF 4096
#define LN_EPS 1e-5f

// ---------------- scratch (device globals; no runtime allocation) ----------------
__device__ float g_q[(size_t)BB*HH*TT*HS];
__device__ float g_k[(size_t)BB*HH*TT*HS];
__device__ float g_v[(size_t)BB*HH*TT*HS];
__device__ float g_attn[(size_t)NTOK*DD];
__device__ float g_h[(size_t)NTOK*2*DFF];     // pair-indexed rows: rowid = tok*2 + slot
__device__ float g_y[(size_t)NTOK*2*DD];
__device__ float g_wtok[NTOK*2];
__device__ int   g_rows[NE*NTOK];
__device__ int   g_cnt[NE];

// ---------------- utility ----------------
__global__ void zero_counts_kernel() {
    if (threadIdx.x < NE) g_cnt[threadIdx.x] = 0;
}

// ---------------- QKV projection GEMM ----------------
// grid (NTOK/128, 48), block 256. blockIdx.y: part = y>>4 (0=q,1=k,2=v), h = y&15.
__global__ __launch_bounds__(256) void qkv_gemm_kernel(
    const float* __restrict__ X,
    const float* __restrict__ Wq,
    const float* __restrict__ Wk,
    const float* __restrict__ Wv)
{
    __shared__ float As[16][128];
    __shared__ float Bs[16][64];

    int by = blockIdx.y;
    int part = by >> 4;
    int h = by & 15;
    const float* W = (part == 0) ? Wq : (part == 1) ? Wk : Wv;
    float* Out = (part == 0) ? g_q : (part == 1) ? g_k : g_v;

    int row0 = blockIdx.x * 128;
    int tid = threadIdx.x;
    int tx = tid & 15, ty = tid >> 4;

    float acc[8][4];
#pragma unroll
    for (int i = 0; i < 8; i++)
#pragma unroll
        for (int j = 0; j < 4; j++) acc[i][j] = 0.f;

    for (int k0 = 0; k0 < DD; k0 += 16) {
        {
            int kk = tid & 15, mb = tid >> 4;
#pragma unroll
            for (int i = 0; i < 8; i++) {
                int m = mb + i * 16;
                As[kk][m] = X[(size_t)(row0 + m) * DD + k0 + kk];
            }
        }
        {
            int e = tid & 63, kb = tid >> 6;
#pragma unroll
            for (int i = 0; i < 4; i++) {
                int kk = kb + i * 4;
                Bs[kk][e] = W[((size_t)h * DD + k0 + kk) * HS + e];
            }
        }
        __syncthreads();
#pragma unroll
        for (int kk = 0; kk < 16; kk++) {
            float4 a0 = *(const float4*)&As[kk][ty * 8];
            float4 a1 = *(const float4*)&As[kk][ty * 8 + 4];
            float4 b0 = *(const float4*)&Bs[kk][tx * 4];
            float a[8] = {a0.x, a0.y, a0.z, a0.w, a1.x, a1.y, a1.z, a1.w};
            float b[4] = {b0.x, b0.y, b0.z, b0.w};
#pragma unroll
            for (int i = 0; i < 8; i++)
#pragma unroll
                for (int j = 0; j < 4; j++) acc[i][j] += a[i] * b[j];
        }
        __syncthreads();
    }

#pragma unroll
    for (int i = 0; i < 8; i++) {
        int row = row0 + ty * 8 + i;
        int b = row >> 10, t = row & 1023;
        float* dst = Out + (((size_t)b * HH + h) * TT + t) * HS + tx * 4;
        float4 v4 = make_float4(acc[i][0], acc[i][1], acc[i][2], acc[i][3]);
        *(float4*)dst = v4;
    }
}

// ---------------- causal flash attention ----------------
// grid (16, 128), block 64. Each thread owns one query row.
__global__ __launch_bounds__(64) void attn_kernel()
{
    __shared__ float Ks[64][64];
    __shared__ float Vs[64][64];
    __shared__ float Ss[64][64];   // Ss[kk][tid]

    int bh = blockIdx.y;
    int qt = blockIdx.x;
    int tid = threadIdx.x;
    int row = qt * 64 + tid;

    const float* qp = g_q + ((size_t)bh * TT + row) * HS;
    float q[64];
#pragma unroll
    for (int d4 = 0; d4 < 16; d4++) {
        float4 f = ((const float4*)qp)[d4];
        q[d4 * 4 + 0] = f.x; q[d4 * 4 + 1] = f.y;
        q[d4 * 4 + 2] = f.z; q[d4 * 4 + 3] = f.w;
    }
    float acc[64];
#pragma unroll
    for (int d = 0; d < 64; d++) acc[d] = 0.f;
    float mval = -INFINITY, l = 0.f;

    for (int kt = 0; kt <= qt; kt++) {
        int k0 = kt * 64;
        const float* kp = g_k + ((size_t)bh * TT + k0) * HS;
        const float* vp = g_v + ((size_t)bh * TT + k0) * HS;
        __syncthreads();
#pragma unroll
        for (int i = 0; i < 16; i++) {
            int idx = tid + i * 64;
            int r = idx >> 4, c4 = idx & 15;
            ((float4*)Ks[r])[c4] = ((const float4*)(kp + (size_t)r * HS))[c4];
            ((float4*)Vs[r])[c4] = ((const float4*)(vp + (size_t)r * HS))[c4];
        }
        __syncthreads();

        int kmax = (kt == qt) ? (tid + 1) : 64;
        float tmax = -INFINITY;
        for (int kk = 0; kk < kmax; kk++) {
            const float4* kr = (const float4*)Ks[kk];
            float s0 = 0.f, s1 = 0.f, s2 = 0.f, s3 = 0.f;
#pragma unroll
            for (int d4 = 0; d4 < 16; d4++) {
                float4 kv = kr[d4];
                s0 += q[d4 * 4 + 0] * kv.x;
                s1 += q[d4 * 4 + 1] * kv.y;
                s2 += q[d4 * 4 + 2] * kv.z;
                s3 += q[d4 * 4 + 3] * kv.w;
            }
            float ss = ((s0 + s1) + (s2 + s3)) * 0.03125f;
            Ss[kk][tid] = ss;
            tmax = fmaxf(tmax, ss);
        }
        float mnew = fmaxf(mval, tmax);
        float corr = __expf(mval - mnew);
        l *= corr;
#pragma unroll
        for (int d = 0; d < 64; d++) acc[d] *= corr;
        for (int kk = 0; kk < kmax; kk++) {
            float p = __expf(Ss[kk][tid] - mnew);
            l += p;
            const float4* vr = (const float4*)Vs[kk];
#pragma unroll
            for (int d4 = 0; d4 < 16; d4++) {
                float4 vv = vr[d4];
                acc[d4 * 4 + 0] += p * vv.x;
                acc[d4 * 4 + 1] += p * vv.y;
                acc[d4 * 4 + 2] += p * vv.z;
                acc[d4 * 4 + 3] += p * vv.w;
            }
        }
        mval = mnew;
    }

    int b = bh >> 4, h = bh & 15;
    float inv = 1.f / l;
    float* op = g_attn + ((size_t)b * TT + row) * DD + h * HS;
#pragma unroll
    for (int d4 = 0; d4 < 16; d4++) {
        float4 v4 = make_float4(acc[d4 * 4 + 0] * inv, acc[d4 * 4 + 1] * inv,
                                acc[d4 * 4 + 2] * inv, acc[d4 * 4 + 3] * inv);
        ((float4*)op)[d4] = v4;
    }
}

// ---------------- MoE routing: gate + top-2 + softmax + expert lists ----------------
// grid (NTOK/8), block 256 (8 warps, one token per warp)
__global__ __launch_bounds__(256) void route_kernel(
    const float* __restrict__ X, const float* __restrict__ Wg)
{
    int tok = (blockIdx.x * blockDim.x + threadIdx.x) >> 5;
    int lane = threadIdx.x & 31;
    if (tok >= NTOK) return;
    const float* xr = X + (size_t)tok * DD;
    float p[NE];
#pragma unroll
    for (int e = 0; e < NE; e++) p[e] = 0.f;
    for (int d = lane; d < DD; d += 32) {
        float xv = xr[d];
#pragma unroll
        for (int e = 0; e < NE; e++) p[e] += xv * Wg[d * NE + e];
    }
#pragma unroll
    for (int e = 0; e < NE; e++)
#pragma unroll
        for (int off = 16; off; off >>= 1)
            p[e] += __shfl_xor_sync(0xffffffffu, p[e], off);

    if (lane == 0) {
        int i0 = 0; float v0 = p[0];
#pragma unroll
        for (int e = 1; e < NE; e++) if (p[e] > v0) { v0 = p[e]; i0 = e; }
        int i1 = -1; float v1 = -INFINITY;
#pragma unroll
        for (int e = 0; e < NE; e++) if (e != i0 && p[e] > v1) { v1 = p[e]; i1 = e; }
        float e1v = expf(v1 - v0);
        float inv = 1.f / (1.f + e1v);
        g_wtok[tok * 2 + 0] = inv;
        g_wtok[tok * 2 + 1] = e1v * inv;
        int pos0 = atomicAdd(&g_cnt[i0], 1);
        g_rows[i0 * NTOK + pos0] = tok * 2;
        int pos1 = atomicAdd(&g_cnt[i1], 1);
        g_rows[i1 * NTOK + pos1] = tok * 2 + 1;
    }
}

// ---------------- MoE expert GEMM 1: h = relu(x @ W1[e] + b1[e]) ----------------
// grid (64, DFF/64, NE), block 256
__global__ __launch_bounds__(256) void moe_gemm1_kernel(
    const float* __restrict__ X,
    const float* __restrict__ W1,
    const float* __restrict__ b1)
{
    int e = blockIdx.z;
    int cnt = g_cnt[e];
    int m0 = blockIdx.x * 128;
    if (m0 >= cnt) return;
    int col0 = blockIdx.y * 64;

    __shared__ float As[16][128];
    __shared__ float Bs[16][64];
    __shared__ int rowids[128];

    int tid = threadIdx.x;
    if (tid < 128) {
        int m = m0 + tid;
        rowids[tid] = (m < cnt) ? g_rows[e * NTOK + m] : -1;
    }
    __syncthreads();

    float acc[8][4];
#pragma unroll
    for (int i = 0; i < 8; i++)
#pragma unroll
        for (int j = 0; j < 4; j++) acc[i][j] = 0.f;

    const float* Wp = W1 + (size_t)e * DD * DFF;
    int tx = tid & 15, ty = tid >> 4;

    for (int k0 = 0; k0 < DD; k0 += 16) {
        {
            int kk = tid & 15, mb = tid >> 4;
#pragma unroll
            for (int i = 0; i < 8; i++) {
                int m = mb + i * 16;
                int rid = rowids[m];
                int tok = (rid >= 0) ? (rid >> 1) : 0;
                As[kk][m] = X[(size_t)tok * DD + k0 + kk];
            }
        }
        {
            int n = tid & 63, kb = tid >> 6;
#pragma unroll
            for (int i = 0; i < 4; i++) {
                int kk = kb + i * 4;
                Bs[kk][n] = Wp[(size_t)(k0 + kk) * DFF + col0 + n];
            }
        }
        __syncthreads();
#pragma unroll
        for (int kk = 0; kk < 16; kk++) {
            float4 a0 = *(const float4*)&As[kk][ty * 8];
            float4 a1 = *(const float4*)&As[kk][ty * 8 + 4];
            float4 b0 = *(const float4*)&Bs[kk][tx * 4];
            float a[8] = {a0.x, a0.y, a0.z, a0.w, a1.x, a1.y, a1.z, a1.w};
            float b[4] = {b0.x, b0.y, b0.z, b0.w};
#pragma unroll
            for (int i = 0; i < 8; i++)
#pragma unroll
                for (int j = 0; j < 4; j++) acc[i][j] += a[i] * b[j];
        }
        __syncthreads();
    }

    float4 bias = *(const float4*)&b1[(size_t)e * DFF + col0 + tx * 4];
#pragma unroll
    for (int i = 0; i < 8; i++) {
        int m = ty * 8 + i;
        int rid = rowids[m];
        if (rid < 0) continue;
        float* dst = g_h + (size_t)rid * DFF + col0 + tx * 4;
        float4 v4 = make_float4(fmaxf(acc[i][0] + bias.x, 0.f),
                                fmaxf(acc[i][1] + bias.y, 0.f),
                                fmaxf(acc[i][2] + bias.z, 0.f),
                                fmaxf(acc[i][3] + bias.w, 0.f));
        *(float4*)dst = v4;
    }
}

// ---------------- MoE expert GEMM 2: y = h @ W2[e] + b2[e] ----------------
// grid (64, DD/64, NE), block 256
__global__ __launch_bounds__(256) void moe_gemm2_kernel(
    const float* __restrict__ W2,
    const float* __restrict__ b2)
{
    int e = blockIdx.z;
    int cnt = g_cnt[e];
    int m0 = blockIdx.x * 128;
    if (m0 >= cnt) return;
    int col0 = blockIdx.y * 64;

    __shared__ float As[16][128];
    __shared__ float Bs[16][64];
    __shared__ int rowids[128];

    int tid = threadIdx.x;
    if (tid < 128) {
        int m = m0 + tid;
        rowids[tid] = (m < cnt) ? g_rows[e * NTOK + m] : -1;
    }
    __syncthreads();

    float acc[8][4];
#pragma unroll
    for (int i = 0; i < 8; i++)
#pragma unroll
        for (int j = 0; j < 4; j++) acc[i][j] = 0.f;

    const float* Wp = W2 + (size_t)e * DFF * DD;
    int tx = tid & 15, ty = tid >> 4;

    for (int k0 = 0; k0 < DFF; k0 += 16) {
        {
            int kk = tid & 15, mb = tid >> 4;
#pragma unroll
            for (int i = 0; i < 8; i++) {
                int m = mb + i * 16;
                int rid = rowids[m];
                size_t rr = (rid >= 0) ? (size_t)rid : 0;
                As[kk][m] = g_h[rr * DFF + k0 + kk];
            }
        }
        {
            int n = tid & 63, kb = tid >> 6;
#pragma unroll
            for (int i = 0; i < 4; i++) {
                int kk = kb + i * 4;
                Bs[kk][n] = Wp[(size_t)(k0 + kk) * DD + col0 + n];
            }
        }
        __syncthreads();
#pragma unroll
        for (int kk = 0; kk < 16; kk++) {
            float4 a0 = *(const float4*)&As[kk][ty * 8];
            float4 a1 = *(const float4*)&As[kk][ty * 8 + 4];
            float4 b0 = *(const float4*)&Bs[kk][tx * 4];
            float a[8] = {a0.x, a0.y, a0.z, a0.w, a1.x, a1.y, a1.z, a1.w};
            float b[4] = {b0.x, b0.y, b0.z, b0.w};
#pragma unroll
            for (int i = 0; i < 8; i++)
#pragma unroll
                for (int j = 0; j < 4; j++) acc[i][j] += a[i] * b[j];
        }
        __syncthreads();
    }

    float4 bias = *(const float4*)&b2[(size_t)e * DD + col0 + tx * 4];
#pragma unroll
    for (int i = 0; i < 8; i++) {
        int m = ty * 8 + i;
        int rid = rowids[m];
        if (rid < 0) continue;
        float* dst = g_y + (size_t)rid * DD + col0 + tx * 4;
        float4 v4 = make_float4(acc[i][0] + bias.x, acc[i][1] + bias.y,
                                acc[i][2] + bias.z, acc[i][3] + bias.w);
        *(float4*)dst = v4;
    }
}

// ---------------- final: out = x + LN(attn)*g1+be1 + LN(moe)*g2+be2 ----------------
__device__ __forceinline__ float4 block_reduce4(float4 v) {
    __shared__ float4 sh[8];
    __shared__ float4 bc;
    int lane = threadIdx.x & 31, w = threadIdx.x >> 5;
#pragma unroll
    for (int off = 16; off; off >>= 1) {
        v.x += __shfl_xor_sync(0xffffffffu, v.x, off);
        v.y += __shfl_xor_sync(0xffffffffu, v.y, off);
        v.z += __shfl_xor_sync(0xffffffffu, v.z, off);
        v.w += __shfl_xor_sync(0xffffffffu, v.w, off);
    }
    if (lane == 0) sh[w] = v;
    __syncthreads();
    if (w == 0) {
        float4 t = (lane < 8) ? sh[lane] : make_float4(0, 0, 0, 0);
#pragma unroll
        for (int off = 4; off; off >>= 1) {
            t.x += __shfl_xor_sync(0xffffffffu, t.x, off);
            t.y += __shfl_xor_sync(0xffffffffu, t.y, off);
            t.z += __shfl_xor_sync(0xffffffffu, t.z, off);
            t.w += __shfl_xor_sync(0xffffffffu, t.w, off);
        }
        if (lane == 0) bc = t;
    }
    __syncthreads();
    return bc;
}

// grid (NTOK), block 256
__global__ __launch_bounds__(256) void final_kernel(
    const float* __restrict__ X,
    const float* __restrict__ g1, const float* __restrict__ be1,
    const float* __restrict__ g2, const float* __restrict__ be2,
    float* __restrict__ out)
{
    int t = blockIdx.x;
    int tid = threadIdx.x;
    const float* ar = g_attn + (size_t)t * DD;
    const float* y0 = g_y + (size_t)(t * 2) * DD;
    const float* y1 = g_y + (size_t)(t * 2 + 1) * DD;
    float w0 = g_wtok[t * 2], w1 = g_wtok[t * 2 + 1];

    float4 a4 = ((const float4*)ar)[tid];
    float4 y04 = ((const float4*)y0)[tid];
    float4 y14 = ((const float4*)y1)[tid];
    float a[4] = {a4.x, a4.y, a4.z, a4.w};
    float m[4] = {w0 * y04.x + w1 * y14.x, w0 * y04.y + w1 * y14.y,
                  w0 * y04.z + w1 * y14.z, w0 * y04.w + w1 * y14.w};

    float4 s = make_float4(0, 0, 0, 0);  // sa, sa2, sm, sm2
#pragma unroll
    for (int j = 0; j < 4; j++) {
        s.x += a[j]; s.y += a[j] * a[j];
        s.z += m[j]; s.w += m[j] * m[j];
    }
    s = block_reduce4(s);
    const float invD = 1.0f / (float)DD;
    float mua = s.x * invD;
    float vara = fmaxf(s.y * invD - mua * mua, 0.f);
    float rsa = rsqrtf(vara + LN_EPS);
    float mum = s.z * invD;
    float varm = fmaxf(s.w * invD - mum * mum, 0.f);
    float rsm = rsqrtf(varm + LN_EPS);

    float4 x4 = ((const float4*)(X + (size_t)t * DD))[tid];
    float4 g14 = ((const float4*)g1)[tid];
    float4 b14 = ((const float4*)be1)[tid];
    float4 g24 = ((const float4*)g2)[tid];
    float4 b24 = ((const float4*)be2)[tid];
    float xs[4] = {x4.x, x4.y, x4.z, x4.w};
    float g1s[4] = {g14.x, g14.y, g14.z, g14.w};
    float b1s[4] = {b14.x, b14.y, b14.z, b14.w};
    float g2s[4] = {g24.x, g24.y, g24.z, g24.w};
    float b2s[4] = {b24.x, b24.y, b24.z, b24.w};
    float o[4];
#pragma unroll
    for (int j = 0; j < 4; j++) {
        o[j] = xs[j]
             + (a[j] - mua) * rsa * g1s[j] + b1s[j]
             + (m[j] - mum) * rsm * g2s[j] + b2s[j];
    }
    ((float4*)(out + (size_t)t * DD))[tid] = make_float4(o[0], o[1], o[2], o[3]);
}

// ---------------- launch ----------------
extern "C" void kernel_launch(void* const* d_in, const int* in_sizes, int n_in,
                              void* d_out, int out_size)
{
    const float* x   = (const float*)d_in[0];
    const float* Wq  = (const float*)d_in[1];
    const float* Wk  = (const float*)d_in[2];
    const float* Wv  = (const float*)d_in[3];
    const float* Wg  = (const float*)d_in[4];
    const float* W1  = (const float*)d_in[5];
    const float* b1  = (const float*)d_in[6];
    const float* W2  = (const float*)d_in[7];
    const float* b2  = (const float*)d_in[8];
    const float* g1  = (const float*)d_in[9];
    const float* be1 = (const float*)d_in[10];
    const float* g2  = (const float*)d_in[11];
    const float* be2 = (const float*)d_in[12];
    float* out = (float*)d_out;

    zero_counts_kernel<<<1, 32>>>();
    qkv_gemm_kernel<<<dim3(NTOK / 128, 48), 256>>>(x, Wq, Wk, Wv);
    attn_kernel<<<dim3(16, BB * HH), 64>>>();
    route_kernel<<<NTOK / 8, 256>>>(x, Wg);
    moe_gemm1_kernel<<<dim3(64, DFF / 64, NE), 256>>>(x, W1, b1);
    moe_gemm2_kernel<<<dim3(64, DD / 64, NE), 256>>>(W2, b2);
    final_kernel<<<NTOK, 256>>>(x, g1, be1, g2, be2, out);
}

// round 4
// speedup vs baseline: 3.4372x; 3.4372x over previous
#include <cuda_runtime.h>
#include <cstdint>
#include <math.h>

#define BB 8
#define TT 1024
#define DD 1024
#define HH 16
#define HS 64
#define NE 8
#define NTOK (BB*TT)        // 8192
#define DFF 4096
#define LN_EPS 1e-5f

#if defined(__CUDA_ARCH__) && defined(__CUDA_ARCH_FEAT_SM103_ALL)
#define USE_TCGEN05 1
#else
#define USE_TCGEN05 0
#endif

// ---------------- scratch (device globals; no runtime allocation) ----------------
__device__ float g_q[(size_t)BB*HH*TT*HS];
__device__ float g_k[(size_t)BB*HH*TT*HS];
__device__ float g_v[(size_t)BB*HH*TT*HS];
__device__ float g_attn[(size_t)NTOK*DD];
__device__ float g_h[(size_t)NTOK*2*DFF];     // pair-indexed rows: rowid = tok*2 + slot
__device__ float g_y[(size_t)NTOK*2*DD];
__device__ float g_wtok[NTOK*2];
__device__ int   g_rows[NE*NTOK];
__device__ int   g_cnt[NE];

// ---------------- common helpers ----------------
__device__ __forceinline__ uint32_t smem_u32(const void* p) {
    uint32_t a;
    asm("{ .reg .u64 t; cvta.to.shared.u64 t, %1; cvt.u32.u64 %0, t; }" : "=r"(a) : "l"(p));
    return a;
}
__device__ __forceinline__ uint32_t f2tf32(float x) {
    uint32_t r;
    asm("cvt.rna.tf32.f32 %0, %1;" : "=r"(r) : "f"(x));
    return r;
}
#define SWZ(b) ((b) ^ (((b) >> 3) & 0x70))

// mma.sync fallback primitive (valid on any sm_80+ target incl. plain sm_103)
__device__ __forceinline__ void mma_sync_tf32(float* c,
    uint32_t a0, uint32_t a1, uint32_t a2, uint32_t a3,
    uint32_t b0, uint32_t b1)
{
    asm volatile(
        "mma.sync.aligned.m16n8k8.row.col.f32.tf32.tf32.f32 "
        "{%0,%1,%2,%3}, {%4,%5,%6,%7}, {%8,%9}, {%0,%1,%2,%3};"
        : "+f"(c[0]), "+f"(c[1]), "+f"(c[2]), "+f"(c[3])
        : "r"(a0), "r"(a1), "r"(a2), "r"(a3), "r"(b0), "r"(b1));
}

#if USE_TCGEN05
// ---------------- tcgen05 helpers (only compiled for sm_103a passes) ----------------
__device__ __forceinline__ uint32_t elect1() {
    uint32_t p;
    asm volatile("{\n\t.reg .pred p;\n\telect.sync _|p, 0xFFFFFFFF;\n\tselp.b32 %0, 1, 0, p;\n\t}" : "=r"(p));
    return p;
}
#define MBARRIER_INIT(a, c) \
    asm volatile("mbarrier.init.shared.b64 [%0], %1;" :: "r"(a), "r"(c) : "memory")
#define MBARRIER_WAIT_PARITY(mbar_smem_addr, phase_parity) do { \
    uint32_t _mbar = (uint32_t)(mbar_smem_addr); \
    uint32_t _parity = (uint32_t)(phase_parity); \
    uint32_t _done; \
    asm volatile( \
        "{\n\t.reg .pred p;\n\t" \
        "mbarrier.try_wait.parity.acquire.cta.shared::cta.b64 p, [%1], %2;\n\t" \
        "selp.b32 %0, 1, 0, p;\n\t}" \
        : "=r"(_done) : "r"(_mbar), "r"(_parity) : "memory"); \
    if (!_done) { \
        asm volatile( \
            "{\n\t.reg .pred P1;\n\t" \
            "WAIT_LOOP_%=:\n\t" \
            "mbarrier.try_wait.parity.acquire.cta.shared::cta.b64 P1, [%0], %1, 0x989680;\n\t" \
            "@P1 bra.uni WAIT_DONE_%=;\n\t" \
            "bra.uni WAIT_LOOP_%=;\n\t" \
            "WAIT_DONE_%=:\n\t}" \
            :: "r"(_mbar), "r"(_parity) : "memory"); \
    } \
} while (0)
#define TCGEN05_ALLOC(dst, n) \
    asm volatile("tcgen05.alloc.cta_group::1.sync.aligned.shared::cta.b32 [%0], %1;" :: "r"(dst), "r"(n) : "memory")
#define TCGEN05_RELQ() \
    asm volatile("tcgen05.relinquish_alloc_permit.cta_group::1.sync.aligned;")
#define TCGEN05_DEALLOC(t, n) \
    asm volatile("tcgen05.dealloc.cta_group::1.sync.aligned.b32 %0, %1;" :: "r"(t), "r"(n))
#define TCGEN05_COMMIT(mb) \
    asm volatile("tcgen05.commit.cta_group::1.mbarrier::arrive::one.shared::cluster.b64 [%0];" :: "r"(mb) : "memory")
#define TCGEN05_FENCE_AFTER() asm volatile("tcgen05.fence::after_thread_sync;" ::: "memory")
#define TCGEN05_WAIT_LD() asm volatile("tcgen05.wait::ld.sync.aligned;" ::: "memory")
#define FENCE_PROXY() asm volatile("fence.proxy.async.shared::cta;" ::: "memory")

#define TCGEN05_LD_X32(r, tmem_addr) \
    asm volatile( \
        "tcgen05.ld.sync.aligned.32x32b.x32.b32 " \
        "{%0, %1, %2, %3, %4, %5, %6, %7, " \
        " %8, %9, %10, %11, %12, %13, %14, %15, " \
        " %16, %17, %18, %19, %20, %21, %22, %23, " \
        " %24, %25, %26, %27, %28, %29, %30, %31}, [%32];" \
        : "=r"((r)[0]),  "=r"((r)[1]),  "=r"((r)[2]),  "=r"((r)[3]), \
          "=r"((r)[4]),  "=r"((r)[5]),  "=r"((r)[6]),  "=r"((r)[7]), \
          "=r"((r)[8]),  "=r"((r)[9]),  "=r"((r)[10]), "=r"((r)[11]), \
          "=r"((r)[12]), "=r"((r)[13]), "=r"((r)[14]), "=r"((r)[15]), \
          "=r"((r)[16]), "=r"((r)[17]), "=r"((r)[18]), "=r"((r)[19]), \
          "=r"((r)[20]), "=r"((r)[21]), "=r"((r)[22]), "=r"((r)[23]), \
          "=r"((r)[24]), "=r"((r)[25]), "=r"((r)[26]), "=r"((r)[27]), \
          "=r"((r)[28]), "=r"((r)[29]), "=r"((r)[30]), "=r"((r)[31]) \
        : "r"(tmem_addr))

static constexpr uint64_t SMEM_DESC_BASE_SW128 =
    (uint64_t(2) << 61) | (uint64_t(1) << 46) | (uint64_t(64) << 32) | (uint64_t(1) << 16);
#define MAKE_DESC(addr) (SMEM_DESC_BASE_SW128 | ((uint64_t)((addr) >> 4) & 0x3FFF))

// idesc: c=F32(1<<4), a=TF32(2<<7), b=TF32(2<<10), N=128(16<<17), M=128(8<<24)
static constexpr uint32_t IDESC_TF32_M128_N128 =
    (1u << 4) | (2u << 7) | (2u << 10) | (16u << 17) | (8u << 24);

__device__ __forceinline__ void mma_tf32(uint32_t d, uint64_t ad, uint64_t bd,
                                         uint32_t idesc, uint32_t en) {
    asm volatile(
        "{\n\t.reg .pred p;\n\tsetp.ne.u32 p, %4, 0;\n\t"
        "tcgen05.mma.cta_group::1.kind::tf32 [%0], %1, %2, %3, {%5, %5, %5, %5}, p;\n\t}"
        :: "r"(d), "l"(ad), "l"(bd), "r"(idesc), "r"(en), "r"(0u) : "memory");
}
#endif  // USE_TCGEN05

// dynamic smem: [0,32768) A stages, [32768,65536) B stages, [65536, +16896) staging
#define DYN_SMEM_BYTES (65536 + 16896 + 1024)

// ---------------- utility ----------------
__global__ void zero_counts_kernel() {
    if (threadIdx.x < NE) g_cnt[threadIdx.x] = 0;
}

// =======================================================================
// QKV GEMM: grid (64, 24), block 256.
// by: part = by>>3 (q/k/v), h0 = (by&7)*2, 128-wide N tile spans 2 heads.
// =======================================================================
__global__ __launch_bounds__(256) void qkv_tc_kernel(
    const float* __restrict__ X,
    const float* __restrict__ Wq,
    const float* __restrict__ Wk,
    const float* __restrict__ Wv)
{
    const int row0 = blockIdx.x * 128;
    const int by = blockIdx.y;
    const int part = by >> 3;
    const int h0 = (by & 7) * 2;
    const float* W = (part == 0) ? Wq : (part == 1) ? Wk : Wv;
    float* Out = (part == 0) ? g_q : (part == 1) ? g_k : g_v;

    extern __shared__ char dynraw[];
    char* p = (char*)(((uintptr_t)dynraw + 1023) & ~(uintptr_t)1023);
    float* stg = (float*)(p + 65536);
    const int tid = threadIdx.x;

#if USE_TCGEN05
    const uint32_t sb = smem_u32(p);
    __shared__ uint32_t s_tmem;
    __shared__ uint64_t s_mbar[2];
    const uint32_t mb = smem_u32(&s_mbar[0]);
    if (tid == 0) { MBARRIER_INIT(mb, 1); MBARRIER_INIT(mb + 8, 1); }
    if (tid < 32) { TCGEN05_ALLOC(smem_u32(&s_tmem), 128); TCGEN05_RELQ(); }
    __syncthreads();
    const uint32_t tmem = s_tmem;
#else
    const int wid = tid >> 5, lane = tid & 31;
    const int wm = (wid & 1) * 64, wn = (wid >> 1) * 32;
    float acc[4][4][4];
#pragma unroll
    for (int i = 0; i < 4; i++)
#pragma unroll
        for (int j = 0; j < 4; j++)
#pragma unroll
            for (int q = 0; q < 4; q++) acc[i][j][q] = 0.f;
#endif

    const int a_m = tid >> 3, a_k4 = tid & 7;
    const int b_n4 = tid & 31, b_kb = tid >> 5;
    const int NCH = DD / 32;

    for (int c = 0; c < NCH; c++) {
        const int s = c & 1;
#if USE_TCGEN05
        if (c >= 2) MBARRIER_WAIT_PARITY(mb + s * 8, ((c >> 1) - 1) & 1);
#endif
        const int k0 = c * 32;
        // A tile: 128 m x 32 k (K-major, SW128)
#pragma unroll
        for (int i = 0; i < 4; i++) {
            int m = a_m + i * 32;
            float4 v = *(const float4*)(X + (size_t)(row0 + m) * DD + k0 + a_k4 * 4);
            uint4 u = make_uint4(f2tf32(v.x), f2tf32(v.y), f2tf32(v.z), f2tf32(v.w));
            int rel = m * 128 + a_k4 * 16;
            *(uint4*)(p + s * 16384 + SWZ(rel)) = u;
        }
        // B pass 1: gmem (n-contiguous) -> padded staging [32 k][132 n]
#pragma unroll
        for (int i = 0; i < 4; i++) {
            int k = b_kb * 4 + i;
            int head = h0 + (b_n4 >> 4);
            int cidx = (b_n4 & 15) * 4;
            float4 v = *(const float4*)(W + ((size_t)head * DD + k0 + k) * HS + cidx);
            uint4 u = make_uint4(f2tf32(v.x), f2tf32(v.y), f2tf32(v.z), f2tf32(v.w));
            *(uint4*)(stg + k * 132 + b_n4 * 4) = u;
        }
        __syncthreads();
        // B pass 2: staging -> swizzled K-major tile [128 n][32 k]
#pragma unroll
        for (int i = 0; i < 4; i++) {
            int idx = tid + i * 256;
            int n = idx & 127, k4 = idx >> 7;
            const float* sp = stg + (k4 * 4) * 132 + n;
            uint4 u = make_uint4(__float_as_uint(sp[0]), __float_as_uint(sp[132]),
                                 __float_as_uint(sp[264]), __float_as_uint(sp[396]));
            int rel = n * 128 + k4 * 16;
            *(uint4*)(p + 32768 + s * 16384 + SWZ(rel)) = u;
        }
#if USE_TCGEN05
        FENCE_PROXY();
        __syncthreads();
        if (tid < 32 && elect1()) {
            uint64_t ad = MAKE_DESC(sb + s * 16384);
            uint64_t bd = MAKE_DESC(sb + 32768 + s * 16384);
#pragma unroll
            for (int ks = 0; ks < 4; ks++)
                mma_tf32(tmem, ad + ks * 2, bd + ks * 2, IDESC_TF32_M128_N128, (c | ks) != 0);
            TCGEN05_COMMIT(mb + s * 8);
        }
#else
        __syncthreads();
        {
            const char* At = p + s * 16384;
            const char* Bt = p + 32768 + s * 16384;
#pragma unroll
            for (int ks = 0; ks < 4; ks++) {
                int kb = ks * 8 + (lane & 3);
                uint32_t af[4][4];
#pragma unroll
                for (int mt = 0; mt < 4; mt++) {
                    int m = wm + mt * 16 + (lane >> 2);
                    af[mt][0] = *(const uint32_t*)(At + SWZ(m * 128 + kb * 4));
                    af[mt][1] = *(const uint32_t*)(At + SWZ((m + 8) * 128 + kb * 4));
                    af[mt][2] = *(const uint32_t*)(At + SWZ(m * 128 + (kb + 4) * 4));
                    af[mt][3] = *(const uint32_t*)(At + SWZ((m + 8) * 128 + (kb + 4) * 4));
                }
                uint32_t bf[4][2];
#pragma unroll
                for (int nt = 0; nt < 4; nt++) {
                    int n = wn + nt * 8 + (lane >> 2);
                    bf[nt][0] = *(const uint32_t*)(Bt + SWZ(n * 128 + kb * 4));
                    bf[nt][1] = *(const uint32_t*)(Bt + SWZ(n * 128 + (kb + 4) * 4));
                }
#pragma unroll
                for (int mt = 0; mt < 4; mt++)
#pragma unroll
                    for (int nt = 0; nt < 4; nt++)
                        mma_sync_tf32(acc[mt][nt], af[mt][0], af[mt][1], af[mt][2], af[mt][3],
                                      bf[nt][0], bf[nt][1]);
            }
        }
#endif
    }

#if USE_TCGEN05
    { int cl = NCH - 1; MBARRIER_WAIT_PARITY(mb + (cl & 1) * 8, (cl >> 1) & 1); }
    TCGEN05_FENCE_AFTER();
    // epilogue: D[128 m][128 n] from TMEM, staged transpose, coalesced stores
    const int wid = tid >> 5, lid = tid & 31;
    const int sub = wid & 3, half = wid >> 2;
    const int head = h0 + half;
    float* tp = (float*)p + wid * (32 * 33);
    for (int cc = 0; cc < 2; cc++) {
        int cb = half * 64 + cc * 32;
        uint32_t dr[32];
        TCGEN05_LD_X32(dr, tmem + cb);
        TCGEN05_WAIT_LD();
#pragma unroll
        for (int cj = 0; cj < 32; cj++) tp[lid * 33 + cj] = __uint_as_float(dr[cj]);
        __syncwarp();
#pragma unroll
        for (int it = 0; it < 8; it++) {
            int r = it * 4 + (lid >> 3), c4 = lid & 7;
            int grow = row0 + sub * 32 + r;
            int b = grow >> 10, t = grow & 1023;
            float* op = Out + (((size_t)b * HH + head) * TT + t) * HS + cc * 32 + c4 * 4;
            *(float4*)op = make_float4(tp[r * 33 + c4 * 4], tp[r * 33 + c4 * 4 + 1],
                                       tp[r * 33 + c4 * 4 + 2], tp[r * 33 + c4 * 4 + 3]);
        }
        __syncwarp();
    }
    __syncthreads();
    if (tid < 32) TCGEN05_DEALLOC(tmem, 128);
#else
    // register epilogue: float2 stores per fragment
#pragma unroll
    for (int mt = 0; mt < 4; mt++) {
        int r = row0 + wm + mt * 16 + (lane >> 2);
        int r1 = r + 8;
        int b0i = r >> 10, t0 = r & 1023;
        int b1i = r1 >> 10, t1 = r1 & 1023;
#pragma unroll
        for (int nt = 0; nt < 4; nt++) {
            int n = wn + nt * 8 + 2 * (lane & 3);
            int head = h0 + (n >> 6);
            int hs = n & 63;
            float2 v0 = make_float2(acc[mt][nt][0], acc[mt][nt][1]);
            float2 v1 = make_float2(acc[mt][nt][2], acc[mt][nt][3]);
            *(float2*)(Out + (((size_t)b0i * HH + head) * TT + t0) * HS + hs) = v0;
            *(float2*)(Out + (((size_t)b1i * HH + head) * TT + t1) * HS + hs) = v1;
        }
    }
#endif
}

// =======================================================================
// MoE GEMM (templated: G1 = x@W1+relu -> g_h, !G1 = g_h@W2 -> g_y)
// grid (64, Ntiles, NE), block 256
// =======================================================================
template<bool G1>
__global__ __launch_bounds__(256) void moe_tc_kernel(
    const float* __restrict__ X,
    const float* __restrict__ Wfull,
    const float* __restrict__ biasfull)
{
    const int e = blockIdx.z;
    const int cnt = g_cnt[e];
    const int m0 = blockIdx.x * 128;
    if (m0 >= cnt) return;
    const int col0 = blockIdx.y * 128;
    const int KTOT = G1 ? DD : DFF;
    const int LDB  = G1 ? DFF : DD;
    const int LDO  = G1 ? DFF : DD;
    const int NCH = KTOT / 32;

    extern __shared__ char dynraw[];
    char* p = (char*)(((uintptr_t)dynraw + 1023) & ~(uintptr_t)1023);
    float* stg = (float*)(p + 65536);

    __shared__ int rowids[128];
    const int tid = threadIdx.x;
    if (tid < 128) {
        int m = m0 + tid;
        rowids[tid] = (m < cnt) ? g_rows[e * NTOK + m] : -1;
    }

#if USE_TCGEN05
    const uint32_t sb = smem_u32(p);
    __shared__ uint32_t s_tmem;
    __shared__ uint64_t s_mbar[2];
    const uint32_t mb = smem_u32(&s_mbar[0]);
    if (tid == 0) { MBARRIER_INIT(mb, 1); MBARRIER_INIT(mb + 8, 1); }
    if (tid < 32) { TCGEN05_ALLOC(smem_u32(&s_tmem), 128); TCGEN05_RELQ(); }
    __syncthreads();
    const uint32_t tmem = s_tmem;
#else
    __syncthreads();
    const int wid = tid >> 5, lane = tid & 31;
    const int wm = (wid & 1) * 64, wn = (wid >> 1) * 32;
    float acc[4][4][4];
#pragma unroll
    for (int i = 0; i < 4; i++)
#pragma unroll
        for (int j = 0; j < 4; j++)
#pragma unroll
            for (int q = 0; q < 4; q++) acc[i][j][q] = 0.f;
#endif

    const float* Wp = Wfull + (size_t)e * ((size_t)DD * DFF);
    const float* bp = biasfull + (size_t)e * (G1 ? DFF : DD);

    const int a_m = tid >> 3, a_k4 = tid & 7;
    const int b_n4 = tid & 31, b_kb = tid >> 5;

    for (int c = 0; c < NCH; c++) {
        const int s = c & 1;
#if USE_TCGEN05
        if (c >= 2) MBARRIER_WAIT_PARITY(mb + s * 8, ((c >> 1) - 1) & 1);
#endif
        const int k0 = c * 32;
        // A tile (gathered rows)
#pragma unroll
        for (int i = 0; i < 4; i++) {
            int m = a_m + i * 32;
            int rid = rowids[m];
            const float* src;
            if (G1) src = X + (size_t)((rid >= 0) ? (rid >> 1) : 0) * DD;
            else    src = g_h + (size_t)((rid >= 0) ? rid : 0) * DFF;
            float4 v = *(const float4*)(src + k0 + a_k4 * 4);
            uint4 u = make_uint4(f2tf32(v.x), f2tf32(v.y), f2tf32(v.z), f2tf32(v.w));
            int rel = m * 128 + a_k4 * 16;
            *(uint4*)(p + s * 16384 + SWZ(rel)) = u;
        }
        // B pass 1 -> staging
#pragma unroll
        for (int i = 0; i < 4; i++) {
            int k = b_kb * 4 + i;
            float4 v = *(const float4*)(Wp + (size_t)(k0 + k) * LDB + col0 + b_n4 * 4);
            uint4 u = make_uint4(f2tf32(v.x), f2tf32(v.y), f2tf32(v.z), f2tf32(v.w));
            *(uint4*)(stg + k * 132 + b_n4 * 4) = u;
        }
        __syncthreads();
        // B pass 2 -> swizzled K-major tile
#pragma unroll
        for (int i = 0; i < 4; i++) {
            int idx = tid + i * 256;
            int n = idx & 127, k4 = idx >> 7;
            const float* sp = stg + (k4 * 4) * 132 + n;
            uint4 u = make_uint4(__float_as_uint(sp[0]), __float_as_uint(sp[132]),
                                 __float_as_uint(sp[264]), __float_as_uint(sp[396]));
            int rel = n * 128 + k4 * 16;
            *(uint4*)(p + 32768 + s * 16384 + SWZ(rel)) = u;
        }
#if USE_TCGEN05
        FENCE_PROXY();
        __syncthreads();
        if (tid < 32 && elect1()) {
            uint64_t ad = MAKE_DESC(sb + s * 16384);
            uint64_t bd = MAKE_DESC(sb + 32768 + s * 16384);
#pragma unroll
            for (int ks = 0; ks < 4; ks++)
                mma_tf32(tmem, ad + ks * 2, bd + ks * 2, IDESC_TF32_M128_N128, (c | ks) != 0);
            TCGEN05_COMMIT(mb + s * 8);
        }
#else
        __syncthreads();
        {
            const char* At = p + s * 16384;
            const char* Bt = p + 32768 + s * 16384;
#pragma unroll
            for (int ks = 0; ks < 4; ks++) {
                int kb = ks * 8 + (lane & 3);
                uint32_t af[4][4];
#pragma unroll
                for (int mt = 0; mt < 4; mt++) {
                    int m = wm + mt * 16 + (lane >> 2);
                    af[mt][0] = *(const uint32_t*)(At + SWZ(m * 128 + kb * 4));
                    af[mt][1] = *(const uint32_t*)(At + SWZ((m + 8) * 128 + kb * 4));
                    af[mt][2] = *(const uint32_t*)(At + SWZ(m * 128 + (kb + 4) * 4));
                    af[mt][3] = *(const uint32_t*)(At + SWZ((m + 8) * 128 + (kb + 4) * 4));
                }
                uint32_t bf[4][2];
#pragma unroll
                for (int nt = 0; nt < 4; nt++) {
                    int n = wn + nt * 8 + (lane >> 2);
                    bf[nt][0] = *(const uint32_t*)(Bt + SWZ(n * 128 + kb * 4));
                    bf[nt][1] = *(const uint32_t*)(Bt + SWZ(n * 128 + (kb + 4) * 4));
                }
#pragma unroll
                for (int mt = 0; mt < 4; mt++)
#pragma unroll
                    for (int nt = 0; nt < 4; nt++)
                        mma_sync_tf32(acc[mt][nt], af[mt][0], af[mt][1], af[mt][2], af[mt][3],
                                      bf[nt][0], bf[nt][1]);
            }
        }
#endif
    }

    float* Outbase = G1 ? g_h : g_y;
#if USE_TCGEN05
    { int cl = NCH - 1; MBARRIER_WAIT_PARITY(mb + (cl & 1) * 8, (cl >> 1) & 1); }
    TCGEN05_FENCE_AFTER();
    const int wid = tid >> 5, lid = tid & 31;
    const int sub = wid & 3, half = wid >> 2;
    float* tp = (float*)p + wid * (32 * 33);
    for (int cc = 0; cc < 2; cc++) {
        int cb = half * 64 + cc * 32;
        uint32_t dr[32];
        TCGEN05_LD_X32(dr, tmem + cb);
        TCGEN05_WAIT_LD();
#pragma unroll
        for (int cj = 0; cj < 32; cj++) {
            float val = __uint_as_float(dr[cj]) + __ldg(&bp[col0 + cb + cj]);
            if (G1) val = fmaxf(val, 0.f);
            tp[lid * 33 + cj] = val;
        }
        __syncwarp();
#pragma unroll
        for (int it = 0; it < 8; it++) {
            int r = it * 4 + (lid >> 3), c4 = lid & 7;
            int rid = rowids[sub * 32 + r];
            if (rid >= 0) {
                float* op = Outbase + (size_t)rid * LDO + col0 + cb + c4 * 4;
                *(float4*)op = make_float4(tp[r * 33 + c4 * 4], tp[r * 33 + c4 * 4 + 1],
                                           tp[r * 33 + c4 * 4 + 2], tp[r * 33 + c4 * 4 + 3]);
            }
        }
        __syncwarp();
    }
    __syncthreads();
    if (tid < 32) TCGEN05_DEALLOC(tmem, 128);
#else
#pragma unroll
    for (int mt = 0; mt < 4; mt++) {
        int ml = wm + mt * 16 + (lane >> 2);
        int rid0 = rowids[ml];
        int rid1 = rowids[ml + 8];
#pragma unroll
        for (int nt = 0; nt < 4; nt++) {
            int n = col0 + wn + nt * 8 + 2 * (lane & 3);
            float bx = __ldg(&bp[n]), by = __ldg(&bp[n + 1]);
            if (rid0 >= 0) {
                float v0 = acc[mt][nt][0] + bx, v1 = acc[mt][nt][1] + by;
                if (G1) { v0 = fmaxf(v0, 0.f); v1 = fmaxf(v1, 0.f); }
                *(float2*)(Outbase + (size_t)rid0 * LDO + n) = make_float2(v0, v1);
            }
            if (rid1 >= 0) {
                float v2 = acc[mt][nt][2] + bx, v3 = acc[mt][nt][3] + by;
                if (G1) { v2 = fmaxf(v2, 0.f); v3 = fmaxf(v3, 0.f); }
                *(float2*)(Outbase + (size_t)rid1 * LDO + n) = make_float2(v2, v3);
            }
        }
    }
#endif
}

// ---------------- causal flash attention (SIMT fp32) ----------------
__global__ __launch_bounds__(64) void attn_kernel()
{
    __shared__ float Ks[64][64];
    __shared__ float Vs[64][64];
    __shared__ float Ss[64][64];

    int bh = blockIdx.y;
    int qt = blockIdx.x;
    int tid = threadIdx.x;
    int row = qt * 64 + tid;

    const float* qp = g_q + ((size_t)bh * TT + row) * HS;
    float q[64];
#pragma unroll
    for (int d4 = 0; d4 < 16; d4++) {
        float4 f = ((const float4*)qp)[d4];
        q[d4 * 4 + 0] = f.x; q[d4 * 4 + 1] = f.y;
        q[d4 * 4 + 2] = f.z; q[d4 * 4 + 3] = f.w;
    }
    float acc[64];
#pragma unroll
    for (int d = 0; d < 64; d++) acc[d] = 0.f;
    float mval = -INFINITY, l = 0.f;

    for (int kt = 0; kt <= qt; kt++) {
        int k0 = kt * 64;
        const float* kp = g_k + ((size_t)bh * TT + k0) * HS;
        const float* vp = g_v + ((size_t)bh * TT + k0) * HS;
        __syncthreads();
#pragma unroll
        for (int i = 0; i < 16; i++) {
            int idx = tid + i * 64;
            int r = idx >> 4, c4 = idx & 15;
            ((float4*)Ks[r])[c4] = ((const float4*)(kp + (size_t)r * HS))[c4];
            ((float4*)Vs[r])[c4] = ((const float4*)(vp + (size_t)r * HS))[c4];
        }
        __syncthreads();

        int kmax = (kt == qt) ? (tid + 1) : 64;
        float tmax = -INFINITY;
        for (int kk = 0; kk < kmax; kk++) {
            const float4* kr = (const float4*)Ks[kk];
            float s0 = 0.f, s1 = 0.f, s2 = 0.f, s3 = 0.f;
#pragma unroll
            for (int d4 = 0; d4 < 16; d4++) {
                float4 kv = kr[d4];
                s0 += q[d4 * 4 + 0] * kv.x;
                s1 += q[d4 * 4 + 1] * kv.y;
                s2 += q[d4 * 4 + 2] * kv.z;
                s3 += q[d4 * 4 + 3] * kv.w;
            }
            float ss = ((s0 + s1) + (s2 + s3)) * 0.03125f;
            Ss[kk][tid] = ss;
            tmax = fmaxf(tmax, ss);
        }
        float mnew = fmaxf(mval, tmax);
        float corr = __expf(mval - mnew);
        l *= corr;
#pragma unroll
        for (int d = 0; d < 64; d++) acc[d] *= corr;
        for (int kk = 0; kk < kmax; kk++) {
            float pv = __expf(Ss[kk][tid] - mnew);
            l += pv;
            const float4* vr = (const float4*)Vs[kk];
#pragma unroll
            for (int d4 = 0; d4 < 16; d4++) {
                float4 vv = vr[d4];
                acc[d4 * 4 + 0] += pv * vv.x;
                acc[d4 * 4 + 1] += pv * vv.y;
                acc[d4 * 4 + 2] += pv * vv.z;
                acc[d4 * 4 + 3] += pv * vv.w;
            }
        }
        mval = mnew;
    }

    int b = bh >> 4, h = bh & 15;
    float inv = 1.f / l;
    float* op = g_attn + ((size_t)b * TT + row) * DD + h * HS;
#pragma unroll
    for (int d4 = 0; d4 < 16; d4++) {
        float4 v4 = make_float4(acc[d4 * 4 + 0] * inv, acc[d4 * 4 + 1] * inv,
                                acc[d4 * 4 + 2] * inv, acc[d4 * 4 + 3] * inv);
        ((float4*)op)[d4] = v4;
    }
}

// ---------------- MoE routing ----------------
__global__ __launch_bounds__(256) void route_kernel(
    const float* __restrict__ X, const float* __restrict__ Wg)
{
    int tok = (blockIdx.x * blockDim.x + threadIdx.x) >> 5;
    int lane = threadIdx.x & 31;
    if (tok >= NTOK) return;
    const float* xr = X + (size_t)tok * DD;
    float p[NE];
#pragma unroll
    for (int e = 0; e < NE; e++) p[e] = 0.f;
    for (int d = lane; d < DD; d += 32) {
        float xv = xr[d];
#pragma unroll
        for (int e = 0; e < NE; e++) p[e] += xv * Wg[d * NE + e];
    }
#pragma unroll
    for (int e = 0; e < NE; e++)
#pragma unroll
        for (int off = 16; off; off >>= 1)
            p[e] += __shfl_xor_sync(0xffffffffu, p[e], off);

    if (lane == 0) {
        int i0 = 0; float v0 = p[0];
#pragma unroll
        for (int e = 1; e < NE; e++) if (p[e] > v0) { v0 = p[e]; i0 = e; }
        int i1 = -1; float v1 = -INFINITY;
#pragma unroll
        for (int e = 0; e < NE; e++) if (e != i0 && p[e] > v1) { v1 = p[e]; i1 = e; }
        float e1v = expf(v1 - v0);
        float inv = 1.f / (1.f + e1v);
        g_wtok[tok * 2 + 0] = inv;
        g_wtok[tok * 2 + 1] = e1v * inv;
        int pos0 = atomicAdd(&g_cnt[i0], 1);
        g_rows[i0 * NTOK + pos0] = tok * 2;
        int pos1 = atomicAdd(&g_cnt[i1], 1);
        g_rows[i1 * NTOK + pos1] = tok * 2 + 1;
    }
}

// ---------------- final LN+residual ----------------
__device__ __forceinline__ float4 block_reduce4(float4 v) {
    __shared__ float4 sh[8];
    __shared__ float4 bc;
    int lane = threadIdx.x & 31, w = threadIdx.x >> 5;
#pragma unroll
    for (int off = 16; off; off >>= 1) {
        v.x += __shfl_xor_sync(0xffffffffu, v.x, off);
        v.y += __shfl_xor_sync(0xffffffffu, v.y, off);
        v.z += __shfl_xor_sync(0xffffffffu, v.z, off);
        v.w += __shfl_xor_sync(0xffffffffu, v.w, off);
    }
    if (lane == 0) sh[w] = v;
    __syncthreads();
    if (w == 0) {
        float4 t = (lane < 8) ? sh[lane] : make_float4(0, 0, 0, 0);
#pragma unroll
        for (int off = 4; off; off >>= 1) {
            t.x += __shfl_xor_sync(0xffffffffu, t.x, off);
            t.y += __shfl_xor_sync(0xffffffffu, t.y, off);
            t.z += __shfl_xor_sync(0xffffffffu, t.z, off);
            t.w += __shfl_xor_sync(0xffffffffu, t.w, off);
        }
        if (lane == 0) bc = t;
    }
    __syncthreads();
    return bc;
}

__global__ __launch_bounds__(256) void final_kernel(
    const float* __restrict__ X,
    const float* __restrict__ g1, const float* __restrict__ be1,
    const float* __restrict__ g2, const float* __restrict__ be2,
    float* __restrict__ out)
{
    int t = blockIdx.x;
    int tid = threadIdx.x;
    const float* ar = g_attn + (size_t)t * DD;
    const float* y0 = g_y + (size_t)(t * 2) * DD;
    const float* y1 = g_y + (size_t)(t * 2 + 1) * DD;
    float w0 = g_wtok[t * 2], w1 = g_wtok[t * 2 + 1];

    float4 a4 = ((const float4*)ar)[tid];
    float4 y04 = ((const float4*)y0)[tid];
    float4 y14 = ((const float4*)y1)[tid];
    float a[4] = {a4.x, a4.y, a4.z, a4.w};
    float m[4] = {w0 * y04.x + w1 * y14.x, w0 * y04.y + w1 * y14.y,
                  w0 * y04.z + w1 * y14.z, w0 * y04.w + w1 * y14.w};

    float4 s = make_float4(0, 0, 0, 0);
#pragma unroll
    for (int j = 0; j < 4; j++) {
        s.x += a[j]; s.y += a[j] * a[j];
        s.z += m[j]; s.w += m[j] * m[j];
    }
    s = block_reduce4(s);
    const float invD = 1.0f / (float)DD;
    float mua = s.x * invD;
    float vara = fmaxf(s.y * invD - mua * mua, 0.f);
    float rsa = rsqrtf(vara + LN_EPS);
    float mum = s.z * invD;
    float varm = fmaxf(s.w * invD - mum * mum, 0.f);
    float rsm = rsqrtf(varm + LN_EPS);

    float4 x4 = ((const float4*)(X + (size_t)t * DD))[tid];
    float4 g14 = ((const float4*)g1)[tid];
    float4 b14 = ((const float4*)be1)[tid];
    float4 g24 = ((const float4*)g2)[tid];
    float4 b24 = ((const float4*)be2)[tid];
    float xs[4] = {x4.x, x4.y, x4.z, x4.w};
    float g1s[4] = {g14.x, g14.y, g14.z, g14.w};
    float b1s[4] = {b14.x, b14.y, b14.z, b14.w};
    float g2s[4] = {g24.x, g24.y, g24.z, g24.w};
    float b2s[4] = {b24.x, b24.y, b24.z, b24.w};
    float o[4];
#pragma unroll
    for (int j = 0; j < 4; j++) {
        o[j] = xs[j]
             + (a[j] - mua) * rsa * g1s[j] + b1s[j]
             + (m[j] - mum) * rsm * g2s[j] + b2s[j];
    }
    ((float4*)(out + (size_t)t * DD))[tid] = make_float4(o[0], o[1], o[2], o[3]);
}

// ---------------- launch ----------------
extern "C" void kernel_launch(void* const* d_in, const int* in_sizes, int n_in,
                              void* d_out, int out_size)
{
    const float* x   = (const float*)d_in[0];
    const float* Wq  = (const float*)d_in[1];
    const float* Wk  = (const float*)d_in[2];
    const float* Wv  = (const float*)d_in[3];
    const float* Wg  = (const float*)d_in[4];
    const float* W1  = (const float*)d_in[5];
    const float* b1  = (const float*)d_in[6];
    const float* W2  = (const float*)d_in[7];
    const float* b2  = (const float*)d_in[8];
    const float* g1  = (const float*)d_in[9];
    const float* be1 = (const float*)d_in[10];
    const float* g2  = (const float*)d_in[11];
    const float* be2 = (const float*)d_in[12];
    float* out = (float*)d_out;

    cudaFuncSetAttribute(qkv_tc_kernel, cudaFuncAttributeMaxDynamicSharedMemorySize, DYN_SMEM_BYTES);
    cudaFuncSetAttribute(moe_tc_kernel<true>, cudaFuncAttributeMaxDynamicSharedMemorySize, DYN_SMEM_BYTES);
    cudaFuncSetAttribute(moe_tc_kernel<false>, cudaFuncAttributeMaxDynamicSharedMemorySize, DYN_SMEM_BYTES);

    zero_counts_kernel<<<1, 32>>>();
    qkv_tc_kernel<<<dim3(NTOK / 128, 24), 256, DYN_SMEM_BYTES>>>(x, Wq, Wk, Wv);
    attn_kernel<<<dim3(16, BB * HH), 64>>>();
    route_kernel<<<NTOK / 8, 256>>>(x, Wg);
    moe_tc_kernel<true><<<dim3(64, DFF / 128, NE), 256, DYN_SMEM_BYTES>>>(x, W1, b1);
    moe_tc_kernel<false><<<dim3(64, DD / 128, NE), 256, DYN_SMEM_BYTES>>>(x, W2, b2);
    final_kernel<<<NTOK, 256>>>(x, g1, be1, g2, be2, out);
}

// round 5
// speedup vs baseline: 4.2070x; 1.2240x over previous
#include <cuda_runtime.h>
#include <cstdint>
#include <math.h>

#define BB 8
#define TT 1024
#define DD 1024
#define HH 16
#define HS 64
#define NE 8
#define NTOK (BB*TT)        // 8192
#define DFF 4096
#define LN_EPS 1e-5f

// ---------------- scratch (device globals; no runtime allocation) ----------------
__device__ float g_q[(size_t)BB*HH*TT*HS];
__device__ float g_k[(size_t)BB*HH*TT*HS];
__device__ float g_v[(size_t)BB*HH*TT*HS];
__device__ float g_attn[(size_t)NTOK*DD];
__device__ float g_h[(size_t)NTOK*2*DFF];     // pair-indexed rows: rowid = tok*2 + slot
__device__ float g_y[(size_t)NTOK*2*DD];
__device__ float g_wtok[NTOK*2];
__device__ int   g_rows[NE*NTOK];
__device__ int   g_cnt[NE];

// ---------------- helpers ----------------
__device__ __forceinline__ uint32_t smem_u32(const void* p) {
    uint32_t a;
    asm("{ .reg .u64 t; cvta.to.shared.u64 t, %1; cvt.u32.u64 %0, t; }" : "=r"(a) : "l"(p));
    return a;
}
__device__ __forceinline__ uint32_t f2tf32(float x) {
    uint32_t r;
    asm("cvt.rna.tf32.f32 %0, %1;" : "=r"(r) : "f"(x));
    return r;
}
#define SWZ(b) ((b) ^ (((b) >> 3) & 0x70))

__device__ __forceinline__ void mma_sync_tf32(float* c,
    uint32_t a0, uint32_t a1, uint32_t a2, uint32_t a3,
    uint32_t b0, uint32_t b1)
{
    asm volatile(
        "mma.sync.aligned.m16n8k8.row.col.f32.tf32.tf32.f32 "
        "{%0,%1,%2,%3}, {%4,%5,%6,%7}, {%8,%9}, {%0,%1,%2,%3};"
        : "+f"(c[0]), "+f"(c[1]), "+f"(c[2]), "+f"(c[3])
        : "r"(a0), "r"(a1), "r"(a2), "r"(a3), "r"(b0), "r"(b1));
}
__device__ __forceinline__ void ldsm_x4(uint32_t* r, uint32_t addr) {
    asm volatile("ldmatrix.sync.aligned.m8n8.x4.shared.b16 {%0,%1,%2,%3}, [%4];"
        : "=r"(r[0]), "=r"(r[1]), "=r"(r[2]), "=r"(r[3]) : "r"(addr));
}
__device__ __forceinline__ void ldsm_x2(uint32_t* r, uint32_t addr) {
    asm volatile("ldmatrix.sync.aligned.m8n8.x2.shared.b16 {%0,%1}, [%2];"
        : "=r"(r[0]), "=r"(r[1]) : "r"(addr));
}
__device__ __forceinline__ uint4 cvt4(float4 v) {
    return make_uint4(f2tf32(v.x), f2tf32(v.y), f2tf32(v.z), f2tf32(v.w));
}

// dynamic smem GEMM: [0,32768) A stages, [32768,65536) B stages, [65536,+16896) staging
#define DYN_SMEM_BYTES (65536 + 16896 + 1024)

// ---------------- utility ----------------
__global__ void zero_counts_kernel() {
    if (threadIdx.x < NE) g_cnt[threadIdx.x] = 0;
}

// =======================================================================
// QKV GEMM: grid (64, 24), block 256
// =======================================================================
__global__ __launch_bounds__(256) void qkv_tc_kernel(
    const float* __restrict__ X,
    const float* __restrict__ Wq,
    const float* __restrict__ Wk,
    const float* __restrict__ Wv)
{
    const int row0 = blockIdx.x * 128;
    const int by = blockIdx.y;
    const int part = by >> 3;
    const int h0 = (by & 7) * 2;
    const float* W = (part == 0) ? Wq : (part == 1) ? Wk : Wv;
    float* Out = (part == 0) ? g_q : (part == 1) ? g_k : g_v;

    extern __shared__ char dynraw[];
    char* p = (char*)(((uintptr_t)dynraw + 1023) & ~(uintptr_t)1023);
    float* stg = (float*)(p + 65536);
    const uint32_t sb = smem_u32(p);
    const int tid = threadIdx.x;
    const int wid = tid >> 5, lane = tid & 31;
    const int wm = (wid & 1) * 64, wn = (wid >> 1) * 32;

    // ldmatrix per-lane constants
    const int quad = lane >> 3, lr = lane & 7;
    const uint32_t a_rowb = (uint32_t)(wm + (quad & 1) * 8 + lr) * 128;
    const uint32_t a_boff = (uint32_t)(quad >> 1) * 16;
    const uint32_t b_rowb = (uint32_t)(wn + lr) * 128;
    const uint32_t b_boff = (uint32_t)((lane >> 3) & 1) * 16;
    const uint32_t xv = (uint32_t)lr << 4;

    float acc[4][4][4];
#pragma unroll
    for (int i = 0; i < 4; i++)
#pragma unroll
        for (int j = 0; j < 4; j++)
#pragma unroll
            for (int q = 0; q < 4; q++) acc[i][j][q] = 0.f;

    const int a_m = tid >> 3, a_k4 = tid & 7;
    const int b_n4 = tid & 31, b_kb = tid >> 5;
    const int NCH = DD / 32;

    float4 pa[4], pbr[4];
    auto loadA = [&](int c) {
        int k0 = c * 32;
#pragma unroll
        for (int i = 0; i < 4; i++) {
            int m = a_m + i * 32;
            pa[i] = *(const float4*)(X + (size_t)(row0 + m) * DD + k0 + a_k4 * 4);
        }
    };
    auto loadB = [&](int c) {
        int k0 = c * 32;
        int head = h0 + (b_n4 >> 4);
        int cidx = (b_n4 & 15) * 4;
#pragma unroll
        for (int i = 0; i < 4; i++) {
            int k = b_kb * 4 + i;
            pbr[i] = *(const float4*)(W + ((size_t)head * DD + k0 + k) * HS + cidx);
        }
    };
    loadA(0); loadB(0);

    for (int c = 0; c < NCH; c++) {
        const int s = c & 1;
        // STS A (cvt), STS B pass1 to staging
#pragma unroll
        for (int i = 0; i < 4; i++) {
            int m = a_m + i * 32;
            int rel = m * 128 + a_k4 * 16;
            *(uint4*)(p + s * 16384 + SWZ(rel)) = cvt4(pa[i]);
        }
#pragma unroll
        for (int i = 0; i < 4; i++) {
            int k = b_kb * 4 + i;
            *(uint4*)(stg + k * 132 + b_n4 * 4) = cvt4(pbr[i]);
        }
        __syncthreads();
        // B pass2: staging -> swizzled K-major tile
#pragma unroll
        for (int i = 0; i < 4; i++) {
            int idx = tid + i * 256;
            int n = idx & 127, k4 = idx >> 7;
            const float* sp = stg + (k4 * 4) * 132 + n;
            uint4 u = make_uint4(__float_as_uint(sp[0]), __float_as_uint(sp[132]),
                                 __float_as_uint(sp[264]), __float_as_uint(sp[396]));
            int rel = n * 128 + k4 * 16;
            *(uint4*)(p + 32768 + s * 16384 + SWZ(rel)) = u;
        }
        if (c + 1 < NCH) { loadA(c + 1); loadB(c + 1); }
        __syncthreads();
        // MMA via ldmatrix
        {
            const uint32_t At = sb + s * 16384;
            const uint32_t Bt = sb + 32768 + s * 16384;
#pragma unroll
            for (int ks = 0; ks < 4; ks++) {
                uint32_t akoff = (((uint32_t)ks * 32) + a_boff) ^ xv;
                uint32_t bkoff = (((uint32_t)ks * 32) + b_boff) ^ xv;
                uint32_t af[4][4], bf[4][2];
#pragma unroll
                for (int mt = 0; mt < 4; mt++)
                    ldsm_x4(af[mt], At + a_rowb + mt * 2048 + akoff);
#pragma unroll
                for (int nt = 0; nt < 4; nt++)
                    ldsm_x2(bf[nt], Bt + b_rowb + nt * 1024 + bkoff);
#pragma unroll
                for (int mt = 0; mt < 4; mt++)
#pragma unroll
                    for (int nt = 0; nt < 4; nt++)
                        mma_sync_tf32(acc[mt][nt], af[mt][0], af[mt][1], af[mt][2], af[mt][3],
                                      bf[nt][0], bf[nt][1]);
            }
        }
    }

    // epilogue: float2 per fragment
#pragma unroll
    for (int mt = 0; mt < 4; mt++) {
        int r = row0 + wm + mt * 16 + (lane >> 2);
        int r1 = r + 8;
        int b0i = r >> 10, t0 = r & 1023;
        int b1i = r1 >> 10, t1 = r1 & 1023;
#pragma unroll
        for (int nt = 0; nt < 4; nt++) {
            int n = wn + nt * 8 + 2 * (lane & 3);
            int head = h0 + (n >> 6);
            int hs = n & 63;
            *(float2*)(Out + (((size_t)b0i * HH + head) * TT + t0) * HS + hs) =
                make_float2(acc[mt][nt][0], acc[mt][nt][1]);
            *(float2*)(Out + (((size_t)b1i * HH + head) * TT + t1) * HS + hs) =
                make_float2(acc[mt][nt][2], acc[mt][nt][3]);
        }
    }
}

// =======================================================================
// MoE GEMM (G1: x@W1+relu -> g_h, else g_h@W2 -> g_y), grid (64, Ntiles, NE)
// =======================================================================
template<bool G1>
__global__ __launch_bounds__(256) void moe_tc_kernel(
    const float* __restrict__ X,
    const float* __restrict__ Wfull,
    const float* __restrict__ biasfull)
{
    const int e = blockIdx.z;
    const int cnt = g_cnt[e];
    const int m0 = blockIdx.x * 128;
    if (m0 >= cnt) return;
    const int col0 = blockIdx.y * 128;
    const int KTOT = G1 ? DD : DFF;
    const int LDB  = G1 ? DFF : DD;
    const int LDO  = G1 ? DFF : DD;
    const int NCH = KTOT / 32;

    extern __shared__ char dynraw[];
    char* p = (char*)(((uintptr_t)dynraw + 1023) & ~(uintptr_t)1023);
    float* stg = (float*)(p + 65536);
    const uint32_t sb = smem_u32(p);

    __shared__ int rowids[128];
    const int tid = threadIdx.x;
    if (tid < 128) {
        int m = m0 + tid;
        rowids[tid] = (m < cnt) ? g_rows[e * NTOK + m] : -1;
    }
    __syncthreads();

    const int wid = tid >> 5, lane = tid & 31;
    const int wm = (wid & 1) * 64, wn = (wid >> 1) * 32;
    const int quad = lane >> 3, lr = lane & 7;
    const uint32_t a_rowb = (uint32_t)(wm + (quad & 1) * 8 + lr) * 128;
    const uint32_t a_boff = (uint32_t)(quad >> 1) * 16;
    const uint32_t b_rowb = (uint32_t)(wn + lr) * 128;
    const uint32_t b_boff = (uint32_t)((lane >> 3) & 1) * 16;
    const uint32_t xv = (uint32_t)lr << 4;

    float acc[4][4][4];
#pragma unroll
    for (int i = 0; i < 4; i++)
#pragma unroll
        for (int j = 0; j < 4; j++)
#pragma unroll
            for (int q = 0; q < 4; q++) acc[i][j][q] = 0.f;

    const float* Wp = Wfull + (size_t)e * ((size_t)DD * DFF);
    const float* bp = biasfull + (size_t)e * (G1 ? DFF : DD);

    const int a_m = tid >> 3, a_k4 = tid & 7;
    const int b_n4 = tid & 31, b_kb = tid >> 5;

    float4 pa[4], pbr[4];
    auto loadA = [&](int c) {
        int k0 = c * 32;
#pragma unroll
        for (int i = 0; i < 4; i++) {
            int m = a_m + i * 32;
            int rid = rowids[m];
            const float* src;
            if (G1) src = X + (size_t)((rid >= 0) ? (rid >> 1) : 0) * DD;
            else    src = g_h + (size_t)((rid >= 0) ? rid : 0) * DFF;
            pa[i] = *(const float4*)(src + k0 + a_k4 * 4);
        }
    };
    auto loadB = [&](int c) {
        int k0 = c * 32;
#pragma unroll
        for (int i = 0; i < 4; i++) {
            int k = b_kb * 4 + i;
            pbr[i] = *(const float4*)(Wp + (size_t)(k0 + k) * LDB + col0 + b_n4 * 4);
        }
    };
    loadA(0); loadB(0);

    for (int c = 0; c < NCH; c++) {
        const int s = c & 1;
#pragma unroll
        for (int i = 0; i < 4; i++) {
            int m = a_m + i * 32;
            int rel = m * 128 + a_k4 * 16;
            *(uint4*)(p + s * 16384 + SWZ(rel)) = cvt4(pa[i]);
        }
#pragma unroll
        for (int i = 0; i < 4; i++) {
            int k = b_kb * 4 + i;
            *(uint4*)(stg + k * 132 + b_n4 * 4) = cvt4(pbr[i]);
        }
        __syncthreads();
#pragma unroll
        for (int i = 0; i < 4; i++) {
            int idx = tid + i * 256;
            int n = idx & 127, k4 = idx >> 7;
            const float* sp = stg + (k4 * 4) * 132 + n;
            uint4 u = make_uint4(__float_as_uint(sp[0]), __float_as_uint(sp[132]),
                                 __float_as_uint(sp[264]), __float_as_uint(sp[396]));
            int rel = n * 128 + k4 * 16;
            *(uint4*)(p + 32768 + s * 16384 + SWZ(rel)) = u;
        }
        if (c + 1 < NCH) { loadA(c + 1); loadB(c + 1); }
        __syncthreads();
        {
            const uint32_t At = sb + s * 16384;
            const uint32_t Bt = sb + 32768 + s * 16384;
#pragma unroll
            for (int ks = 0; ks < 4; ks++) {
                uint32_t akoff = (((uint32_t)ks * 32) + a_boff) ^ xv;
                uint32_t bkoff = (((uint32_t)ks * 32) + b_boff) ^ xv;
                uint32_t af[4][4], bf[4][2];
#pragma unroll
                for (int mt = 0; mt < 4; mt++)
                    ldsm_x4(af[mt], At + a_rowb + mt * 2048 + akoff);
#pragma unroll
                for (int nt = 0; nt < 4; nt++)
                    ldsm_x2(bf[nt], Bt + b_rowb + nt * 1024 + bkoff);
#pragma unroll
                for (int mt = 0; mt < 4; mt++)
#pragma unroll
                    for (int nt = 0; nt < 4; nt++)
                        mma_sync_tf32(acc[mt][nt], af[mt][0], af[mt][1], af[mt][2], af[mt][3],
                                      bf[nt][0], bf[nt][1]);
            }
        }
    }

    float* Outbase = G1 ? g_h : g_y;
#pragma unroll
    for (int mt = 0; mt < 4; mt++) {
        int ml = wm + mt * 16 + (lane >> 2);
        int rid0 = rowids[ml];
        int rid1 = rowids[ml + 8];
#pragma unroll
        for (int nt = 0; nt < 4; nt++) {
            int n = col0 + wn + nt * 8 + 2 * (lane & 3);
            float bx = __ldg(&bp[n]), by = __ldg(&bp[n + 1]);
            if (rid0 >= 0) {
                float v0 = acc[mt][nt][0] + bx, v1 = acc[mt][nt][1] + by;
                if (G1) { v0 = fmaxf(v0, 0.f); v1 = fmaxf(v1, 0.f); }
                *(float2*)(Outbase + (size_t)rid0 * LDO + n) = make_float2(v0, v1);
            }
            if (rid1 >= 0) {
                float v2 = acc[mt][nt][2] + bx, v3 = acc[mt][nt][3] + by;
                if (G1) { v2 = fmaxf(v2, 0.f); v3 = fmaxf(v3, 0.f); }
                *(float2*)(Outbase + (size_t)rid1 * LDO + n) = make_float2(v2, v3);
            }
        }
    }
}

// =======================================================================
// Tensor-core causal flash attention: grid (16, 128), block 128 (4 warps)
// Each CTA: 64 q-rows. smem: Ps(=Qs) 64x68, Ks 64x68, Vs 64x72 (floats)
// =======================================================================
#define ALD 68
#define VLD 72
#define ATT_SMEM ((64*ALD + 64*ALD + 64*VLD) * 4)

__global__ __launch_bounds__(128) void attn_tc_kernel()
{
    extern __shared__ float asf[];
    float* Ps = asf;              // doubles as Q staging
    float* Ks = asf + 64 * ALD;
    float* Vs = Ks + 64 * ALD;

    const int bh = blockIdx.y;
    const int qt = 15 - blockIdx.x;
    const int tid = threadIdx.x;
    const int wid = tid >> 5, lane = tid & 31;
    const int gid = lane >> 2, tq = lane & 3;
    const int qrow = wid * 16 + gid;       // local q row for fragment row-group
    const int qglob = qt * 64;

    // load Q tile, pre-scaled by 2^-5 (exact), converted to tf32 bits
    {
        const float* qp = g_q + ((size_t)bh * TT + qglob) * HS;
#pragma unroll
        for (int i = 0; i < 8; i++) {
            int idx = tid + i * 128;
            int r = idx >> 4, c4 = (idx & 15) * 4;
            float4 v = *(const float4*)(qp + (size_t)r * HS + c4);
            v.x *= 0.03125f; v.y *= 0.03125f; v.z *= 0.03125f; v.w *= 0.03125f;
            *(uint4*)(Ps + r * ALD + c4) = cvt4(v);
        }
    }
    __syncthreads();
    // Q fragments (register-resident for whole kernel)
    uint32_t qf[8][4];
    {
        const uint32_t* Pu = (const uint32_t*)Ps;
#pragma unroll
        for (int ks = 0; ks < 8; ks++) {
            qf[ks][0] = Pu[qrow * ALD + ks * 8 + tq];
            qf[ks][1] = Pu[(qrow + 8) * ALD + ks * 8 + tq];
            qf[ks][2] = Pu[qrow * ALD + ks * 8 + tq + 4];
            qf[ks][3] = Pu[(qrow + 8) * ALD + ks * 8 + tq + 4];
        }
    }
    __syncthreads();   // Ps free for P reuse

    float oacc[8][4];
#pragma unroll
    for (int i = 0; i < 8; i++)
#pragma unroll
        for (int j = 0; j < 4; j++) oacc[i][j] = 0.f;
    float m0 = -INFINITY, m1 = -INFINITY, l0 = 0.f, l1 = 0.f;

    for (int kt = 0; kt <= qt; kt++) {
        // load K/V tiles (cvt to tf32 bits)
        {
            const float* kp = g_k + ((size_t)bh * TT + kt * 64) * HS;
            const float* vp = g_v + ((size_t)bh * TT + kt * 64) * HS;
#pragma unroll
            for (int i = 0; i < 8; i++) {
                int idx = tid + i * 128;
                int r = idx >> 4, c4 = (idx & 15) * 4;
                *(uint4*)(Ks + r * ALD + c4) = cvt4(*(const float4*)(kp + (size_t)r * HS + c4));
                *(uint4*)(Vs + r * VLD + c4) = cvt4(*(const float4*)(vp + (size_t)r * HS + c4));
            }
        }
        __syncthreads();

        // S = Q K^T  (16 q-rows x 64 s per warp)
        float sacc[8][4];
#pragma unroll
        for (int nt = 0; nt < 8; nt++)
#pragma unroll
            for (int j = 0; j < 4; j++) sacc[nt][j] = 0.f;
        {
            const uint32_t* Ku = (const uint32_t*)Ks;
#pragma unroll
            for (int ks = 0; ks < 8; ks++) {
#pragma unroll
                for (int nt = 0; nt < 8; nt++) {
                    uint32_t b0 = Ku[(nt * 8 + gid) * ALD + ks * 8 + tq];
                    uint32_t b1 = Ku[(nt * 8 + gid) * ALD + ks * 8 + tq + 4];
                    mma_sync_tf32(sacc[nt], qf[ks][0], qf[ks][1], qf[ks][2], qf[ks][3], b0, b1);
                }
            }
        }
        // causal mask on diagonal tile
        if (kt == qt) {
#pragma unroll
            for (int nt = 0; nt < 8; nt++) {
                int col = nt * 8 + 2 * tq;
                if (col     > qrow)     sacc[nt][0] = -INFINITY;
                if (col + 1 > qrow)     sacc[nt][1] = -INFINITY;
                if (col     > qrow + 8) sacc[nt][2] = -INFINITY;
                if (col + 1 > qrow + 8) sacc[nt][3] = -INFINITY;
            }
        }
        // online softmax
        float r0 = -INFINITY, r1 = -INFINITY;
#pragma unroll
        for (int nt = 0; nt < 8; nt++) {
            r0 = fmaxf(r0, fmaxf(sacc[nt][0], sacc[nt][1]));
            r1 = fmaxf(r1, fmaxf(sacc[nt][2], sacc[nt][3]));
        }
        r0 = fmaxf(r0, __shfl_xor_sync(0xffffffffu, r0, 1));
        r0 = fmaxf(r0, __shfl_xor_sync(0xffffffffu, r0, 2));
        r1 = fmaxf(r1, __shfl_xor_sync(0xffffffffu, r1, 1));
        r1 = fmaxf(r1, __shfl_xor_sync(0xffffffffu, r1, 2));
        float mn0 = fmaxf(m0, r0), mn1 = fmaxf(m1, r1);
        float c0 = __expf(m0 - mn0), c1 = __expf(m1 - mn1);
        float ps0 = 0.f, ps1 = 0.f;
        {
            uint32_t* Pu = (uint32_t*)Ps;
#pragma unroll
            for (int nt = 0; nt < 8; nt++) {
                float p0 = __expf(sacc[nt][0] - mn0);
                float p1 = __expf(sacc[nt][1] - mn0);
                float p2 = __expf(sacc[nt][2] - mn1);
                float p3 = __expf(sacc[nt][3] - mn1);
                ps0 += p0 + p1; ps1 += p2 + p3;
                int col = nt * 8 + 2 * tq;
                *(uint2*)(Pu + qrow * ALD + col)       = make_uint2(f2tf32(p0), f2tf32(p1));
                *(uint2*)(Pu + (qrow + 8) * ALD + col) = make_uint2(f2tf32(p2), f2tf32(p3));
            }
        }
        ps0 += __shfl_xor_sync(0xffffffffu, ps0, 1);
        ps0 += __shfl_xor_sync(0xffffffffu, ps0, 2);
        ps1 += __shfl_xor_sync(0xffffffffu, ps1, 1);
        ps1 += __shfl_xor_sync(0xffffffffu, ps1, 2);
        l0 = l0 * c0 + ps0;
        l1 = l1 * c1 + ps1;
#pragma unroll
        for (int dt = 0; dt < 8; dt++) {
            oacc[dt][0] *= c0; oacc[dt][1] *= c0;
            oacc[dt][2] *= c1; oacc[dt][3] *= c1;
        }
        m0 = mn0; m1 = mn1;
        __syncwarp();
        // O += P V
        {
            const uint32_t* Pu = (const uint32_t*)Ps;
            const uint32_t* Vu = (const uint32_t*)Vs;
#pragma unroll
            for (int ks = 0; ks < 8; ks++) {
                uint32_t pa0 = Pu[qrow * ALD + ks * 8 + tq];
                uint32_t pa1 = Pu[(qrow + 8) * ALD + ks * 8 + tq];
                uint32_t pa2 = Pu[qrow * ALD + ks * 8 + tq + 4];
                uint32_t pa3 = Pu[(qrow + 8) * ALD + ks * 8 + tq + 4];
#pragma unroll
                for (int dt = 0; dt < 8; dt++) {
                    uint32_t b0 = Vu[(ks * 8 + tq) * VLD + dt * 8 + gid];
                    uint32_t b1 = Vu[(ks * 8 + tq + 4) * VLD + dt * 8 + gid];
                    mma_sync_tf32(oacc[dt], pa0, pa1, pa2, pa3, b0, b1);
                }
            }
        }
        __syncthreads();   // before next kt overwrites K/V
    }

    // epilogue
    float i0 = 1.f / l0, i1 = 1.f / l1;
    int b = bh >> 4, h = bh & 15;
    int gq0 = qglob + qrow, gq1 = gq0 + 8;
#pragma unroll
    for (int dt = 0; dt < 8; dt++) {
        int d = h * HS + dt * 8 + 2 * tq;
        *(float2*)(g_attn + ((size_t)b * TT + gq0) * DD + d) =
            make_float2(oacc[dt][0] * i0, oacc[dt][1] * i0);
        *(float2*)(g_attn + ((size_t)b * TT + gq1) * DD + d) =
            make_float2(oacc[dt][2] * i1, oacc[dt][3] * i1);
    }
}

// ---------------- MoE routing ----------------
__global__ __launch_bounds__(256) void route_kernel(
    const float* __restrict__ X, const float* __restrict__ Wg)
{
    int tok = (blockIdx.x * blockDim.x + threadIdx.x) >> 5;
    int lane = threadIdx.x & 31;
    if (tok >= NTOK) return;
    const float* xr = X + (size_t)tok * DD;
    float p[NE];
#pragma unroll
    for (int e = 0; e < NE; e++) p[e] = 0.f;
    for (int d = lane; d < DD; d += 32) {
        float xv = xr[d];
#pragma unroll
        for (int e = 0; e < NE; e++) p[e] += xv * Wg[d * NE + e];
    }
#pragma unroll
    for (int e = 0; e < NE; e++)
#pragma unroll
        for (int off = 16; off; off >>= 1)
            p[e] += __shfl_xor_sync(0xffffffffu, p[e], off);

    if (lane == 0) {
        int i0 = 0; float v0 = p[0];
#pragma unroll
        for (int e = 1; e < NE; e++) if (p[e] > v0) { v0 = p[e]; i0 = e; }
        int i1 = -1; float v1 = -INFINITY;
#pragma unroll
        for (int e = 0; e < NE; e++) if (e != i0 && p[e] > v1) { v1 = p[e]; i1 = e; }
        float e1v = expf(v1 - v0);
        float inv = 1.f / (1.f + e1v);
        g_wtok[tok * 2 + 0] = inv;
        g_wtok[tok * 2 + 1] = e1v * inv;
        int pos0 = atomicAdd(&g_cnt[i0], 1);
        g_rows[i0 * NTOK + pos0] = tok * 2;
        int pos1 = atomicAdd(&g_cnt[i1], 1);
        g_rows[i1 * NTOK + pos1] = tok * 2 + 1;
    }
}

// ---------------- final LN+residual ----------------
__device__ __forceinline__ float4 block_reduce4(float4 v) {
    __shared__ float4 sh[8];
    __shared__ float4 bc;
    int lane = threadIdx.x & 31, w = threadIdx.x >> 5;
#pragma unroll
    for (int off = 16; off; off >>= 1) {
        v.x += __shfl_xor_sync(0xffffffffu, v.x, off);
        v.y += __shfl_xor_sync(0xffffffffu, v.y, off);
        v.z += __shfl_xor_sync(0xffffffffu, v.z, off);
        v.w += __shfl_xor_sync(0xffffffffu, v.w, off);
    }
    if (lane == 0) sh[w] = v;
    __syncthreads();
    if (w == 0) {
        float4 t = (lane < 8) ? sh[lane] : make_float4(0, 0, 0, 0);
#pragma unroll
        for (int off = 4; off; off >>= 1) {
            t.x += __shfl_xor_sync(0xffffffffu, t.x, off);
            t.y += __shfl_xor_sync(0xffffffffu, t.y, off);
            t.z += __shfl_xor_sync(0xffffffffu, t.z, off);
            t.w += __shfl_xor_sync(0xffffffffu, t.w, off);
        }
        if (lane == 0) bc = t;
    }
    __syncthreads();
    return bc;
}

__global__ __launch_bounds__(256) void final_kernel(
    const float* __restrict__ X,
    const float* __restrict__ g1, const float* __restrict__ be1,
    const float* __restrict__ g2, const float* __restrict__ be2,
    float* __restrict__ out)
{
    int t = blockIdx.x;
    int tid = threadIdx.x;
    const float* ar = g_attn + (size_t)t * DD;
    const float* y0 = g_y + (size_t)(t * 2) * DD;
    const float* y1 = g_y + (size_t)(t * 2 + 1) * DD;
    float w0 = g_wtok[t * 2], w1 = g_wtok[t * 2 + 1];

    float4 a4 = ((const float4*)ar)[tid];
    float4 y04 = ((const float4*)y0)[tid];
    float4 y14 = ((const float4*)y1)[tid];
    float a[4] = {a4.x, a4.y, a4.z, a4.w};
    float m[4] = {w0 * y04.x + w1 * y14.x, w0 * y04.y + w1 * y14.y,
                  w0 * y04.z + w1 * y14.z, w0 * y04.w + w1 * y14.w};

    float4 s = make_float4(0, 0, 0, 0);
#pragma unroll
    for (int j = 0; j < 4; j++) {
        s.x += a[j]; s.y += a[j] * a[j];
        s.z += m[j]; s.w += m[j] * m[j];
    }
    s = block_reduce4(s);
    const float invD = 1.0f / (float)DD;
    float mua = s.x * invD;
    float vara = fmaxf(s.y * invD - mua * mua, 0.f);
    float rsa = rsqrtf(vara + LN_EPS);
    float mum = s.z * invD;
    float varm = fmaxf(s.w * invD - mum * mum, 0.f);
    float rsm = rsqrtf(varm + LN_EPS);

    float4 x4 = ((const float4*)(X + (size_t)t * DD))[tid];
    float4 g14 = ((const float4*)g1)[tid];
    float4 b14 = ((const float4*)be1)[tid];
    float4 g24 = ((const float4*)g2)[tid];
    float4 b24 = ((const float4*)be2)[tid];
    float xs[4] = {x4.x, x4.y, x4.z, x4.w};
    float g1s[4] = {g14.x, g14.y, g14.z, g14.w};
    float b1s[4] = {b14.x, b14.y, b14.z, b14.w};
    float g2s[4] = {g24.x, g24.y, g24.z, g24.w};
    float b2s[4] = {b24.x, b24.y, b24.z, b24.w};
    float o[4];
#pragma unroll
    for (int j = 0; j < 4; j++) {
        o[j] = xs[j]
             + (a[j] - mua) * rsa * g1s[j] + b1s[j]
             + (m[j] - mum) * rsm * g2s[j] + b2s[j];
    }
    ((float4*)(out + (size_t)t * DD))[tid] = make_float4(o[0], o[1], o[2], o[3]);
}

// ---------------- launch ----------------
extern "C" void kernel_launch(void* const* d_in, const int* in_sizes, int n_in,
                              void* d_out, int out_size)
{
    const float* x   = (const float*)d_in[0];
    const float* Wq  = (const float*)d_in[1];
    const float* Wk  = (const float*)d_in[2];
    const float* Wv  = (const float*)d_in[3];
    const float* Wg  = (const float*)d_in[4];
    const float* W1  = (const float*)d_in[5];
    const float* b1  = (const float*)d_in[6];
    const float* W2  = (const float*)d_in[7];
    const float* b2  = (const float*)d_in[8];
    const float* g1  = (const float*)d_in[9];
    const float* be1 = (const float*)d_in[10];
    const float* g2  = (const float*)d_in[11];
    const float* be2 = (const float*)d_in[12];
    float* out = (float*)d_out;

    cudaFuncSetAttribute(qkv_tc_kernel, cudaFuncAttributeMaxDynamicSharedMemorySize, DYN_SMEM_BYTES);
    cudaFuncSetAttribute(moe_tc_kernel<true>, cudaFuncAttributeMaxDynamicSharedMemorySize, DYN_SMEM_BYTES);
    cudaFuncSetAttribute(moe_tc_kernel<false>, cudaFuncAttributeMaxDynamicSharedMemorySize, DYN_SMEM_BYTES);
    cudaFuncSetAttribute(attn_tc_kernel, cudaFuncAttributeMaxDynamicSharedMemorySize, ATT_SMEM);

    zero_counts_kernel<<<1, 32>>>();
    qkv_tc_kernel<<<dim3(NTOK / 128, 24), 256, DYN_SMEM_BYTES>>>(x, Wq, Wk, Wv);
    attn_tc_kernel<<<dim3(16, BB * HH), 128, ATT_SMEM>>>();
    route_kernel<<<NTOK / 8, 256>>>(x, Wg);
    moe_tc_kernel<true><<<dim3(64, DFF / 128, NE), 256, DYN_SMEM_BYTES>>>(x, W1, b1);
    moe_tc_kernel<false><<<dim3(64, DD / 128, NE), 256, DYN_SMEM_BYTES>>>(x, W2, b2);
    final_kernel<<<NTOK, 256>>>(x, g1, be1, g2, be2, out);
}

// round 6
// speedup vs baseline: 6.0928x; 1.4482x over previous
#include <cuda_runtime.h>
#include <cstdint>
#include <math.h>

#define BB 8
#define TT 1024
#define DD 1024
#define HH 16
#define HS 64
#define NE 8
#define NTOK (BB*TT)        // 8192
#define DFF 4096
#define LN_EPS 1e-5f

// ---------------- scratch (device globals; no runtime allocation) ----------------
__device__ float g_q[(size_t)BB*HH*TT*HS];       // tf32 bits, Q pre-scaled by 2^-5
__device__ float g_k[(size_t)BB*HH*TT*HS];       // tf32 bits
__device__ float g_v[(size_t)BB*HH*TT*HS];       // tf32 bits
__device__ float g_attn[(size_t)NTOK*DD];        // fp32
__device__ float g_h[(size_t)NTOK*2*DFF];        // tf32 bits (post-relu)
__device__ float g_y[(size_t)NTOK*2*DD];         // fp32
__device__ float g_wtok[NTOK*2];
__device__ int   g_rows[NE*NTOK];
__device__ int   g_cnt[NE];
__device__ float g_xt[(size_t)NTOK*DD];          // tf32 bits of x
__device__ float g_w1t[(size_t)NE*DFF*DD];       // W1^T tf32 bits: [e][n][k]
__device__ float g_w2t[(size_t)NE*DD*DFF];       // W2^T tf32 bits: [e][n][k]
__device__ float g_wqkv[(size_t)3*HH*HS*DD];     // [part*16+h][hs][k] tf32 bits

// ---------------- helpers ----------------
__device__ __forceinline__ uint32_t smem_u32(const void* p) {
    uint32_t a;
    asm("{ .reg .u64 t; cvta.to.shared.u64 t, %1; cvt.u32.u64 %0, t; }" : "=r"(a) : "l"(p));
    return a;
}
__device__ __forceinline__ uint32_t f2tf32(float x) {
    uint32_t r;
    asm("cvt.rna.tf32.f32 %0, %1;" : "=r"(r) : "f"(x));
    return r;
}
#define SWZ(b) ((b) ^ (((b) >> 3) & 0x70))

__device__ __forceinline__ void mma_sync_tf32(float* c,
    uint32_t a0, uint32_t a1, uint32_t a2, uint32_t a3,
    uint32_t b0, uint32_t b1)
{
    asm volatile(
        "mma.sync.aligned.m16n8k8.row.col.f32.tf32.tf32.f32 "
        "{%0,%1,%2,%3}, {%4,%5,%6,%7}, {%8,%9}, {%0,%1,%2,%3};"
        : "+f"(c[0]), "+f"(c[1]), "+f"(c[2]), "+f"(c[3])
        : "r"(a0), "r"(a1), "r"(a2), "r"(a3), "r"(b0), "r"(b1));
}
__device__ __forceinline__ void ldsm_x4(uint32_t* r, uint32_t addr) {
    asm volatile("ldmatrix.sync.aligned.m8n8.x4.shared.b16 {%0,%1,%2,%3}, [%4];"
        : "=r"(r[0]), "=r"(r[1]), "=r"(r[2]), "=r"(r[3]) : "r"(addr));
}
__device__ __forceinline__ void ldsm_x2(uint32_t* r, uint32_t addr) {
    asm volatile("ldmatrix.sync.aligned.m8n8.x2.shared.b16 {%0,%1}, [%2];"
        : "=r"(r[0]), "=r"(r[1]) : "r"(addr));
}
#define CP_ASYNC16(dst, src) \
    asm volatile("cp.async.cg.shared.global [%0], [%1], 16;" :: "r"(dst), "l"(src))
#define CP_COMMIT() asm volatile("cp.async.commit_group;" ::: "memory")
#define CP_WAIT0() asm volatile("cp.async.wait_group 0;" ::: "memory")
#define CP_WAIT1() asm volatile("cp.async.wait_group 1;" ::: "memory")

// GEMM smem: 3 stages x (A 16KB + B 16KB) = 96KB
#define ST_BYTES 16384
#define GEMM_SMEM (6 * ST_BYTES + 1024)

// ---------------- utility/preprocessing ----------------
__global__ void zero_counts_kernel() {
    if (threadIdx.x < NE) g_cnt[threadIdx.x] = 0;
}

__global__ __launch_bounds__(256) void xcvt_kernel(const float* __restrict__ X) {
    size_t i = ((size_t)blockIdx.x * 256 + threadIdx.x) * 4;
    float4 v = *(const float4*)(X + i);
    uint4 u = make_uint4(f2tf32(v.x), f2tf32(v.y), f2tf32(v.z), f2tf32(v.w));
    *(uint4*)(g_xt + i) = u;
}

// transpose [slab][R][C] -> [slab][C][R] with tf32 cvt. block (32,8)
__global__ __launch_bounds__(256) void transpose_cvt_kernel(
    const float* __restrict__ in, float* __restrict__ out, int R, int C)
{
    __shared__ float t[32][33];
    int slab = blockIdx.z;
    const float* ip = in + (size_t)slab * R * C;
    float* op = out + (size_t)slab * R * C;
    int c0 = blockIdx.x * 32, r0 = blockIdx.y * 32;
    int x = threadIdx.x, y = threadIdx.y;
#pragma unroll
    for (int j = 0; j < 4; j++)
        t[y + j * 8][x] = ip[(size_t)(r0 + y + j * 8) * C + c0 + x];
    __syncthreads();
#pragma unroll
    for (int j = 0; j < 4; j++)
        op[(size_t)(c0 + y + j * 8) * R + r0 + x] =
            __uint_as_float(f2tf32(t[x][y + j * 8]));
}

// =======================================================================
// QKV GEMM: grid (64, 24), block 256. 3-stage cp.async pipeline.
// =======================================================================
__global__ __launch_bounds__(256) void qkv_tc_kernel()
{
    const int row0 = blockIdx.x * 128;
    const int by = blockIdx.y;
    const int part = by >> 3;
    const int h0 = (by & 7) * 2;
    float* Out = (part == 0) ? g_q : (part == 1) ? g_k : g_v;
    const float qscale = (part == 0) ? 0.03125f : 1.0f;

    extern __shared__ char dynraw[];
    char* p = (char*)(((uintptr_t)dynraw + 1023) & ~(uintptr_t)1023);
    const uint32_t sb = smem_u32(p);
    const int tid = threadIdx.x;
    const int wid = tid >> 5, lane = tid & 31;
    const int wm = (wid & 1) * 64, wn = (wid >> 1) * 32;

    const int quad = lane >> 3, lr = lane & 7;
    const uint32_t a_rowb = (uint32_t)(wm + (quad & 1) * 8 + lr) * 128;
    const uint32_t a_boff = (uint32_t)(quad >> 1) * 16;
    const uint32_t b_rowb = (uint32_t)(wn + lr) * 128;
    const uint32_t b_boff = (uint32_t)((lane >> 3) & 1) * 16;
    const uint32_t xv = (uint32_t)lr << 4;

    float acc[4][4][4];
#pragma unroll
    for (int i = 0; i < 4; i++)
#pragma unroll
        for (int j = 0; j < 4; j++)
#pragma unroll
            for (int q = 0; q < 4; q++) acc[i][j][q] = 0.f;

    const int NCH = DD / 32;
    auto issue = [&](int c) {
        int k0 = c * 32;
        int s = c % 3;
        uint32_t ab = sb + s * ST_BYTES;
        uint32_t bb = sb + 3 * ST_BYTES + s * ST_BYTES;
#pragma unroll
        for (int i = 0; i < 4; i++) {
            int idx = tid + i * 256;
            int row = idx >> 3, c16 = idx & 7;
            const float* asrc = g_xt + (size_t)(row0 + row) * DD + k0 + c16 * 4;
            CP_ASYNC16(ab + SWZ(row * 128 + c16 * 16), asrc);
            int head = h0 + (row >> 6), hs = row & 63;
            const float* bsrc = g_wqkv + (((size_t)(part * HH + head)) * HS + hs) * DD + k0 + c16 * 4;
            CP_ASYNC16(bb + SWZ(row * 128 + c16 * 16), bsrc);
        }
        CP_COMMIT();
    };
    issue(0); issue(1);

    for (int c = 0; c < NCH; c++) {
        CP_WAIT1();
        __syncthreads();
        if (c + 2 < NCH) issue(c + 2); else CP_COMMIT();
        const int s = c % 3;
        const uint32_t At = sb + s * ST_BYTES;
        const uint32_t Bt = sb + 3 * ST_BYTES + s * ST_BYTES;
#pragma unroll
        for (int ks = 0; ks < 4; ks++) {
            uint32_t akoff = (((uint32_t)ks * 32) + a_boff) ^ xv;
            uint32_t bkoff = (((uint32_t)ks * 32) + b_boff) ^ xv;
            uint32_t af[4][4], bf[4][2];
#pragma unroll
            for (int mt = 0; mt < 4; mt++)
                ldsm_x4(af[mt], At + a_rowb + mt * 2048 + akoff);
#pragma unroll
            for (int nt = 0; nt < 4; nt++)
                ldsm_x2(bf[nt], Bt + b_rowb + nt * 1024 + bkoff);
#pragma unroll
            for (int mt = 0; mt < 4; mt++)
#pragma unroll
                for (int nt = 0; nt < 4; nt++)
                    mma_sync_tf32(acc[mt][nt], af[mt][0], af[mt][1], af[mt][2], af[mt][3],
                                  bf[nt][0], bf[nt][1]);
        }
        __syncthreads();
    }

    // epilogue: write tf32 bits (Q pre-scaled)
#pragma unroll
    for (int mt = 0; mt < 4; mt++) {
        int r = row0 + wm + mt * 16 + (lane >> 2);
        int r1 = r + 8;
        int b0i = r >> 10, t0 = r & 1023;
        int b1i = r1 >> 10, t1 = r1 & 1023;
#pragma unroll
        for (int nt = 0; nt < 4; nt++) {
            int n = wn + nt * 8 + 2 * (lane & 3);
            int head = h0 + (n >> 6);
            int hs = n & 63;
            uint2 u0 = make_uint2(f2tf32(acc[mt][nt][0] * qscale), f2tf32(acc[mt][nt][1] * qscale));
            uint2 u1 = make_uint2(f2tf32(acc[mt][nt][2] * qscale), f2tf32(acc[mt][nt][3] * qscale));
            *(uint2*)(Out + (((size_t)b0i * HH + head) * TT + t0) * HS + hs) = u0;
            *(uint2*)(Out + (((size_t)b1i * HH + head) * TT + t1) * HS + hs) = u1;
        }
    }
}

// =======================================================================
// MoE GEMM (G1: xt@W1t+relu -> g_h bits, else g_h@W2t -> g_y fp32)
// grid (64, Ntiles, NE), block 256, 3-stage cp.async pipeline
// =======================================================================
template<bool G1>
__global__ __launch_bounds__(256) void moe_tc_kernel(
    const float* __restrict__ biasfull)
{
    const int e = blockIdx.z;
    const int cnt = g_cnt[e];
    const int m0 = blockIdx.x * 128;
    if (m0 >= cnt) return;
    const int col0 = blockIdx.y * 128;
    const int KTOT = G1 ? DD : DFF;
    const int LDO  = G1 ? DFF : DD;
    const int NCH = KTOT / 32;

    extern __shared__ char dynraw[];
    char* p = (char*)(((uintptr_t)dynraw + 1023) & ~(uintptr_t)1023);
    const uint32_t sb = smem_u32(p);

    __shared__ int rowids[128];
    const int tid = threadIdx.x;
    if (tid < 128) {
        int m = m0 + tid;
        rowids[tid] = (m < cnt) ? g_rows[e * NTOK + m] : -1;
    }
    __syncthreads();

    const int wid = tid >> 5, lane = tid & 31;
    const int wm = (wid & 1) * 64, wn = (wid >> 1) * 32;
    const int quad = lane >> 3, lr = lane & 7;
    const uint32_t a_rowb = (uint32_t)(wm + (quad & 1) * 8 + lr) * 128;
    const uint32_t a_boff = (uint32_t)(quad >> 1) * 16;
    const uint32_t b_rowb = (uint32_t)(wn + lr) * 128;
    const uint32_t b_boff = (uint32_t)((lane >> 3) & 1) * 16;
    const uint32_t xv = (uint32_t)lr << 4;

    float acc[4][4][4];
#pragma unroll
    for (int i = 0; i < 4; i++)
#pragma unroll
        for (int j = 0; j < 4; j++)
#pragma unroll
            for (int q = 0; q < 4; q++) acc[i][j][q] = 0.f;

    const float* Wt = (G1 ? g_w1t : g_w2t) + (size_t)e * ((size_t)DD * DFF);
    const float* bp = biasfull + (size_t)e * (G1 ? DFF : DD);

    auto issue = [&](int c) {
        int k0 = c * 32;
        int s = c % 3;
        uint32_t ab = sb + s * ST_BYTES;
        uint32_t bb = sb + 3 * ST_BYTES + s * ST_BYTES;
#pragma unroll
        for (int i = 0; i < 4; i++) {
            int idx = tid + i * 256;
            int row = idx >> 3, c16 = idx & 7;
            int rid = rowids[row];
            const float* asrc;
            if (G1) asrc = g_xt + (size_t)((rid >= 0) ? (rid >> 1) : 0) * DD + k0 + c16 * 4;
            else    asrc = g_h + (size_t)((rid >= 0) ? rid : 0) * DFF + k0 + c16 * 4;
            CP_ASYNC16(ab + SWZ(row * 128 + c16 * 16), asrc);
            const float* bsrc = Wt + (size_t)(col0 + row) * KTOT + k0 + c16 * 4;
            CP_ASYNC16(bb + SWZ(row * 128 + c16 * 16), bsrc);
        }
        CP_COMMIT();
    };
    issue(0); issue(1);

    for (int c = 0; c < NCH; c++) {
        CP_WAIT1();
        __syncthreads();
        if (c + 2 < NCH) issue(c + 2); else CP_COMMIT();
        const int s = c % 3;
        const uint32_t At = sb + s * ST_BYTES;
        const uint32_t Bt = sb + 3 * ST_BYTES + s * ST_BYTES;
#pragma unroll
        for (int ks = 0; ks < 4; ks++) {
            uint32_t akoff = (((uint32_t)ks * 32) + a_boff) ^ xv;
            uint32_t bkoff = (((uint32_t)ks * 32) + b_boff) ^ xv;
            uint32_t af[4][4], bf[4][2];
#pragma unroll
            for (int mt = 0; mt < 4; mt++)
                ldsm_x4(af[mt], At + a_rowb + mt * 2048 + akoff);
#pragma unroll
            for (int nt = 0; nt < 4; nt++)
                ldsm_x2(bf[nt], Bt + b_rowb + nt * 1024 + bkoff);
#pragma unroll
            for (int mt = 0; mt < 4; mt++)
#pragma unroll
                for (int nt = 0; nt < 4; nt++)
                    mma_sync_tf32(acc[mt][nt], af[mt][0], af[mt][1], af[mt][2], af[mt][3],
                                  bf[nt][0], bf[nt][1]);
        }
        __syncthreads();
    }

    float* Outbase = G1 ? g_h : g_y;
#pragma unroll
    for (int mt = 0; mt < 4; mt++) {
        int ml = wm + mt * 16 + (lane >> 2);
        int rid0 = rowids[ml];
        int rid1 = rowids[ml + 8];
#pragma unroll
        for (int nt = 0; nt < 4; nt++) {
            int n = col0 + wn + nt * 8 + 2 * (lane & 3);
            float bx = __ldg(&bp[n]), by = __ldg(&bp[n + 1]);
            if (rid0 >= 0) {
                float v0 = acc[mt][nt][0] + bx, v1 = acc[mt][nt][1] + by;
                if (G1) {
                    v0 = fmaxf(v0, 0.f); v1 = fmaxf(v1, 0.f);
                    *(uint2*)(Outbase + (size_t)rid0 * LDO + n) =
                        make_uint2(f2tf32(v0), f2tf32(v1));
                } else {
                    *(float2*)(Outbase + (size_t)rid0 * LDO + n) = make_float2(v0, v1);
                }
            }
            if (rid1 >= 0) {
                float v2 = acc[mt][nt][2] + bx, v3 = acc[mt][nt][3] + by;
                if (G1) {
                    v2 = fmaxf(v2, 0.f); v3 = fmaxf(v3, 0.f);
                    *(uint2*)(Outbase + (size_t)rid1 * LDO + n) =
                        make_uint2(f2tf32(v2), f2tf32(v3));
                } else {
                    *(float2*)(Outbase + (size_t)rid1 * LDO + n) = make_float2(v2, v3);
                }
            }
        }
    }
}

// =======================================================================
// Tensor-core causal flash attention, cp.async double-buffered K/V
// grid (16, 128), block 128. smem: Ps 64x68, K/V 2 stages (64x68 + 64x72)
// =======================================================================
#define ALD 68
#define VLD 72
#define KVST (64 * ALD + 64 * VLD)                 // floats per stage
#define ATT_SMEM ((64 * ALD + 2 * KVST) * 4)

__global__ __launch_bounds__(128) void attn_tc_kernel()
{
    extern __shared__ float asf[];
    float* Ps = asf;                               // Q staging, then P
    const uint32_t psb = smem_u32(asf);
    const uint32_t kvb = psb + 64 * ALD * 4;       // stage base

    const int bh = blockIdx.y;
    const int qt = 15 - blockIdx.x;
    const int tid = threadIdx.x;
    const int wid = tid >> 5, lane = tid & 31;
    const int gid = lane >> 2, tq = lane & 3;
    const int qrow = wid * 16 + gid;
    const int qglob = qt * 64;

    auto issue_kv = [&](int kt) {
        int s = kt & 1;
        uint32_t kb = kvb + s * KVST * 4;
        uint32_t vb = kb + 64 * ALD * 4;
        const float* kp = g_k + ((size_t)bh * TT + kt * 64) * HS;
        const float* vp = g_v + ((size_t)bh * TT + kt * 64) * HS;
#pragma unroll
        for (int i = 0; i < 8; i++) {
            int idx = tid + i * 128;
            int r = idx >> 4, c16 = idx & 15;
            CP_ASYNC16(kb + (uint32_t)(r * ALD * 4 + c16 * 16), kp + (size_t)r * HS + c16 * 4);
            CP_ASYNC16(vb + (uint32_t)(r * VLD * 4 + c16 * 16), vp + (size_t)r * HS + c16 * 4);
        }
        CP_COMMIT();
    };

    // Q into Ps via cp.async (already tf32 bits, pre-scaled)
    {
        const float* qp = g_q + ((size_t)bh * TT + qglob) * HS;
#pragma unroll
        for (int i = 0; i < 8; i++) {
            int idx = tid + i * 128;
            int r = idx >> 4, c16 = idx & 15;
            CP_ASYNC16(psb + (uint32_t)(r * ALD * 4 + c16 * 16), qp + (size_t)r * HS + c16 * 4);
        }
        CP_COMMIT();
    }
    issue_kv(0);
    CP_WAIT1();                    // Q done
    __syncthreads();

    uint32_t qf[8][4];
    {
        const uint32_t* Pu = (const uint32_t*)Ps;
#pragma unroll
        for (int ks = 0; ks < 8; ks++) {
            qf[ks][0] = Pu[qrow * ALD + ks * 8 + tq];
            qf[ks][1] = Pu[(qrow + 8) * ALD + ks * 8 + tq];
            qf[ks][2] = Pu[qrow * ALD + ks * 8 + tq + 4];
            qf[ks][3] = Pu[(qrow + 8) * ALD + ks * 8 + tq + 4];
        }
    }
    __syncthreads();

    float oacc[8][4];
#pragma unroll
    for (int i = 0; i < 8; i++)
#pragma unroll
        for (int j = 0; j < 4; j++) oacc[i][j] = 0.f;
    float m0 = -INFINITY, m1 = -INFINITY, l0 = 0.f, l1 = 0.f;

    for (int kt = 0; kt <= qt; kt++) {
        if (kt + 1 <= qt) issue_kv(kt + 1); else CP_COMMIT();
        CP_WAIT1();
        __syncthreads();
        const int s = kt & 1;
        const uint32_t* Ku = (const uint32_t*)(asf + 64 * ALD + s * KVST);
        const uint32_t* Vu = Ku + 64 * ALD;

        float sacc[8][4];
#pragma unroll
        for (int nt = 0; nt < 8; nt++)
#pragma unroll
            for (int j = 0; j < 4; j++) sacc[nt][j] = 0.f;
#pragma unroll
        for (int ks = 0; ks < 8; ks++) {
#pragma unroll
            for (int nt = 0; nt < 8; nt++) {
                uint32_t b0 = Ku[(nt * 8 + gid) * ALD + ks * 8 + tq];
                uint32_t b1 = Ku[(nt * 8 + gid) * ALD + ks * 8 + tq + 4];
                mma_sync_tf32(sacc[nt], qf[ks][0], qf[ks][1], qf[ks][2], qf[ks][3], b0, b1);
            }
        }
        if (kt == qt) {
#pragma unroll
            for (int nt = 0; nt < 8; nt++) {
                int col = nt * 8 + 2 * tq;
                if (col     > qrow)     sacc[nt][0] = -INFINITY;
                if (col + 1 > qrow)     sacc[nt][1] = -INFINITY;
                if (col     > qrow + 8) sacc[nt][2] = -INFINITY;
                if (col + 1 > qrow + 8) sacc[nt][3] = -INFINITY;
            }
        }
        float r0 = -INFINITY, r1 = -INFINITY;
#pragma unroll
        for (int nt = 0; nt < 8; nt++) {
            r0 = fmaxf(r0, fmaxf(sacc[nt][0], sacc[nt][1]));
            r1 = fmaxf(r1, fmaxf(sacc[nt][2], sacc[nt][3]));
        }
        r0 = fmaxf(r0, __shfl_xor_sync(0xffffffffu, r0, 1));
        r0 = fmaxf(r0, __shfl_xor_sync(0xffffffffu, r0, 2));
        r1 = fmaxf(r1, __shfl_xor_sync(0xffffffffu, r1, 1));
        r1 = fmaxf(r1, __shfl_xor_sync(0xffffffffu, r1, 2));
        float mn0 = fmaxf(m0, r0), mn1 = fmaxf(m1, r1);
        float c0 = __expf(m0 - mn0), c1 = __expf(m1 - mn1);
        float ps0 = 0.f, ps1 = 0.f;
        {
            uint32_t* Pu = (uint32_t*)Ps;
#pragma unroll
            for (int nt = 0; nt < 8; nt++) {
                float p0 = __expf(sacc[nt][0] - mn0);
                float p1 = __expf(sacc[nt][1] - mn0);
                float p2 = __expf(sacc[nt][2] - mn1);
                float p3 = __expf(sacc[nt][3] - mn1);
                ps0 += p0 + p1; ps1 += p2 + p3;
                int col = nt * 8 + 2 * tq;
                *(uint2*)(Pu + qrow * ALD + col)       = make_uint2(f2tf32(p0), f2tf32(p1));
                *(uint2*)(Pu + (qrow + 8) * ALD + col) = make_uint2(f2tf32(p2), f2tf32(p3));
            }
        }
        ps0 += __shfl_xor_sync(0xffffffffu, ps0, 1);
        ps0 += __shfl_xor_sync(0xffffffffu, ps0, 2);
        ps1 += __shfl_xor_sync(0xffffffffu, ps1, 1);
        ps1 += __shfl_xor_sync(0xffffffffu, ps1, 2);
        l0 = l0 * c0 + ps0;
        l1 = l1 * c1 + ps1;
#pragma unroll
        for (int dt = 0; dt < 8; dt++) {
            oacc[dt][0] *= c0; oacc[dt][1] *= c0;
            oacc[dt][2] *= c1; oacc[dt][3] *= c1;
        }
        m0 = mn0; m1 = mn1;
        __syncwarp();
        {
            const uint32_t* Pu = (const uint32_t*)Ps;
#pragma unroll
            for (int ks = 0; ks < 8; ks++) {
                uint32_t pa0 = Pu[qrow * ALD + ks * 8 + tq];
                uint32_t pa1 = Pu[(qrow + 8) * ALD + ks * 8 + tq];
                uint32_t pa2 = Pu[qrow * ALD + ks * 8 + tq + 4];
                uint32_t pa3 = Pu[(qrow + 8) * ALD + ks * 8 + tq + 4];
#pragma unroll
                for (int dt = 0; dt < 8; dt++) {
                    uint32_t b0 = Vu[(ks * 8 + tq) * VLD + dt * 8 + gid];
                    uint32_t b1 = Vu[(ks * 8 + tq + 4) * VLD + dt * 8 + gid];
                    mma_sync_tf32(oacc[dt], pa0, pa1, pa2, pa3, b0, b1);
                }
            }
        }
        __syncthreads();
    }

    float i0 = 1.f / l0, i1 = 1.f / l1;
    int b = bh >> 4, h = bh & 15;
    int gq0 = qglob + qrow, gq1 = gq0 + 8;
#pragma unroll
    for (int dt = 0; dt < 8; dt++) {
        int d = h * HS + dt * 8 + 2 * tq;
        *(float2*)(g_attn + ((size_t)b * TT + gq0) * DD + d) =
            make_float2(oacc[dt][0] * i0, oacc[dt][1] * i0);
        *(float2*)(g_attn + ((size_t)b * TT + gq1) * DD + d) =
            make_float2(oacc[dt][2] * i1, oacc[dt][3] * i1);
    }
}

// ---------------- MoE routing ----------------
__global__ __launch_bounds__(256) void route_kernel(
    const float* __restrict__ X, const float* __restrict__ Wg)
{
    int tok = (blockIdx.x * blockDim.x + threadIdx.x) >> 5;
    int lane = threadIdx.x & 31;
    if (tok >= NTOK) return;
    const float* xr = X + (size_t)tok * DD;
    float p[NE];
#pragma unroll
    for (int e = 0; e < NE; e++) p[e] = 0.f;
    for (int d = lane; d < DD; d += 32) {
        float xv = xr[d];
#pragma unroll
        for (int e = 0; e < NE; e++) p[e] += xv * Wg[d * NE + e];
    }
#pragma unroll
    for (int e = 0; e < NE; e++)
#pragma unroll
        for (int off = 16; off; off >>= 1)
            p[e] += __shfl_xor_sync(0xffffffffu, p[e], off);

    if (lane == 0) {
        int i0 = 0; float v0 = p[0];
#pragma unroll
        for (int e = 1; e < NE; e++) if (p[e] > v0) { v0 = p[e]; i0 = e; }
        int i1 = -1; float v1 = -INFINITY;
#pragma unroll
        for (int e = 0; e < NE; e++) if (e != i0 && p[e] > v1) { v1 = p[e]; i1 = e; }
        float e1v = expf(v1 - v0);
        float inv = 1.f / (1.f + e1v);
        g_wtok[tok * 2 + 0] = inv;
        g_wtok[tok * 2 + 1] = e1v * inv;
        int pos0 = atomicAdd(&g_cnt[i0], 1);
        g_rows[i0 * NTOK + pos0] = tok * 2;
        int pos1 = atomicAdd(&g_cnt[i1], 1);
        g_rows[i1 * NTOK + pos1] = tok * 2 + 1;
    }
}

// ---------------- final LN+residual ----------------
__device__ __forceinline__ float4 block_reduce4(float4 v) {
    __shared__ float4 sh[8];
    __shared__ float4 bc;
    int lane = threadIdx.x & 31, w = threadIdx.x >> 5;
#pragma unroll
    for (int off = 16; off; off >>= 1) {
        v.x += __shfl_xor_sync(0xffffffffu, v.x, off);
        v.y += __shfl_xor_sync(0xffffffffu, v.y, off);
        v.z += __shfl_xor_sync(0xffffffffu, v.z, off);
        v.w += __shfl_xor_sync(0xffffffffu, v.w, off);
    }
    if (lane == 0) sh[w] = v;
    __syncthreads();
    if (w == 0) {
        float4 t = (lane < 8) ? sh[lane] : make_float4(0, 0, 0, 0);
#pragma unroll
        for (int off = 4; off; off >>= 1) {
            t.x += __shfl_xor_sync(0xffffffffu, t.x, off);
            t.y += __shfl_xor_sync(0xffffffffu, t.y, off);
            t.z += __shfl_xor_sync(0xffffffffu, t.z, off);
            t.w += __shfl_xor_sync(0xffffffffu, t.w, off);
        }
        if (lane == 0) bc = t;
    }
    __syncthreads();
    return bc;
}

__global__ __launch_bounds__(256) void final_kernel(
    const float* __restrict__ X,
    const float* __restrict__ g1, const float* __restrict__ be1,
    const float* __restrict__ g2, const float* __restrict__ be2,
    float* __restrict__ out)
{
    int t = blockIdx.x;
    int tid = threadIdx.x;
    const float* ar = g_attn + (size_t)t * DD;
    const float* y0 = g_y + (size_t)(t * 2) * DD;
    const float* y1 = g_y + (size_t)(t * 2 + 1) * DD;
    float w0 = g_wtok[t * 2], w1 = g_wtok[t * 2 + 1];

    float4 a4 = ((const float4*)ar)[tid];
    float4 y04 = ((const float4*)y0)[tid];
    float4 y14 = ((const float4*)y1)[tid];
    float a[4] = {a4.x, a4.y, a4.z, a4.w};
    float m[4] = {w0 * y04.x + w1 * y14.x, w0 * y04.y + w1 * y14.y,
                  w0 * y04.z + w1 * y14.z, w0 * y04.w + w1 * y14.w};

    float4 s = make_float4(0, 0, 0, 0);
#pragma unroll
    for (int j = 0; j < 4; j++) {
        s.x += a[j]; s.y += a[j] * a[j];
        s.z += m[j]; s.w += m[j] * m[j];
    }
    s = block_reduce4(s);
    const float invD = 1.0f / (float)DD;
    float mua = s.x * invD;
    float vara = fmaxf(s.y * invD - mua * mua, 0.f);
    float rsa = rsqrtf(vara + LN_EPS);
    float mum = s.z * invD;
    float varm = fmaxf(s.w * invD - mum * mum, 0.f);
    float rsm = rsqrtf(varm + LN_EPS);

    float4 x4 = ((const float4*)(X + (size_t)t * DD))[tid];
    float4 g14 = ((const float4*)g1)[tid];
    float4 b14 = ((const float4*)be1)[tid];
    float4 g24 = ((const float4*)g2)[tid];
    float4 b24 = ((const float4*)be2)[tid];
    float xs[4] = {x4.x, x4.y, x4.z, x4.w};
    float g1s[4] = {g14.x, g14.y, g14.z, g14.w};
    float b1s[4] = {b14.x, b14.y, b14.z, b14.w};
    float g2s[4] = {g24.x, g24.y, g24.z, g24.w};
    float b2s[4] = {b24.x, b24.y, b24.z, b24.w};
    float o[4];
#pragma unroll
    for (int j = 0; j < 4; j++) {
        o[j] = xs[j]
             + (a[j] - mua) * rsa * g1s[j] + b1s[j]
             + (m[j] - mum) * rsm * g2s[j] + b2s[j];
    }
    ((float4*)(out + (size_t)t * DD))[tid] = make_float4(o[0], o[1], o[2], o[3]);
}

// ---------------- launch ----------------
extern "C" void kernel_launch(void* const* d_in, const int* in_sizes, int n_in,
                              void* d_out, int out_size)
{
    const float* x   = (const float*)d_in[0];
    const float* Wq  = (const float*)d_in[1];
    const float* Wk  = (const float*)d_in[2];
    const float* Wv  = (const float*)d_in[3];
    const float* Wg  = (const float*)d_in[4];
    const float* W1  = (const float*)d_in[5];
    const float* b1  = (const float*)d_in[6];
    const float* W2  = (const float*)d_in[7];
    const float* b2  = (const float*)d_in[8];
    const float* g1  = (const float*)d_in[9];
    const float* be1 = (const float*)d_in[10];
    const float* g2  = (const float*)d_in[11];
    const float* be2 = (const float*)d_in[12];
    float* out = (float*)d_out;

    cudaFuncSetAttribute(qkv_tc_kernel, cudaFuncAttributeMaxDynamicSharedMemorySize, GEMM_SMEM);
    cudaFuncSetAttribute(moe_tc_kernel<true>, cudaFuncAttributeMaxDynamicSharedMemorySize, GEMM_SMEM);
    cudaFuncSetAttribute(moe_tc_kernel<false>, cudaFuncAttributeMaxDynamicSharedMemorySize, GEMM_SMEM);
    cudaFuncSetAttribute(attn_tc_kernel, cudaFuncAttributeMaxDynamicSharedMemorySize, ATT_SMEM);

    float* d_w1t; cudaGetSymbolAddress((void**)&d_w1t, g_w1t);
    float* d_w2t; cudaGetSymbolAddress((void**)&d_w2t, g_w2t);
    float* d_wqkv; cudaGetSymbolAddress((void**)&d_wqkv, g_wqkv);

    zero_counts_kernel<<<1, 32>>>();
    xcvt_kernel<<<NTOK * DD / 1024, 256>>>(x);
    transpose_cvt_kernel<<<dim3(HS / 32, DD / 32, HH), dim3(32, 8)>>>(Wq, d_wqkv, DD, HS);
    transpose_cvt_kernel<<<dim3(HS / 32, DD / 32, HH), dim3(32, 8)>>>(Wk, d_wqkv + (size_t)HH * HS * DD, DD, HS);
    transpose_cvt_kernel<<<dim3(HS / 32, DD / 32, HH), dim3(32, 8)>>>(Wv, d_wqkv + (size_t)2 * HH * HS * DD, DD, HS);
    transpose_cvt_kernel<<<dim3(DFF / 32, DD / 32, NE), dim3(32, 8)>>>(W1, d_w1t, DD, DFF);
    transpose_cvt_kernel<<<dim3(DD / 32, DFF / 32, NE), dim3(32, 8)>>>(W2, d_w2t, DFF, DD);
    route_kernel<<<NTOK / 8, 256>>>(x, Wg);
    qkv_tc_kernel<<<dim3(NTOK / 128, 24), 256, GEMM_SMEM>>>();
    attn_tc_kernel<<<dim3(16, BB * HH), 128, ATT_SMEM>>>();
    moe_tc_kernel<true><<<dim3(64, DFF / 128, NE), 256, GEMM_SMEM>>>(b1);
    moe_tc_kernel<false><<<dim3(64, DD / 128, NE), 256, GEMM_SMEM>>>(b2);
    final_kernel<<<NTOK, 256>>>(x, g1, be1, g2, be2, out);
}

// round 7
// speedup vs baseline: 10.8138x; 1.7748x over previous
#include <cuda_runtime.h>
#include <cuda_fp16.h>
#include <cstdint>
#include <math.h>

#define BB 8
#define TT 1024
#define DD 1024
#define HH 16
#define HS 64
#define NE 8
#define NTOK (BB*TT)        // 8192
#define DFF 4096
#define LN_EPS 1e-5f

// ---------------- scratch (device globals; no runtime allocation) ----------------
__device__ __half g_q[(size_t)BB*HH*TT*HS];      // fp16, Q pre-scaled by 2^-5
__device__ __half g_k[(size_t)BB*HH*TT*HS];
__device__ __half g_v[(size_t)BB*HH*TT*HS];
__device__ float  g_attn[(size_t)NTOK*DD];       // fp32
__device__ __half g_h[(size_t)NTOK*2*DFF];       // fp16 (post-relu), rowid = tok*2+slot
__device__ float  g_y[(size_t)NTOK*2*DD];        // fp32
__device__ float  g_wtok[NTOK*2];
__device__ int    g_rows[NE*NTOK];
__device__ int    g_cnt[NE];
__device__ __half g_xt[(size_t)NTOK*DD];         // fp16 of x
__device__ __half g_w1t[(size_t)NE*DFF*DD];      // W1^T fp16: [e][n][k]
__device__ __half g_w2t[(size_t)NE*DD*DFF];      // W2^T fp16: [e][n][k]
__device__ __half g_wqkv[(size_t)3*HH*HS*DD];    // [part*16+h][hs][k] fp16

// ---------------- helpers ----------------
__device__ __forceinline__ uint32_t smem_u32(const void* p) {
    uint32_t a;
    asm("{ .reg .u64 t; cvta.to.shared.u64 t, %1; cvt.u32.u64 %0, t; }" : "=r"(a) : "l"(p));
    return a;
}
#define SWZ(b) ((b) ^ (((b) >> 3) & 0x70))

__device__ __forceinline__ void mma_f16(float* c,
    uint32_t a0, uint32_t a1, uint32_t a2, uint32_t a3,
    uint32_t b0, uint32_t b1)
{
    asm volatile(
        "mma.sync.aligned.m16n8k16.row.col.f32.f16.f16.f32 "
        "{%0,%1,%2,%3}, {%4,%5,%6,%7}, {%8,%9}, {%0,%1,%2,%3};"
        : "+f"(c[0]), "+f"(c[1]), "+f"(c[2]), "+f"(c[3])
        : "r"(a0), "r"(a1), "r"(a2), "r"(a3), "r"(b0), "r"(b1));
}
__device__ __forceinline__ void ldsm_x4(uint32_t* r, uint32_t addr) {
    asm volatile("ldmatrix.sync.aligned.m8n8.x4.shared.b16 {%0,%1,%2,%3}, [%4];"
        : "=r"(r[0]), "=r"(r[1]), "=r"(r[2]), "=r"(r[3]) : "r"(addr));
}
__device__ __forceinline__ void ldsm_x2(uint32_t* r, uint32_t addr) {
    asm volatile("ldmatrix.sync.aligned.m8n8.x2.shared.b16 {%0,%1}, [%2];"
        : "=r"(r[0]), "=r"(r[1]) : "r"(addr));
}
__device__ __forceinline__ void ldsm_x2t(uint32_t* r, uint32_t addr) {
    asm volatile("ldmatrix.sync.aligned.m8n8.x2.trans.shared.b16 {%0,%1}, [%2];"
        : "=r"(r[0]), "=r"(r[1]) : "r"(addr));
}
#define CP_ASYNC16(dst, src) \
    asm volatile("cp.async.cg.shared.global [%0], [%1], 16;" :: "r"(dst), "l"((const void*)(src)))
#define CP_COMMIT() asm volatile("cp.async.commit_group;" ::: "memory")
#define CP_WAIT1() asm volatile("cp.async.wait_group 1;" ::: "memory")

__device__ __forceinline__ uint32_t h2u(float a, float b) {
    __half2 h = __floats2half2_rn(a, b);
    return *(uint32_t*)&h;
}

// GEMM smem: 3 stages x (A 16KB + B 16KB) = 96KB ; K-chunk = 64 halves
#define ST_BYTES 16384
#define GEMM_SMEM (6 * ST_BYTES + 1024)

// ---------------- utility/preprocessing ----------------
__global__ void zero_counts_kernel() {
    if (threadIdx.x < NE) g_cnt[threadIdx.x] = 0;
}

// x fp32 -> fp16, 8 elems/thread
__global__ __launch_bounds__(256) void xcvt_kernel(const float* __restrict__ X) {
    size_t i = ((size_t)blockIdx.x * 256 + threadIdx.x) * 8;
    float4 v0 = *(const float4*)(X + i);
    float4 v1 = *(const float4*)(X + i + 4);
    uint4 u = make_uint4(h2u(v0.x, v0.y), h2u(v0.z, v0.w),
                         h2u(v1.x, v1.y), h2u(v1.z, v1.w));
    *(uint4*)(g_xt + i) = u;
}

// transpose [slab][R][C] fp32 -> [slab][C][R] fp16. block (32,8)
__global__ __launch_bounds__(256) void transpose_cvt_kernel(
    const float* __restrict__ in, __half* __restrict__ out, int R, int C)
{
    __shared__ float t[32][33];
    int slab = blockIdx.z;
    const float* ip = in + (size_t)slab * R * C;
    __half* op = out + (size_t)slab * R * C;
    int c0 = blockIdx.x * 32, r0 = blockIdx.y * 32;
    int x = threadIdx.x, y = threadIdx.y;
#pragma unroll
    for (int j = 0; j < 4; j++)
        t[y + j * 8][x] = ip[(size_t)(r0 + y + j * 8) * C + c0 + x];
    __syncthreads();
#pragma unroll
    for (int j = 0; j < 4; j++)
        op[(size_t)(c0 + y + j * 8) * R + r0 + x] = __float2half_rn(t[x][y + j * 8]);
}

// =======================================================================
// QKV GEMM: grid (64, 24), block 256. K-chunk 64, 3-stage cp.async.
// =======================================================================
__global__ __launch_bounds__(256) void qkv_tc_kernel()
{
    const int row0 = blockIdx.x * 128;
    const int by = blockIdx.y;
    const int part = by >> 3;
    const int h0 = (by & 7) * 2;
    __half* Out = (part == 0) ? g_q : (part == 1) ? g_k : g_v;
    const float qscale = (part == 0) ? 0.03125f : 1.0f;

    extern __shared__ char dynraw[];
    char* p = (char*)(((uintptr_t)dynraw + 1023) & ~(uintptr_t)1023);
    const uint32_t sb = smem_u32(p);
    const int tid = threadIdx.x;
    const int wid = tid >> 5, lane = tid & 31;
    const int wm = (wid & 1) * 64, wn = (wid >> 1) * 32;

    const int quad = lane >> 3, lr = lane & 7;
    const uint32_t a_rowb = (uint32_t)(wm + (quad & 1) * 8 + lr) * 128;
    const uint32_t a_boff = (uint32_t)(quad >> 1) * 16;
    const uint32_t b_rowb = (uint32_t)(wn + lr) * 128;
    const uint32_t b_boff = (uint32_t)((lane >> 3) & 1) * 16;
    const uint32_t xv = (uint32_t)lr << 4;

    float acc[4][4][4];
#pragma unroll
    for (int i = 0; i < 4; i++)
#pragma unroll
        for (int j = 0; j < 4; j++)
#pragma unroll
            for (int q = 0; q < 4; q++) acc[i][j][q] = 0.f;

    const int NCH = DD / 64;
    auto issue = [&](int c) {
        int k0 = c * 64;
        int s = c % 3;
        uint32_t ab = sb + s * ST_BYTES;
        uint32_t bb = sb + 3 * ST_BYTES + s * ST_BYTES;
#pragma unroll
        for (int i = 0; i < 4; i++) {
            int idx = tid + i * 256;
            int row = idx >> 3, c16 = idx & 7;
            const __half* asrc = g_xt + (size_t)(row0 + row) * DD + k0 + c16 * 8;
            CP_ASYNC16(ab + SWZ(row * 128 + c16 * 16), asrc);
            int head = h0 + (row >> 6), hs = row & 63;
            const __half* bsrc = g_wqkv + (((size_t)(part * HH + head)) * HS + hs) * DD + k0 + c16 * 8;
            CP_ASYNC16(bb + SWZ(row * 128 + c16 * 16), bsrc);
        }
        CP_COMMIT();
    };
    issue(0); issue(1);

    for (int c = 0; c < NCH; c++) {
        CP_WAIT1();
        __syncthreads();
        if (c + 2 < NCH) issue(c + 2); else CP_COMMIT();
        const int s = c % 3;
        const uint32_t At = sb + s * ST_BYTES;
        const uint32_t Bt = sb + 3 * ST_BYTES + s * ST_BYTES;
#pragma unroll
        for (int ks = 0; ks < 4; ks++) {
            uint32_t akoff = (((uint32_t)ks * 32) + a_boff) ^ xv;
            uint32_t bkoff = (((uint32_t)ks * 32) + b_boff) ^ xv;
            uint32_t af[4][4], bf[4][2];
#pragma unroll
            for (int mt = 0; mt < 4; mt++)
                ldsm_x4(af[mt], At + a_rowb + mt * 2048 + akoff);
#pragma unroll
            for (int nt = 0; nt < 4; nt++)
                ldsm_x2(bf[nt], Bt + b_rowb + nt * 1024 + bkoff);
#pragma unroll
            for (int mt = 0; mt < 4; mt++)
#pragma unroll
                for (int nt = 0; nt < 4; nt++)
                    mma_f16(acc[mt][nt], af[mt][0], af[mt][1], af[mt][2], af[mt][3],
                            bf[nt][0], bf[nt][1]);
        }
        __syncthreads();
    }

    // epilogue: fp16 out (Q pre-scaled)
#pragma unroll
    for (int mt = 0; mt < 4; mt++) {
        int r = row0 + wm + mt * 16 + (lane >> 2);
        int r1 = r + 8;
        int b0i = r >> 10, t0 = r & 1023;
        int b1i = r1 >> 10, t1 = r1 & 1023;
#pragma unroll
        for (int nt = 0; nt < 4; nt++) {
            int n = wn + nt * 8 + 2 * (lane & 3);
            int head = h0 + (n >> 6);
            int hs = n & 63;
            *(uint32_t*)(Out + (((size_t)b0i * HH + head) * TT + t0) * HS + hs) =
                h2u(acc[mt][nt][0] * qscale, acc[mt][nt][1] * qscale);
            *(uint32_t*)(Out + (((size_t)b1i * HH + head) * TT + t1) * HS + hs) =
                h2u(acc[mt][nt][2] * qscale, acc[mt][nt][3] * qscale);
        }
    }
}

// =======================================================================
// MoE GEMM (G1: xt@W1t+relu -> g_h fp16, else g_h@W2t -> g_y fp32)
// grid (64, Ntiles, NE), block 256, K-chunk 64, 3-stage cp.async
// =======================================================================
template<bool G1>
__global__ __launch_bounds__(256) void moe_tc_kernel(
    const float* __restrict__ biasfull)
{
    const int e = blockIdx.z;
    const int cnt = g_cnt[e];
    const int m0 = blockIdx.x * 128;
    if (m0 >= cnt) return;
    const int col0 = blockIdx.y * 128;
    const int KTOT = G1 ? DD : DFF;
    const int LDO  = G1 ? DFF : DD;
    const int NCH = KTOT / 64;

    extern __shared__ char dynraw[];
    char* p = (char*)(((uintptr_t)dynraw + 1023) & ~(uintptr_t)1023);
    const uint32_t sb = smem_u32(p);

    __shared__ int rowids[128];
    const int tid = threadIdx.x;
    if (tid < 128) {
        int m = m0 + tid;
        rowids[tid] = (m < cnt) ? g_rows[e * NTOK + m] : -1;
    }
    __syncthreads();

    const int wid = tid >> 5, lane = tid & 31;
    const int wm = (wid & 1) * 64, wn = (wid >> 1) * 32;
    const int quad = lane >> 3, lr = lane & 7;
    const uint32_t a_rowb = (uint32_t)(wm + (quad & 1) * 8 + lr) * 128;
    const uint32_t a_boff = (uint32_t)(quad >> 1) * 16;
    const uint32_t b_rowb = (uint32_t)(wn + lr) * 128;
    const uint32_t b_boff = (uint32_t)((lane >> 3) & 1) * 16;
    const uint32_t xv = (uint32_t)lr << 4;

    float acc[4][4][4];
#pragma unroll
    for (int i = 0; i < 4; i++)
#pragma unroll
        for (int j = 0; j < 4; j++)
#pragma unroll
            for (int q = 0; q < 4; q++) acc[i][j][q] = 0.f;

    const __half* Wt = (G1 ? g_w1t : g_w2t) + (size_t)e * ((size_t)DD * DFF);
    const float* bp = biasfull + (size_t)e * (G1 ? DFF : DD);

    auto issue = [&](int c) {
        int k0 = c * 64;
        int s = c % 3;
        uint32_t ab = sb + s * ST_BYTES;
        uint32_t bb = sb + 3 * ST_BYTES + s * ST_BYTES;
#pragma unroll
        for (int i = 0; i < 4; i++) {
            int idx = tid + i * 256;
            int row = idx >> 3, c16 = idx & 7;
            int rid = rowids[row];
            const __half* asrc;
            if (G1) asrc = g_xt + (size_t)((rid >= 0) ? (rid >> 1) : 0) * DD + k0 + c16 * 8;
            else    asrc = g_h + (size_t)((rid >= 0) ? rid : 0) * DFF + k0 + c16 * 8;
            CP_ASYNC16(ab + SWZ(row * 128 + c16 * 16), asrc);
            const __half* bsrc = Wt + (size_t)(col0 + row) * KTOT + k0 + c16 * 8;
            CP_ASYNC16(bb + SWZ(row * 128 + c16 * 16), bsrc);
        }
        CP_COMMIT();
    };
    issue(0); issue(1);

    for (int c = 0; c < NCH; c++) {
        CP_WAIT1();
        __syncthreads();
        if (c + 2 < NCH) issue(c + 2); else CP_COMMIT();
        const int s = c % 3;
        const uint32_t At = sb + s * ST_BYTES;
        const uint32_t Bt = sb + 3 * ST_BYTES + s * ST_BYTES;
#pragma unroll
        for (int ks = 0; ks < 4; ks++) {
            uint32_t akoff = (((uint32_t)ks * 32) + a_boff) ^ xv;
            uint32_t bkoff = (((uint32_t)ks * 32) + b_boff) ^ xv;
            uint32_t af[4][4], bf[4][2];
#pragma unroll
            for (int mt = 0; mt < 4; mt++)
                ldsm_x4(af[mt], At + a_rowb + mt * 2048 + akoff);
#pragma unroll
            for (int nt = 0; nt < 4; nt++)
                ldsm_x2(bf[nt], Bt + b_rowb + nt * 1024 + bkoff);
#pragma unroll
            for (int mt = 0; mt < 4; mt++)
#pragma unroll
                for (int nt = 0; nt < 4; nt++)
                    mma_f16(acc[mt][nt], af[mt][0], af[mt][1], af[mt][2], af[mt][3],
                            bf[nt][0], bf[nt][1]);
        }
        __syncthreads();
    }

#pragma unroll
    for (int mt = 0; mt < 4; mt++) {
        int ml = wm + mt * 16 + (lane >> 2);
        int rid0 = rowids[ml];
        int rid1 = rowids[ml + 8];
#pragma unroll
        for (int nt = 0; nt < 4; nt++) {
            int n = col0 + wn + nt * 8 + 2 * (lane & 3);
            float bx = __ldg(&bp[n]), by = __ldg(&bp[n + 1]);
            if (G1) {
                if (rid0 >= 0) {
                    float v0 = fmaxf(acc[mt][nt][0] + bx, 0.f);
                    float v1 = fmaxf(acc[mt][nt][1] + by, 0.f);
                    *(uint32_t*)(g_h + (size_t)rid0 * LDO + n) = h2u(v0, v1);
                }
                if (rid1 >= 0) {
                    float v2 = fmaxf(acc[mt][nt][2] + bx, 0.f);
                    float v3 = fmaxf(acc[mt][nt][3] + by, 0.f);
                    *(uint32_t*)(g_h + (size_t)rid1 * LDO + n) = h2u(v2, v3);
                }
            } else {
                if (rid0 >= 0)
                    *(float2*)(g_y + (size_t)rid0 * LDO + n) =
                        make_float2(acc[mt][nt][0] + bx, acc[mt][nt][1] + by);
                if (rid1 >= 0)
                    *(float2*)(g_y + (size_t)rid1 * LDO + n) =
                        make_float2(acc[mt][nt][2] + bx, acc[mt][nt][3] + by);
            }
        }
    }
}

// =======================================================================
// fp16 tensor-core causal flash attention, cp.async double-buffered K/V
// grid (16, 128), block 128. smem: P/Q 8KB + 2 stages x (K 8KB + V 8KB) = 40KB
// =======================================================================
#define ATT_SMEM (8192 + 2 * 16384)

__global__ __launch_bounds__(128) void attn_tc_kernel()
{
    extern __shared__ char asc[];
    const uint32_t psb = smem_u32(asc);
    const uint32_t kvb = psb + 8192;

    const int bh = blockIdx.y;
    const int qt = 15 - blockIdx.x;
    const int tid = threadIdx.x;
    const int wid = tid >> 5, lane = tid & 31;
    const int gid = lane >> 2, tq = lane & 3;
    const int quad = lane >> 3, lr = lane & 7;
    const int qrow = wid * 16 + gid;
    const int qglob = qt * 64;

    const uint32_t a_rowb = (uint32_t)(wid * 16 + (quad & 1) * 8 + lr) * 128;
    const uint32_t a_boff = (uint32_t)(quad >> 1) * 16;
    const uint32_t b_boff = (uint32_t)((lane >> 3) & 1) * 16;
    const uint32_t xv = (uint32_t)lr << 4;
    const uint32_t v_rowb = (uint32_t)(((lane >> 3) & 1) * 8 + lr) * 128;
    const uint32_t xvq = (uint32_t)gid << 4;

    auto issue_kv = [&](int kt) {
        int s = kt & 1;
        uint32_t kb = kvb + s * 16384;
        uint32_t vb = kb + 8192;
        const __half* kp = g_k + ((size_t)bh * TT + kt * 64) * HS;
        const __half* vp = g_v + ((size_t)bh * TT + kt * 64) * HS;
#pragma unroll
        for (int i = 0; i < 4; i++) {
            int idx = tid + i * 128;
            int r = idx >> 3, c16 = idx & 7;
            CP_ASYNC16(kb + SWZ(r * 128 + c16 * 16), kp + (size_t)r * HS + c16 * 8);
            CP_ASYNC16(vb + SWZ(r * 128 + c16 * 16), vp + (size_t)r * HS + c16 * 8);
        }
        CP_COMMIT();
    };

    // Q into P buffer
    {
        const __half* qp = g_q + ((size_t)bh * TT + qglob) * HS;
#pragma unroll
        for (int i = 0; i < 4; i++) {
            int idx = tid + i * 128;
            int r = idx >> 3, c16 = idx & 7;
            CP_ASYNC16(psb + SWZ(r * 128 + c16 * 16), qp + (size_t)r * HS + c16 * 8);
        }
        CP_COMMIT();
    }
    issue_kv(0);
    CP_WAIT1();
    __syncthreads();

    uint32_t qf[4][4];
#pragma unroll
    for (int ks = 0; ks < 4; ks++)
        ldsm_x4(qf[ks], psb + a_rowb + ((((uint32_t)ks * 32) + a_boff) ^ xv));
    __syncthreads();

    float oacc[8][4];
#pragma unroll
    for (int i = 0; i < 8; i++)
#pragma unroll
        for (int j = 0; j < 4; j++) oacc[i][j] = 0.f;
    float m0 = -INFINITY, m1 = -INFINITY, l0 = 0.f, l1 = 0.f;

    for (int kt = 0; kt <= qt; kt++) {
        if (kt + 1 <= qt) issue_kv(kt + 1); else CP_COMMIT();
        CP_WAIT1();
        __syncthreads();
        const int s = kt & 1;
        const uint32_t Kb = kvb + s * 16384;
        const uint32_t Vb = Kb + 8192;

        float sacc[8][4];
#pragma unroll
        for (int nt = 0; nt < 8; nt++)
#pragma unroll
            for (int j = 0; j < 4; j++) sacc[nt][j] = 0.f;
#pragma unroll
        for (int ks = 0; ks < 4; ks++) {
            uint32_t bkoff = (((uint32_t)ks * 32) + b_boff) ^ xv;
#pragma unroll
            for (int nt = 0; nt < 8; nt++) {
                uint32_t bf[2];
                ldsm_x2(bf, Kb + (uint32_t)(nt * 8 + lr) * 128 + bkoff);
                mma_f16(sacc[nt], qf[ks][0], qf[ks][1], qf[ks][2], qf[ks][3], bf[0], bf[1]);
            }
        }
        if (kt == qt) {
#pragma unroll
            for (int nt = 0; nt < 8; nt++) {
                int col = nt * 8 + 2 * tq;
                if (col     > qrow)     sacc[nt][0] = -INFINITY;
                if (col + 1 > qrow)     sacc[nt][1] = -INFINITY;
                if (col     > qrow + 8) sacc[nt][2] = -INFINITY;
                if (col + 1 > qrow + 8) sacc[nt][3] = -INFINITY;
            }
        }
        float r0 = -INFINITY, r1 = -INFINITY;
#pragma unroll
        for (int nt = 0; nt < 8; nt++) {
            r0 = fmaxf(r0, fmaxf(sacc[nt][0], sacc[nt][1]));
            r1 = fmaxf(r1, fmaxf(sacc[nt][2], sacc[nt][3]));
        }
        r0 = fmaxf(r0, __shfl_xor_sync(0xffffffffu, r0, 1));
        r0 = fmaxf(r0, __shfl_xor_sync(0xffffffffu, r0, 2));
        r1 = fmaxf(r1, __shfl_xor_sync(0xffffffffu, r1, 1));
        r1 = fmaxf(r1, __shfl_xor_sync(0xffffffffu, r1, 2));
        float mn0 = fmaxf(m0, r0), mn1 = fmaxf(m1, r1);
        float c0 = __expf(m0 - mn0), c1 = __expf(m1 - mn1);
        float ps0 = 0.f, ps1 = 0.f;
#pragma unroll
        for (int nt = 0; nt < 8; nt++) {
            float p0 = __expf(sacc[nt][0] - mn0);
            float p1 = __expf(sacc[nt][1] - mn0);
            float p2 = __expf(sacc[nt][2] - mn1);
            float p3 = __expf(sacc[nt][3] - mn1);
            ps0 += p0 + p1; ps1 += p2 + p3;
            uint32_t boff = (uint32_t)(nt * 16 + 4 * tq) ^ xvq;
            *(uint32_t*)(asc + qrow * 128 + boff)       = h2u(p0, p1);
            *(uint32_t*)(asc + (qrow + 8) * 128 + boff) = h2u(p2, p3);
        }
        ps0 += __shfl_xor_sync(0xffffffffu, ps0, 1);
        ps0 += __shfl_xor_sync(0xffffffffu, ps0, 2);
        ps1 += __shfl_xor_sync(0xffffffffu, ps1, 1);
        ps1 += __shfl_xor_sync(0xffffffffu, ps1, 2);
        l0 = l0 * c0 + ps0;
        l1 = l1 * c1 + ps1;
#pragma unroll
        for (int dt = 0; dt < 8; dt++) {
            oacc[dt][0] *= c0; oacc[dt][1] *= c0;
            oacc[dt][2] *= c1; oacc[dt][3] *= c1;
        }
        m0 = mn0; m1 = mn1;
        __syncwarp();
        // O += P V  (P A-frags natural, V B-frags via ldmatrix.trans)
#pragma unroll
        for (int ks = 0; ks < 4; ks++) {
            uint32_t pa[4];
            ldsm_x4(pa, psb + a_rowb + ((((uint32_t)ks * 32) + a_boff) ^ xv));
            uint32_t vrow = (uint32_t)(ks * 16) * 128 + v_rowb;
#pragma unroll
            for (int dt = 0; dt < 8; dt++) {
                uint32_t bv[2];
                ldsm_x2t(bv, Vb + vrow + (((uint32_t)dt * 16) ^ xv));
                mma_f16(oacc[dt], pa[0], pa[1], pa[2], pa[3], bv[0], bv[1]);
            }
        }
        __syncthreads();
    }

    float i0 = 1.f / l0, i1 = 1.f / l1;
    int b = bh >> 4, h = bh & 15;
    int gq0 = qglob + qrow, gq1 = gq0 + 8;
#pragma unroll
    for (int dt = 0; dt < 8; dt++) {
        int d = h * HS + dt * 8 + 2 * tq;
        *(float2*)(g_attn + ((size_t)b * TT + gq0) * DD + d) =
            make_float2(oacc[dt][0] * i0, oacc[dt][1] * i0);
        *(float2*)(g_attn + ((size_t)b * TT + gq1) * DD + d) =
            make_float2(oacc[dt][2] * i1, oacc[dt][3] * i1);
    }
}

// ---------------- MoE routing ----------------
__global__ __launch_bounds__(256) void route_kernel(
    const float* __restrict__ X, const float* __restrict__ Wg)
{
    int tok = (blockIdx.x * blockDim.x + threadIdx.x) >> 5;
    int lane = threadIdx.x & 31;
    if (tok >= NTOK) return;
    const float* xr = X + (size_t)tok * DD;
    float p[NE];
#pragma unroll
    for (int e = 0; e < NE; e++) p[e] = 0.f;
    for (int d = lane; d < DD; d += 32) {
        float xv = xr[d];
#pragma unroll
        for (int e = 0; e < NE; e++) p[e] += xv * Wg[d * NE + e];
    }
#pragma unroll
    for (int e = 0; e < NE; e++)
#pragma unroll
        for (int off = 16; off; off >>= 1)
            p[e] += __shfl_xor_sync(0xffffffffu, p[e], off);

    if (lane == 0) {
        int i0 = 0; float v0 = p[0];
#pragma unroll
        for (int e = 1; e < NE; e++) if (p[e] > v0) { v0 = p[e]; i0 = e; }
        int i1 = -1; float v1 = -INFINITY;
#pragma unroll
        for (int e = 0; e < NE; e++) if (e != i0 && p[e] > v1) { v1 = p[e]; i1 = e; }
        float e1v = expf(v1 - v0);
        float inv = 1.f / (1.f + e1v);
        g_wtok[tok * 2 + 0] = inv;
        g_wtok[tok * 2 + 1] = e1v * inv;
        int pos0 = atomicAdd(&g_cnt[i0], 1);
        g_rows[i0 * NTOK + pos0] = tok * 2;
        int pos1 = atomicAdd(&g_cnt[i1], 1);
        g_rows[i1 * NTOK + pos1] = tok * 2 + 1;
    }
}

// ---------------- final LN+residual ----------------
__device__ __forceinline__ float4 block_reduce4(float4 v) {
    __shared__ float4 sh[8];
    __shared__ float4 bc;
    int lane = threadIdx.x & 31, w = threadIdx.x >> 5;
#pragma unroll
    for (int off = 16; off; off >>= 1) {
        v.x += __shfl_xor_sync(0xffffffffu, v.x, off);
        v.y += __shfl_xor_sync(0xffffffffu, v.y, off);
        v.z += __shfl_xor_sync(0xffffffffu, v.z, off);
        v.w += __shfl_xor_sync(0xffffffffu, v.w, off);
    }
    if (lane == 0) sh[w] = v;
    __syncthreads();
    if (w == 0) {
        float4 t = (lane < 8) ? sh[lane] : make_float4(0, 0, 0, 0);
#pragma unroll
        for (int off = 4; off; off >>= 1) {
            t.x += __shfl_xor_sync(0xffffffffu, t.x, off);
            t.y += __shfl_xor_sync(0xffffffffu, t.y, off);
            t.z += __shfl_xor_sync(0xffffffffu, t.z, off);
            t.w += __shfl_xor_sync(0xffffffffu, t.w, off);
        }
        if (lane == 0) bc = t;
    }
    __syncthreads();
    return bc;
}

__global__ __launch_bounds__(256) void final_kernel(
    const float* __restrict__ X,
    const float* __restrict__ g1, const float* __restrict__ be1,
    const float* __restrict__ g2, const float* __restrict__ be2,
    float* __restrict__ out)
{
    int t = blockIdx.x;
    int tid = threadIdx.x;
    const float* ar = g_attn + (size_t)t * DD;
    const float* y0 = g_y + (size_t)(t * 2) * DD;
    const float* y1 = g_y + (size_t)(t * 2 + 1) * DD;
    float w0 = g_wtok[t * 2], w1 = g_wtok[t * 2 + 1];

    float4 a4 = ((const float4*)ar)[tid];
    float4 y04 = ((const float4*)y0)[tid];
    float4 y14 = ((const float4*)y1)[tid];
    float a[4] = {a4.x, a4.y, a4.z, a4.w};
    float m[4] = {w0 * y04.x + w1 * y14.x, w0 * y04.y + w1 * y14.y,
                  w0 * y04.z + w1 * y14.z, w0 * y04.w + w1 * y14.w};

    float4 s = make_float4(0, 0, 0, 0);
#pragma unroll
    for (int j = 0; j < 4; j++) {
        s.x += a[j]; s.y += a[j] * a[j];
        s.z += m[j]; s.w += m[j] * m[j];
    }
    s = block_reduce4(s);
    const float invD = 1.0f / (float)DD;
    float mua = s.x * invD;
    float vara = fmaxf(s.y * invD - mua * mua, 0.f);
    float rsa = rsqrtf(vara + LN_EPS);
    float mum = s.z * invD;
    float varm = fmaxf(s.w * invD - mum * mum, 0.f);
    float rsm = rsqrtf(varm + LN_EPS);

    float4 x4 = ((const float4*)(X + (size_t)t * DD))[tid];
    float4 g14 = ((const float4*)g1)[tid];
    float4 b14 = ((const float4*)be1)[tid];
    float4 g24 = ((const float4*)g2)[tid];
    float4 b24 = ((const float4*)be2)[tid];
    float xs[4] = {x4.x, x4.y, x4.z, x4.w};
    float g1s[4] = {g14.x, g14.y, g14.z, g14.w};
    float b1s[4] = {b14.x, b14.y, b14.z, b14.w};
    float g2s[4] = {g24.x, g24.y, g24.z, g24.w};
    float b2s[4] = {b24.x, b24.y, b24.z, b24.w};
    float o[4];
#pragma unroll
    for (int j = 0; j < 4; j++) {
        o[j] = xs[j]
             + (a[j] - mua) * rsa * g1s[j] + b1s[j]
             + (m[j] - mum) * rsm * g2s[j] + b2s[j];
    }
    ((float4*)(out + (size_t)t * DD))[tid] = make_float4(o[0], o[1], o[2], o[3]);
}

// ---------------- launch ----------------
extern "C" void kernel_launch(void* const* d_in, const int* in_sizes, int n_in,
                              void* d_out, int out_size)
{
    const float* x   = (const float*)d_in[0];
    const float* Wq  = (const float*)d_in[1];
    const float* Wk  = (const float*)d_in[2];
    const float* Wv  = (const float*)d_in[3];
    const float* Wg  = (const float*)d_in[4];
    const float* W1  = (const float*)d_in[5];
    const float* b1  = (const float*)d_in[6];
    const float* W2  = (const float*)d_in[7];
    const float* b2  = (const float*)d_in[8];
    const float* g1  = (const float*)d_in[9];
    const float* be1 = (const float*)d_in[10];
    const float* g2  = (const float*)d_in[11];
    const float* be2 = (const float*)d_in[12];
    float* out = (float*)d_out;

    cudaFuncSetAttribute(qkv_tc_kernel, cudaFuncAttributeMaxDynamicSharedMemorySize, GEMM_SMEM);
    cudaFuncSetAttribute(moe_tc_kernel<true>, cudaFuncAttributeMaxDynamicSharedMemorySize, GEMM_SMEM);
    cudaFuncSetAttribute(moe_tc_kernel<false>, cudaFuncAttributeMaxDynamicSharedMemorySize, GEMM_SMEM);
    cudaFuncSetAttribute(attn_tc_kernel, cudaFuncAttributeMaxDynamicSharedMemorySize, ATT_SMEM);

    __half* d_w1t; cudaGetSymbolAddress((void**)&d_w1t, g_w1t);
    __half* d_w2t; cudaGetSymbolAddress((void**)&d_w2t, g_w2t);
    __half* d_wqkv; cudaGetSymbolAddress((void**)&d_wqkv, g_wqkv);

    zero_counts_kernel<<<1, 32>>>();
    xcvt_kernel<<<NTOK * DD / 2048, 256>>>(x);
    transpose_cvt_kernel<<<dim3(HS / 32, DD / 32, HH), dim3(32, 8)>>>(Wq, d_wqkv, DD, HS);
    transpose_cvt_kernel<<<dim3(HS / 32, DD / 32, HH), dim3(32, 8)>>>(Wk, d_wqkv + (size_t)HH * HS * DD, DD, HS);
    transpose_cvt_kernel<<<dim3(HS / 32, DD / 32, HH), dim3(32, 8)>>>(Wv, d_wqkv + (size_t)2 * HH * HS * DD, DD, HS);
    transpose_cvt_kernel<<<dim3(DFF / 32, DD / 32, NE), dim3(32, 8)>>>(W1, d_w1t, DD, DFF);
    transpose_cvt_kernel<<<dim3(DD / 32, DFF / 32, NE), dim3(32, 8)>>>(W2, d_w2t, DFF, DD);
    route_kernel<<<NTOK / 8, 256>>>(x, Wg);
    qkv_tc_kernel<<<dim3(NTOK / 128, 24), 256, GEMM_SMEM>>>();
    attn_tc_kernel<<<dim3(16, BB * HH), 128, ATT_SMEM>>>();
    moe_tc_kernel<true><<<dim3(64, DFF / 128, NE), 256, GEMM_SMEM>>>(b1);
    moe_tc_kernel<false><<<dim3(64, DD / 128, NE), 256, GEMM_SMEM>>>(b2);
    final_kernel<<<NTOK, 256>>>(x, g1, be1, g2, be2, out);
}

// round 8
// speedup vs baseline: 11.0452x; 1.0214x over previous
#include <cuda_runtime.h>
#include <cuda_fp16.h>
#include <cstdint>
#include <math.h>

#define BB 8
#define TT 1024
#define DD 1024
#define HH 16
#define HS 64
#define NE 8
#define NTOK (BB*TT)        // 8192
#define DFF 4096
#define LN_EPS 1e-5f

// ---------------- scratch (device globals; no runtime allocation) ----------------
__device__ __half g_q[(size_t)BB*HH*TT*HS];      // fp16, Q pre-scaled by 2^-5
__device__ __half g_k[(size_t)BB*HH*TT*HS];
__device__ __half g_v[(size_t)BB*HH*TT*HS];
__device__ float  g_attn[(size_t)NTOK*DD];       // fp32
__device__ __half g_h[(size_t)NTOK*2*DFF];       // fp16 (post-relu), rowid = tok*2+slot
__device__ float  g_y[(size_t)NTOK*2*DD];        // fp32
__device__ float  g_wtok[NTOK*2];
__device__ int    g_rows[NE*NTOK];
__device__ int    g_cnt[NE];
__device__ __half g_xt[(size_t)NTOK*DD];         // fp16 of x
__device__ __half g_w1t[(size_t)NE*DFF*DD];      // W1^T fp16: [e][n][k]
__device__ __half g_w2t[(size_t)NE*DD*DFF];      // W2^T fp16: [e][n][k]
__device__ __half g_wqkv[(size_t)3*HH*HS*DD];    // [part*16+h][hs][k] fp16

// ---------------- helpers ----------------
__device__ __forceinline__ uint32_t smem_u32(const void* p) {
    uint32_t a;
    asm("{ .reg .u64 t; cvta.to.shared.u64 t, %1; cvt.u32.u64 %0, t; }" : "=r"(a) : "l"(p));
    return a;
}
#define SWZ(b) ((b) ^ (((b) >> 3) & 0x70))

__device__ __forceinline__ void mma_f16(float* c,
    uint32_t a0, uint32_t a1, uint32_t a2, uint32_t a3,
    uint32_t b0, uint32_t b1)
{
    asm volatile(
        "mma.sync.aligned.m16n8k16.row.col.f32.f16.f16.f32 "
        "{%0,%1,%2,%3}, {%4,%5,%6,%7}, {%8,%9}, {%0,%1,%2,%3};"
        : "+f"(c[0]), "+f"(c[1]), "+f"(c[2]), "+f"(c[3])
        : "r"(a0), "r"(a1), "r"(a2), "r"(a3), "r"(b0), "r"(b1));
}
__device__ __forceinline__ void ldsm_x4(uint32_t* r, uint32_t addr) {
    asm volatile("ldmatrix.sync.aligned.m8n8.x4.shared.b16 {%0,%1,%2,%3}, [%4];"
        : "=r"(r[0]), "=r"(r[1]), "=r"(r[2]), "=r"(r[3]) : "r"(addr));
}
__device__ __forceinline__ void ldsm_x2(uint32_t* r, uint32_t addr) {
    asm volatile("ldmatrix.sync.aligned.m8n8.x2.shared.b16 {%0,%1}, [%2];"
        : "=r"(r[0]), "=r"(r[1]) : "r"(addr));
}
__device__ __forceinline__ void ldsm_x2t(uint32_t* r, uint32_t addr) {
    asm volatile("ldmatrix.sync.aligned.m8n8.x2.trans.shared.b16 {%0,%1}, [%2];"
        : "=r"(r[0]), "=r"(r[1]) : "r"(addr));
}
#define CP_ASYNC16(dst, src) \
    asm volatile("cp.async.cg.shared.global [%0], [%1], 16;" :: "r"(dst), "l"((const void*)(src)))
#define CP_COMMIT() asm volatile("cp.async.commit_group;" ::: "memory")
#define CP_WAIT1() asm volatile("cp.async.wait_group 1;" ::: "memory")

__device__ __forceinline__ uint32_t h2u(float a, float b) {
    __half2 h = __floats2half2_rn(a, b);
    return *(uint32_t*)&h;
}

// GEMM smem: 3 stages x (A 16KB + B 16KB) = 96KB ; K-chunk = 64 halves
#define ST_BYTES 16384
#define GEMM_SMEM (6 * ST_BYTES + 1024)

// ---------------- preprocessing ----------------
// x fp32 -> fp16, 8 elems/thread; also zeroes expert counters
__global__ __launch_bounds__(256) void xcvt_kernel(const float* __restrict__ X) {
    if (blockIdx.x == 0 && threadIdx.x < NE) g_cnt[threadIdx.x] = 0;
    size_t i = ((size_t)blockIdx.x * 256 + threadIdx.x) * 8;
    float4 v0 = *(const float4*)(X + i);
    float4 v1 = *(const float4*)(X + i + 4);
    uint4 u = make_uint4(h2u(v0.x, v0.y), h2u(v0.z, v0.w),
                         h2u(v1.x, v1.y), h2u(v1.z, v1.w));
    *(uint4*)(g_xt + i) = u;
}

// transpose [slab][R][C] fp32 -> [slab][C][R] fp16. block (32,8)
__global__ __launch_bounds__(256) void transpose_cvt_kernel(
    const float* __restrict__ in, __half* __restrict__ out, int R, int C)
{
    __shared__ float t[32][33];
    int slab = blockIdx.z;
    const float* ip = in + (size_t)slab * R * C;
    __half* op = out + (size_t)slab * R * C;
    int c0 = blockIdx.x * 32, r0 = blockIdx.y * 32;
    int x = threadIdx.x, y = threadIdx.y;
#pragma unroll
    for (int j = 0; j < 4; j++)
        t[y + j * 8][x] = ip[(size_t)(r0 + y + j * 8) * C + c0 + x];
    __syncthreads();
#pragma unroll
    for (int j = 0; j < 4; j++)
        op[(size_t)(c0 + y + j * 8) * R + r0 + x] = __float2half_rn(t[x][y + j * 8]);
}

// =======================================================================
// QKV GEMM: grid (64, 24), block 128 (4 warps, 64x64 warp tiles)
// =======================================================================
__global__ __launch_bounds__(128) void qkv_tc_kernel()
{
    const int row0 = blockIdx.x * 128;
    const int by = blockIdx.y;
    const int part = by >> 3;
    const int h0 = (by & 7) * 2;
    __half* Out = (part == 0) ? g_q : (part == 1) ? g_k : g_v;
    const float qscale = (part == 0) ? 0.03125f : 1.0f;

    extern __shared__ char dynraw[];
    char* p = (char*)(((uintptr_t)dynraw + 1023) & ~(uintptr_t)1023);
    const uint32_t sb = smem_u32(p);
    const int tid = threadIdx.x;
    const int wid = tid >> 5, lane = tid & 31;
    const int wm = (wid & 1) * 64, wn = (wid >> 1) * 64;

    const int quad = lane >> 3, lr = lane & 7;
    const uint32_t a_rowb = (uint32_t)(wm + (quad & 1) * 8 + lr) * 128;
    const uint32_t a_boff = (uint32_t)(quad >> 1) * 16;
    const uint32_t b_rowb = (uint32_t)(wn + ((lane >> 4) & 1) * 8 + lr) * 128;
    const uint32_t b_boff = (uint32_t)((lane >> 3) & 1) * 16;
    const uint32_t xv = (uint32_t)lr << 4;

    float acc[4][8][4];
#pragma unroll
    for (int i = 0; i < 4; i++)
#pragma unroll
        for (int j = 0; j < 8; j++)
#pragma unroll
            for (int q = 0; q < 4; q++) acc[i][j][q] = 0.f;

    const int NCH = DD / 64;
    auto issue = [&](int c) {
        int k0 = c * 64;
        int s = c % 3;
        uint32_t ab = sb + s * ST_BYTES;
        uint32_t bb = sb + 3 * ST_BYTES + s * ST_BYTES;
#pragma unroll
        for (int i = 0; i < 8; i++) {
            int idx = tid + i * 128;
            int row = idx >> 3, c16 = idx & 7;
            const __half* asrc = g_xt + (size_t)(row0 + row) * DD + k0 + c16 * 8;
            CP_ASYNC16(ab + SWZ(row * 128 + c16 * 16), asrc);
            int head = h0 + (row >> 6), hs = row & 63;
            const __half* bsrc = g_wqkv + (((size_t)(part * HH + head)) * HS + hs) * DD + k0 + c16 * 8;
            CP_ASYNC16(bb + SWZ(row * 128 + c16 * 16), bsrc);
        }
        CP_COMMIT();
    };
    issue(0); issue(1);

    for (int c = 0; c < NCH; c++) {
        CP_WAIT1();
        __syncthreads();
        if (c + 2 < NCH) issue(c + 2); else CP_COMMIT();
        const int s = c % 3;
        const uint32_t At = sb + s * ST_BYTES;
        const uint32_t Bt = sb + 3 * ST_BYTES + s * ST_BYTES;
#pragma unroll
        for (int ks = 0; ks < 4; ks++) {
            uint32_t akoff = (((uint32_t)ks * 32) + a_boff) ^ xv;
            uint32_t bkoff = (((uint32_t)ks * 32) + b_boff) ^ xv;
            uint32_t af[4][4], bf[4][4];
#pragma unroll
            for (int mt = 0; mt < 4; mt++)
                ldsm_x4(af[mt], At + a_rowb + mt * 2048 + akoff);
#pragma unroll
            for (int nt2 = 0; nt2 < 4; nt2++)
                ldsm_x4(bf[nt2], Bt + b_rowb + nt2 * 2048 + bkoff);
#pragma unroll
            for (int mt = 0; mt < 4; mt++)
#pragma unroll
                for (int nt2 = 0; nt2 < 4; nt2++) {
                    mma_f16(acc[mt][2 * nt2],     af[mt][0], af[mt][1], af[mt][2], af[mt][3],
                            bf[nt2][0], bf[nt2][1]);
                    mma_f16(acc[mt][2 * nt2 + 1], af[mt][0], af[mt][1], af[mt][2], af[mt][3],
                            bf[nt2][2], bf[nt2][3]);
                }
        }
        __syncthreads();
    }

    // epilogue: fp16 out (Q pre-scaled)
#pragma unroll
    for (int mt = 0; mt < 4; mt++) {
        int r = row0 + wm + mt * 16 + (lane >> 2);
        int r1 = r + 8;
        int b0i = r >> 10, t0 = r & 1023;
        int b1i = r1 >> 10, t1 = r1 & 1023;
#pragma unroll
        for (int nt = 0; nt < 8; nt++) {
            int n = wn + nt * 8 + 2 * (lane & 3);
            int head = h0 + (n >> 6);
            int hs = n & 63;
            *(uint32_t*)(Out + (((size_t)b0i * HH + head) * TT + t0) * HS + hs) =
                h2u(acc[mt][nt][0] * qscale, acc[mt][nt][1] * qscale);
            *(uint32_t*)(Out + (((size_t)b1i * HH + head) * TT + t1) * HS + hs) =
                h2u(acc[mt][nt][2] * qscale, acc[mt][nt][3] * qscale);
        }
    }
}

// =======================================================================
// MoE GEMM (G1: xt@W1t+relu -> g_h fp16, else g_h@W2t -> g_y fp32)
// grid (64, Ntiles, NE), block 128 (4 warps, 64x64 warp tiles)
// =======================================================================
template<bool G1>
__global__ __launch_bounds__(128) void moe_tc_kernel(
    const float* __restrict__ biasfull)
{
    const int e = blockIdx.z;
    const int cnt = g_cnt[e];
    const int m0 = blockIdx.x * 128;
    if (m0 >= cnt) return;
    const int col0 = blockIdx.y * 128;
    const int KTOT = G1 ? DD : DFF;
    const int LDO  = G1 ? DFF : DD;
    const int NCH = KTOT / 64;

    extern __shared__ char dynraw[];
    char* p = (char*)(((uintptr_t)dynraw + 1023) & ~(uintptr_t)1023);
    const uint32_t sb = smem_u32(p);

    __shared__ int rowids[128];
    const int tid = threadIdx.x;
    {
        int m = m0 + tid;
        rowids[tid] = (m < cnt) ? g_rows[e * NTOK + m] : -1;
    }
    __syncthreads();

    const int wid = tid >> 5, lane = tid & 31;
    const int wm = (wid & 1) * 64, wn = (wid >> 1) * 64;
    const int quad = lane >> 3, lr = lane & 7;
    const uint32_t a_rowb = (uint32_t)(wm + (quad & 1) * 8 + lr) * 128;
    const uint32_t a_boff = (uint32_t)(quad >> 1) * 16;
    const uint32_t b_rowb = (uint32_t)(wn + ((lane >> 4) & 1) * 8 + lr) * 128;
    const uint32_t b_boff = (uint32_t)((lane >> 3) & 1) * 16;
    const uint32_t xv = (uint32_t)lr << 4;

    float acc[4][8][4];
#pragma unroll
    for (int i = 0; i < 4; i++)
#pragma unroll
        for (int j = 0; j < 8; j++)
#pragma unroll
            for (int q = 0; q < 4; q++) acc[i][j][q] = 0.f;

    const __half* Wt = (G1 ? g_w1t : g_w2t) + (size_t)e * ((size_t)DD * DFF);
    const float* bp = biasfull + (size_t)e * (G1 ? DFF : DD);

    auto issue = [&](int c) {
        int k0 = c * 64;
        int s = c % 3;
        uint32_t ab = sb + s * ST_BYTES;
        uint32_t bb = sb + 3 * ST_BYTES + s * ST_BYTES;
#pragma unroll
        for (int i = 0; i < 8; i++) {
            int idx = tid + i * 128;
            int row = idx >> 3, c16 = idx & 7;
            int rid = rowids[row];
            const __half* asrc;
            if (G1) asrc = g_xt + (size_t)((rid >= 0) ? (rid >> 1) : 0) * DD + k0 + c16 * 8;
            else    asrc = g_h + (size_t)((rid >= 0) ? rid : 0) * DFF + k0 + c16 * 8;
            CP_ASYNC16(ab + SWZ(row * 128 + c16 * 16), asrc);
            const __half* bsrc = Wt + (size_t)(col0 + row) * KTOT + k0 + c16 * 8;
            CP_ASYNC16(bb + SWZ(row * 128 + c16 * 16), bsrc);
        }
        CP_COMMIT();
    };
    issue(0); issue(1);

    for (int c = 0; c < NCH; c++) {
        CP_WAIT1();
        __syncthreads();
        if (c + 2 < NCH) issue(c + 2); else CP_COMMIT();
        const int s = c % 3;
        const uint32_t At = sb + s * ST_BYTES;
        const uint32_t Bt = sb + 3 * ST_BYTES + s * ST_BYTES;
#pragma unroll
        for (int ks = 0; ks < 4; ks++) {
            uint32_t akoff = (((uint32_t)ks * 32) + a_boff) ^ xv;
            uint32_t bkoff = (((uint32_t)ks * 32) + b_boff) ^ xv;
            uint32_t af[4][4], bf[4][4];
#pragma unroll
            for (int mt = 0; mt < 4; mt++)
                ldsm_x4(af[mt], At + a_rowb + mt * 2048 + akoff);
#pragma unroll
            for (int nt2 = 0; nt2 < 4; nt2++)
                ldsm_x4(bf[nt2], Bt + b_rowb + nt2 * 2048 + bkoff);
#pragma unroll
            for (int mt = 0; mt < 4; mt++)
#pragma unroll
                for (int nt2 = 0; nt2 < 4; nt2++) {
                    mma_f16(acc[mt][2 * nt2],     af[mt][0], af[mt][1], af[mt][2], af[mt][3],
                            bf[nt2][0], bf[nt2][1]);
                    mma_f16(acc[mt][2 * nt2 + 1], af[mt][0], af[mt][1], af[mt][2], af[mt][3],
                            bf[nt2][2], bf[nt2][3]);
                }
        }
        __syncthreads();
    }

#pragma unroll
    for (int mt = 0; mt < 4; mt++) {
        int ml = wm + mt * 16 + (lane >> 2);
        int rid0 = rowids[ml];
        int rid1 = rowids[ml + 8];
#pragma unroll
        for (int nt = 0; nt < 8; nt++) {
            int n = col0 + wn + nt * 8 + 2 * (lane & 3);
            float bx = __ldg(&bp[n]), by = __ldg(&bp[n + 1]);
            if (G1) {
                if (rid0 >= 0) {
                    float v0 = fmaxf(acc[mt][nt][0] + bx, 0.f);
                    float v1 = fmaxf(acc[mt][nt][1] + by, 0.f);
                    *(uint32_t*)(g_h + (size_t)rid0 * LDO + n) = h2u(v0, v1);
                }
                if (rid1 >= 0) {
                    float v2 = fmaxf(acc[mt][nt][2] + bx, 0.f);
                    float v3 = fmaxf(acc[mt][nt][3] + by, 0.f);
                    *(uint32_t*)(g_h + (size_t)rid1 * LDO + n) = h2u(v2, v3);
                }
            } else {
                if (rid0 >= 0)
                    *(float2*)(g_y + (size_t)rid0 * LDO + n) =
                        make_float2(acc[mt][nt][0] + bx, acc[mt][nt][1] + by);
                if (rid1 >= 0)
                    *(float2*)(g_y + (size_t)rid1 * LDO + n) =
                        make_float2(acc[mt][nt][2] + bx, acc[mt][nt][3] + by);
            }
        }
    }
}

// =======================================================================
// fp16 tensor-core causal flash attention, cp.async double-buffered K/V
// grid (16, 128), block 128. smem: P/Q 8KB + 2 stages x (K 8KB + V 8KB) = 40KB
// =======================================================================
#define ATT_SMEM (8192 + 2 * 16384)

__global__ __launch_bounds__(128) void attn_tc_kernel()
{
    extern __shared__ char asc[];
    const uint32_t psb = smem_u32(asc);
    const uint32_t kvb = psb + 8192;

    const int bh = blockIdx.y;
    const int qt = 15 - blockIdx.x;
    const int tid = threadIdx.x;
    const int wid = tid >> 5, lane = tid & 31;
    const int gid = lane >> 2, tq = lane & 3;
    const int quad = lane >> 3, lr = lane & 7;
    const int qrow = wid * 16 + gid;
    const int qglob = qt * 64;

    const uint32_t a_rowb = (uint32_t)(wid * 16 + (quad & 1) * 8 + lr) * 128;
    const uint32_t a_boff = (uint32_t)(quad >> 1) * 16;
    const uint32_t b_boff = (uint32_t)((lane >> 3) & 1) * 16;
    const uint32_t xv = (uint32_t)lr << 4;
    const uint32_t v_rowb = (uint32_t)(((lane >> 3) & 1) * 8 + lr) * 128;
    const uint32_t xvq = (uint32_t)gid << 4;

    auto issue_kv = [&](int kt) {
        int s = kt & 1;
        uint32_t kb = kvb + s * 16384;
        uint32_t vb = kb + 8192;
        const __half* kp = g_k + ((size_t)bh * TT + kt * 64) * HS;
        const __half* vp = g_v + ((size_t)bh * TT + kt * 64) * HS;
#pragma unroll
        for (int i = 0; i < 4; i++) {
            int idx = tid + i * 128;
            int r = idx >> 3, c16 = idx & 7;
            CP_ASYNC16(kb + SWZ(r * 128 + c16 * 16), kp + (size_t)r * HS + c16 * 8);
            CP_ASYNC16(vb + SWZ(r * 128 + c16 * 16), vp + (size_t)r * HS + c16 * 8);
        }
        CP_COMMIT();
    };

    // Q into P buffer
    {
        const __half* qp = g_q + ((size_t)bh * TT + qglob) * HS;
#pragma unroll
        for (int i = 0; i < 4; i++) {
            int idx = tid + i * 128;
            int r = idx >> 3, c16 = idx & 7;
            CP_ASYNC16(psb + SWZ(r * 128 + c16 * 16), qp + (size_t)r * HS + c16 * 8);
        }
        CP_COMMIT();
    }
    issue_kv(0);
    CP_WAIT1();
    __syncthreads();

    uint32_t qf[4][4];
#pragma unroll
    for (int ks = 0; ks < 4; ks++)
        ldsm_x4(qf[ks], psb + a_rowb + ((((uint32_t)ks * 32) + a_boff) ^ xv));
    __syncthreads();

    float oacc[8][4];
#pragma unroll
    for (int i = 0; i < 8; i++)
#pragma unroll
        for (int j = 0; j < 4; j++) oacc[i][j] = 0.f;
    float m0 = -INFINITY, m1 = -INFINITY, l0 = 0.f, l1 = 0.f;

    for (int kt = 0; kt <= qt; kt++) {
        if (kt + 1 <= qt) issue_kv(kt + 1); else CP_COMMIT();
        CP_WAIT1();
        __syncthreads();
        const int s = kt & 1;
        const uint32_t Kb = kvb + s * 16384;
        const uint32_t Vb = Kb + 8192;

        float sacc[8][4];
#pragma unroll
        for (int nt = 0; nt < 8; nt++)
#pragma unroll
            for (int j = 0; j < 4; j++) sacc[nt][j] = 0.f;
#pragma unroll
        for (int ks = 0; ks < 4; ks++) {
            uint32_t bkoff = (((uint32_t)ks * 32) + b_boff) ^ xv;
#pragma unroll
            for (int nt = 0; nt < 8; nt++) {
                uint32_t bf[2];
                ldsm_x2(bf, Kb + (uint32_t)(nt * 8 + lr) * 128 + bkoff);
                mma_f16(sacc[nt], qf[ks][0], qf[ks][1], qf[ks][2], qf[ks][3], bf[0], bf[1]);
            }
        }
        if (kt == qt) {
#pragma unroll
            for (int nt = 0; nt < 8; nt++) {
                int col = nt * 8 + 2 * tq;
                if (col     > qrow)     sacc[nt][0] = -INFINITY;
                if (col + 1 > qrow)     sacc[nt][1] = -INFINITY;
                if (col     > qrow + 8) sacc[nt][2] = -INFINITY;
                if (col + 1 > qrow + 8) sacc[nt][3] = -INFINITY;
            }
        }
        float r0 = -INFINITY, r1 = -INFINITY;
#pragma unroll
        for (int nt = 0; nt < 8; nt++) {
            r0 = fmaxf(r0, fmaxf(sacc[nt][0], sacc[nt][1]));
            r1 = fmaxf(r1, fmaxf(sacc[nt][2], sacc[nt][3]));
        }
        r0 = fmaxf(r0, __shfl_xor_sync(0xffffffffu, r0, 1));
        r0 = fmaxf(r0, __shfl_xor_sync(0xffffffffu, r0, 2));
        r1 = fmaxf(r1, __shfl_xor_sync(0xffffffffu, r1, 1));
        r1 = fmaxf(r1, __shfl_xor_sync(0xffffffffu, r1, 2));
        float mn0 = fmaxf(m0, r0), mn1 = fmaxf(m1, r1);
        float c0 = __expf(m0 - mn0), c1 = __expf(m1 - mn1);
        float ps0 = 0.f, ps1 = 0.f;
#pragma unroll
        for (int nt = 0; nt < 8; nt++) {
            float p0 = __expf(sacc[nt][0] - mn0);
            float p1 = __expf(sacc[nt][1] - mn0);
            float p2 = __expf(sacc[nt][2] - mn1);
            float p3 = __expf(sacc[nt][3] - mn1);
            ps0 += p0 + p1; ps1 += p2 + p3;
            uint32_t boff = (uint32_t)(nt * 16 + 4 * tq) ^ xvq;
            *(uint32_t*)(asc + qrow * 128 + boff)       = h2u(p0, p1);
            *(uint32_t*)(asc + (qrow + 8) * 128 + boff) = h2u(p2, p3);
        }
        ps0 += __shfl_xor_sync(0xffffffffu, ps0, 1);
        ps0 += __shfl_xor_sync(0xffffffffu, ps0, 2);
        ps1 += __shfl_xor_sync(0xffffffffu, ps1, 1);
        ps1 += __shfl_xor_sync(0xffffffffu, ps1, 2);
        l0 = l0 * c0 + ps0;
        l1 = l1 * c1 + ps1;
#pragma unroll
        for (int dt = 0; dt < 8; dt++) {
            oacc[dt][0] *= c0; oacc[dt][1] *= c0;
            oacc[dt][2] *= c1; oacc[dt][3] *= c1;
        }
        m0 = mn0; m1 = mn1;
        __syncwarp();
        // O += P V  (P A-frags natural, V B-frags via ldmatrix.trans)
#pragma unroll
        for (int ks = 0; ks < 4; ks++) {
            uint32_t pa[4];
            ldsm_x4(pa, psb + a_rowb + ((((uint32_t)ks * 32) + a_boff) ^ xv));
            uint32_t vrow = (uint32_t)(ks * 16) * 128 + v_rowb;
#pragma unroll
            for (int dt = 0; dt < 8; dt++) {
                uint32_t bv[2];
                ldsm_x2t(bv, Vb + vrow + (((uint32_t)dt * 16) ^ xv));
                mma_f16(oacc[dt], pa[0], pa[1], pa[2], pa[3], bv[0], bv[1]);
            }
        }
        __syncthreads();
    }

    float i0 = 1.f / l0, i1 = 1.f / l1;
    int b = bh >> 4, h = bh & 15;
    int gq0 = qglob + qrow, gq1 = gq0 + 8;
#pragma unroll
    for (int dt = 0; dt < 8; dt++) {
        int d = h * HS + dt * 8 + 2 * tq;
        *(float2*)(g_attn + ((size_t)b * TT + gq0) * DD + d) =
            make_float2(oacc[dt][0] * i0, oacc[dt][1] * i0);
        *(float2*)(g_attn + ((size_t)b * TT + gq1) * DD + d) =
            make_float2(oacc[dt][2] * i1, oacc[dt][3] * i1);
    }
}

// ---------------- MoE routing (vectorized) ----------------
__global__ __launch_bounds__(256) void route_kernel(
    const float* __restrict__ X, const float* __restrict__ Wg)
{
    int tok = (blockIdx.x * blockDim.x + threadIdx.x) >> 5;
    int lane = threadIdx.x & 31;
    if (tok >= NTOK) return;
    const float* xr = X + (size_t)tok * DD;
    float p[NE];
#pragma unroll
    for (int e = 0; e < NE; e++) p[e] = 0.f;
#pragma unroll
    for (int it = 0; it < DD / 128; it++) {
        int d4 = lane + it * 32;
        float4 xv4 = *(const float4*)(xr + d4 * 4);
        const float* wr = Wg + (size_t)d4 * 4 * NE;
        float xs[4] = {xv4.x, xv4.y, xv4.z, xv4.w};
#pragma unroll
        for (int dd = 0; dd < 4; dd++) {
            float4 w0 = *(const float4*)(wr + dd * 8);
            float4 w1 = *(const float4*)(wr + dd * 8 + 4);
            p[0] += xs[dd] * w0.x; p[1] += xs[dd] * w0.y;
            p[2] += xs[dd] * w0.z; p[3] += xs[dd] * w0.w;
            p[4] += xs[dd] * w1.x; p[5] += xs[dd] * w1.y;
            p[6] += xs[dd] * w1.z; p[7] += xs[dd] * w1.w;
        }
    }
#pragma unroll
    for (int e = 0; e < NE; e++)
#pragma unroll
        for (int off = 16; off; off >>= 1)
            p[e] += __shfl_xor_sync(0xffffffffu, p[e], off);

    if (lane == 0) {
        int i0 = 0; float v0 = p[0];
#pragma unroll
        for (int e = 1; e < NE; e++) if (p[e] > v0) { v0 = p[e]; i0 = e; }
        int i1 = -1; float v1 = -INFINITY;
#pragma unroll
        for (int e = 0; e < NE; e++) if (e != i0 && p[e] > v1) { v1 = p[e]; i1 = e; }
        float e1v = expf(v1 - v0);
        float inv = 1.f / (1.f + e1v);
        g_wtok[tok * 2 + 0] = inv;
        g_wtok[tok * 2 + 1] = e1v * inv;
        int pos0 = atomicAdd(&g_cnt[i0], 1);
        g_rows[i0 * NTOK + pos0] = tok * 2;
        int pos1 = atomicAdd(&g_cnt[i1], 1);
        g_rows[i1 * NTOK + pos1] = tok * 2 + 1;
    }
}

// ---------------- final LN+residual ----------------
__device__ __forceinline__ float4 block_reduce4(float4 v) {
    __shared__ float4 sh[8];
    __shared__ float4 bc;
    int lane = threadIdx.x & 31, w = threadIdx.x >> 5;
#pragma unroll
    for (int off = 16; off; off >>= 1) {
        v.x += __shfl_xor_sync(0xffffffffu, v.x, off);
        v.y += __shfl_xor_sync(0xffffffffu, v.y, off);
        v.z += __shfl_xor_sync(0xffffffffu, v.z, off);
        v.w += __shfl_xor_sync(0xffffffffu, v.w, off);
    }
    if (lane == 0) sh[w] = v;
    __syncthreads();
    if (w == 0) {
        float4 t = (lane < 8) ? sh[lane] : make_float4(0, 0, 0, 0);
#pragma unroll
        for (int off = 4; off; off >>= 1) {
            t.x += __shfl_xor_sync(0xffffffffu, t.x, off);
            t.y += __shfl_xor_sync(0xffffffffu, t.y, off);
            t.z += __shfl_xor_sync(0xffffffffu, t.z, off);
            t.w += __shfl_xor_sync(0xffffffffu, t.w, off);
        }
        if (lane == 0) bc = t;
    }
    __syncthreads();
    return bc;
}

__global__ __launch_bounds__(256) void final_kernel(
    const float* __restrict__ X,
    const float* __restrict__ g1, const float* __restrict__ be1,
    const float* __restrict__ g2, const float* __restrict__ be2,
    float* __restrict__ out)
{
    int t = blockIdx.x;
    int tid = threadIdx.x;
    const float* ar = g_attn + (size_t)t * DD;
    const float* y0 = g_y + (size_t)(t * 2) * DD;
    const float* y1 = g_y + (size_t)(t * 2 + 1) * DD;
    float w0 = g_wtok[t * 2], w1 = g_wtok[t * 2 + 1];

    float4 a4 = ((const float4*)ar)[tid];
    float4 y04 = ((const float4*)y0)[tid];
    float4 y14 = ((const float4*)y1)[tid];
    float a[4] = {a4.x, a4.y, a4.z, a4.w};
    float m[4] = {w0 * y04.x + w1 * y14.x, w0 * y04.y + w1 * y14.y,
                  w0 * y04.z + w1 * y14.z, w0 * y04.w + w1 * y14.w};

    float4 s = make_float4(0, 0, 0, 0);
#pragma unroll
    for (int j = 0; j < 4; j++) {
        s.x += a[j]; s.y += a[j] * a[j];
        s.z += m[j]; s.w += m[j] * m[j];
    }
    s = block_reduce4(s);
    const float invD = 1.0f / (float)DD;
    float mua = s.x * invD;
    float vara = fmaxf(s.y * invD - mua * mua, 0.f);
    float rsa = rsqrtf(vara + LN_EPS);
    float mum = s.z * invD;
    float varm = fmaxf(s.w * invD - mum * mum, 0.f);
    float rsm = rsqrtf(varm + LN_EPS);

    float4 x4 = ((const float4*)(X + (size_t)t * DD))[tid];
    float4 g14 = ((const float4*)g1)[tid];
    float4 b14 = ((const float4*)be1)[tid];
    float4 g24 = ((const float4*)g2)[tid];
    float4 b24 = ((const float4*)be2)[tid];
    float xs[4] = {x4.x, x4.y, x4.z, x4.w};
    float g1s[4] = {g14.x, g14.y, g14.z, g14.w};
    float b1s[4] = {b14.x, b14.y, b14.z, b14.w};
    float g2s[4] = {g24.x, g24.y, g24.z, g24.w};
    float b2s[4] = {b24.x, b24.y, b24.z, b24.w};
    float o[4];
#pragma unroll
    for (int j = 0; j < 4; j++) {
        o[j] = xs[j]
             + (a[j] - mua) * rsa * g1s[j] + b1s[j]
             + (m[j] - mum) * rsm * g2s[j] + b2s[j];
    }
    ((float4*)(out + (size_t)t * DD))[tid] = make_float4(o[0], o[1], o[2], o[3]);
}

// ---------------- launch ----------------
extern "C" void kernel_launch(void* const* d_in, const int* in_sizes, int n_in,
                              void* d_out, int out_size)
{
    const float* x   = (const float*)d_in[0];
    const float* Wq  = (const float*)d_in[1];
    const float* Wk  = (const float*)d_in[2];
    const float* Wv  = (const float*)d_in[3];
    const float* Wg  = (const float*)d_in[4];
    const float* W1  = (const float*)d_in[5];
    const float* b1  = (const float*)d_in[6];
    const float* W2  = (const float*)d_in[7];
    const float* b2  = (const float*)d_in[8];
    const float* g1  = (const float*)d_in[9];
    const float* be1 = (const float*)d_in[10];
    const float* g2  = (const float*)d_in[11];
    const float* be2 = (const float*)d_in[12];
    float* out = (float*)d_out;

    cudaFuncSetAttribute(qkv_tc_kernel, cudaFuncAttributeMaxDynamicSharedMemorySize, GEMM_SMEM);
    cudaFuncSetAttribute(moe_tc_kernel<true>, cudaFuncAttributeMaxDynamicSharedMemorySize, GEMM_SMEM);
    cudaFuncSetAttribute(moe_tc_kernel<false>, cudaFuncAttributeMaxDynamicSharedMemorySize, GEMM_SMEM);
    cudaFuncSetAttribute(attn_tc_kernel, cudaFuncAttributeMaxDynamicSharedMemorySize, ATT_SMEM);

    __half* d_w1t; cudaGetSymbolAddress((void**)&d_w1t, g_w1t);
    __half* d_w2t; cudaGetSymbolAddress((void**)&d_w2t, g_w2t);
    __half* d_wqkv; cudaGetSymbolAddress((void**)&d_wqkv, g_wqkv);

    xcvt_kernel<<<NTOK * DD / 2048, 256>>>(x);
    transpose_cvt_kernel<<<dim3(HS / 32, DD / 32, HH), dim3(32, 8)>>>(Wq, d_wqkv, DD, HS);
    transpose_cvt_kernel<<<dim3(HS / 32, DD / 32, HH), dim3(32, 8)>>>(Wk, d_wqkv + (size_t)HH * HS * DD, DD, HS);
    transpose_cvt_kernel<<<dim3(HS / 32, DD / 32, HH), dim3(32, 8)>>>(Wv, d_wqkv + (size_t)2 * HH * HS * DD, DD, HS);
    transpose_cvt_kernel<<<dim3(DFF / 32, DD / 32, NE), dim3(32, 8)>>>(W1, d_w1t, DD, DFF);
    transpose_cvt_kernel<<<dim3(DD / 32, DFF / 32, NE), dim3(32, 8)>>>(W2, d_w2t, DFF, DD);
    route_kernel<<<NTOK / 8, 256>>>(x, Wg);
    qkv_tc_kernel<<<dim3(NTOK / 128, 24), 128, GEMM_SMEM>>>();
    attn_tc_kernel<<<dim3(16, BB * HH), 128, ATT_SMEM>>>();
    moe_tc_kernel<true><<<dim3(64, DFF / 128, NE), 128, GEMM_SMEM>>>(b1);
    moe_tc_kernel<false><<<dim3(64, DD / 128, NE), 128, GEMM_SMEM>>>(b2);
    final_kernel<<<NTOK, 256>>>(x, g1, be1, g2, be2, out);
}

// round 9
// speedup vs baseline: 11.4167x; 1.0336x over previous
#include <cuda_runtime.h>
#include <cuda_fp16.h>
#include <cstdint>
#include <math.h>

#define BB 8
#define TT 1024
#define DD 1024
#define HH 16
#define HS 64
#define NE 8
#define NTOK (BB*TT)        // 8192
#define DFF 4096
#define LN_EPS 1e-5f

// ---------------- scratch (device globals; no runtime allocation) ----------------
__device__ __half g_q[(size_t)BB*HH*TT*HS];      // fp16, Q pre-scaled by 2^-5
__device__ __half g_k[(size_t)BB*HH*TT*HS];
__device__ __half g_v[(size_t)BB*HH*TT*HS];
__device__ float  g_attn[(size_t)NTOK*DD];       // fp32
__device__ __half g_h[(size_t)NTOK*2*DFF];       // fp16 (post-relu), rowid = tok*2+slot
__device__ float  g_y[(size_t)NTOK*2*DD];        // fp32
__device__ float  g_wtok[NTOK*2];
__device__ int    g_rows[NE*NTOK];
__device__ int    g_cnt[NE];
__device__ __half g_xt[(size_t)NTOK*DD];         // fp16 of x
__device__ __half g_w1[(size_t)NE*DD*DFF];       // W1 fp16, native [e][k][n]
__device__ __half g_w2[(size_t)NE*DFF*DD];       // W2 fp16, native [e][k][n]
__device__ __half g_wqkv[(size_t)3*HH*DD*HS];    // native [part][h][k][hs] fp16

// ---------------- helpers ----------------
__device__ __forceinline__ uint32_t smem_u32(const void* p) {
    uint32_t a;
    asm("{ .reg .u64 t; cvta.to.shared.u64 t, %1; cvt.u32.u64 %0, t; }" : "=r"(a) : "l"(p));
    return a;
}
#define SWZ(b) ((b) ^ (((b) >> 3) & 0x70))

__device__ __forceinline__ void mma_f16(float* c,
    uint32_t a0, uint32_t a1, uint32_t a2, uint32_t a3,
    uint32_t b0, uint32_t b1)
{
    asm volatile(
        "mma.sync.aligned.m16n8k16.row.col.f32.f16.f16.f32 "
        "{%0,%1,%2,%3}, {%4,%5,%6,%7}, {%8,%9}, {%0,%1,%2,%3};"
        : "+f"(c[0]), "+f"(c[1]), "+f"(c[2]), "+f"(c[3])
        : "r"(a0), "r"(a1), "r"(a2), "r"(a3), "r"(b0), "r"(b1));
}
__device__ __forceinline__ void ldsm_x4(uint32_t* r, uint32_t addr) {
    asm volatile("ldmatrix.sync.aligned.m8n8.x4.shared.b16 {%0,%1,%2,%3}, [%4];"
        : "=r"(r[0]), "=r"(r[1]), "=r"(r[2]), "=r"(r[3]) : "r"(addr));
}
__device__ __forceinline__ void ldsm_x2(uint32_t* r, uint32_t addr) {
    asm volatile("ldmatrix.sync.aligned.m8n8.x2.shared.b16 {%0,%1}, [%2];"
        : "=r"(r[0]), "=r"(r[1]) : "r"(addr));
}
__device__ __forceinline__ void ldsm_x2t(uint32_t* r, uint32_t addr) {
    asm volatile("ldmatrix.sync.aligned.m8n8.x2.trans.shared.b16 {%0,%1}, [%2];"
        : "=r"(r[0]), "=r"(r[1]) : "r"(addr));
}
#define CP_ASYNC16(dst, src) \
    asm volatile("cp.async.cg.shared.global [%0], [%1], 16;" :: "r"(dst), "l"((const void*)(src)))
#define CP_COMMIT() asm volatile("cp.async.commit_group;" ::: "memory")
#define CP_WAIT1() asm volatile("cp.async.wait_group 1;" ::: "memory")

__device__ __forceinline__ uint32_t h2u(float a, float b) {
    __half2 h = __floats2half2_rn(a, b);
    return *(uint32_t*)&h;
}

// GEMM smem: 3 stages x (A 16KB + B 16KB) = 96KB ; K-chunk = 64
#define ST_BYTES 16384
#define GEMM_SMEM (6 * ST_BYTES + 1024)

// ---------------- preprocessing ----------------
// x fp32 -> fp16, 8 elems/thread; also zeroes expert counters
__global__ __launch_bounds__(256) void xcvt_kernel(const float* __restrict__ X) {
    if (blockIdx.x == 0 && threadIdx.x < NE) g_cnt[threadIdx.x] = 0;
    size_t i = ((size_t)blockIdx.x * 256 + threadIdx.x) * 8;
    float4 v0 = *(const float4*)(X + i);
    float4 v1 = *(const float4*)(X + i + 4);
    uint4 u = make_uint4(h2u(v0.x, v0.y), h2u(v0.z, v0.w),
                         h2u(v1.x, v1.y), h2u(v1.z, v1.w));
    *(uint4*)(g_xt + i) = u;
}

// streaming fp32 -> fp16 copy (same layout), 8 elems/thread
__global__ __launch_bounds__(256) void wcvt_kernel(
    const float* __restrict__ in, __half* __restrict__ out)
{
    size_t i = ((size_t)blockIdx.x * 256 + threadIdx.x) * 8;
    float4 v0 = *(const float4*)(in + i);
    float4 v1 = *(const float4*)(in + i + 4);
    uint4 u = make_uint4(h2u(v0.x, v0.y), h2u(v0.z, v0.w),
                         h2u(v1.x, v1.y), h2u(v1.z, v1.w));
    *(uint4*)(out + i) = u;
}

// =======================================================================
// QKV GEMM: grid (64, 24), block 128 (4 warps, 64x64 warp tiles)
// B tile: [64 k-rows][128 n] = 2 subtiles (head) of 64x128B, SW128
// =======================================================================
__global__ __launch_bounds__(128) void qkv_tc_kernel()
{
    const int row0 = blockIdx.x * 128;
    const int by = blockIdx.y;
    const int part = by >> 3;
    const int h0 = (by & 7) * 2;
    __half* Out = (part == 0) ? g_q : (part == 1) ? g_k : g_v;
    const float qscale = (part == 0) ? 0.03125f : 1.0f;

    extern __shared__ char dynraw[];
    char* p = (char*)(((uintptr_t)dynraw + 1023) & ~(uintptr_t)1023);
    const uint32_t sb = smem_u32(p);
    const int tid = threadIdx.x;
    const int wid = tid >> 5, lane = tid & 31;
    const int wm = (wid & 1) * 64, wn = (wid >> 1) * 64;

    const int quad = lane >> 3, lr = lane & 7;
    const uint32_t a_rowb = (uint32_t)(wm + (quad & 1) * 8 + lr) * 128;
    const uint32_t a_boff = (uint32_t)(quad >> 1) * 16;
    const uint32_t xv = (uint32_t)lr << 4;
    const uint32_t bt_row = (uint32_t)(((lane >> 3) & 1) * 8 + lr) * 128;  // trans-load rows

    float acc[4][8][4];
#pragma unroll
    for (int i = 0; i < 4; i++)
#pragma unroll
        for (int j = 0; j < 8; j++)
#pragma unroll
            for (int q = 0; q < 4; q++) acc[i][j][q] = 0.f;

    const int NCH = DD / 64;
    auto issue = [&](int c) {
        int k0 = c * 64;
        int s = c % 3;
        uint32_t ab = sb + s * ST_BYTES;
        uint32_t bb = sb + 3 * ST_BYTES + s * ST_BYTES;
#pragma unroll
        for (int i = 0; i < 8; i++) {
            int idx = tid + i * 128;
            // A: 128 m-rows x 64 k
            {
                int row = idx >> 3, c16 = idx & 7;
                const __half* asrc = g_xt + (size_t)(row0 + row) * DD + k0 + c16 * 8;
                CP_ASYNC16(ab + SWZ(row * 128 + c16 * 16), asrc);
            }
            // B: 2 subtiles x 64 k-rows x 128B (one head row each)
            {
                int sub = idx >> 9, rem = idx & 511;
                int r = rem >> 3, c16 = rem & 7;
                const __half* bsrc = g_wqkv +
                    ((size_t)(part * HH + h0 + sub) * DD + k0 + r) * HS + c16 * 8;
                CP_ASYNC16(bb + sub * 8192 + SWZ(r * 128 + c16 * 16), bsrc);
            }
        }
        CP_COMMIT();
    };
    issue(0); issue(1);

    for (int c = 0; c < NCH; c++) {
        CP_WAIT1();
        __syncthreads();
        if (c + 2 < NCH) issue(c + 2); else CP_COMMIT();
        const int s = c % 3;
        const uint32_t At = sb + s * ST_BYTES;
        const uint32_t Bt = sb + 3 * ST_BYTES + s * ST_BYTES;
#pragma unroll
        for (int ks = 0; ks < 4; ks++) {
            uint32_t akoff = (((uint32_t)ks * 32) + a_boff) ^ xv;
            uint32_t trow = (uint32_t)(ks * 16) * 128 + bt_row;
            uint32_t af[4][4], bf[8][2];
#pragma unroll
            for (int mt = 0; mt < 4; mt++)
                ldsm_x4(af[mt], At + a_rowb + mt * 2048 + akoff);
#pragma unroll
            for (int nt = 0; nt < 8; nt++) {
                int gn = wn + nt * 8;
                uint32_t sub = (uint32_t)(gn >> 6) * 8192;
                uint32_t cb = (uint32_t)((gn & 63) * 2);
                ldsm_x2t(bf[nt], Bt + sub + trow + (cb ^ xv));
            }
#pragma unroll
            for (int mt = 0; mt < 4; mt++)
#pragma unroll
                for (int nt = 0; nt < 8; nt++)
                    mma_f16(acc[mt][nt], af[mt][0], af[mt][1], af[mt][2], af[mt][3],
                            bf[nt][0], bf[nt][1]);
        }
        __syncthreads();
    }

    // epilogue: fp16 out (Q pre-scaled)
#pragma unroll
    for (int mt = 0; mt < 4; mt++) {
        int r = row0 + wm + mt * 16 + (lane >> 2);
        int r1 = r + 8;
        int b0i = r >> 10, t0 = r & 1023;
        int b1i = r1 >> 10, t1 = r1 & 1023;
#pragma unroll
        for (int nt = 0; nt < 8; nt++) {
            int n = wn + nt * 8 + 2 * (lane & 3);
            int head = h0 + (n >> 6);
            int hs = n & 63;
            *(uint32_t*)(Out + (((size_t)b0i * HH + head) * TT + t0) * HS + hs) =
                h2u(acc[mt][nt][0] * qscale, acc[mt][nt][1] * qscale);
            *(uint32_t*)(Out + (((size_t)b1i * HH + head) * TT + t1) * HS + hs) =
                h2u(acc[mt][nt][2] * qscale, acc[mt][nt][3] * qscale);
        }
    }
}

// =======================================================================
// MoE GEMM (G1: xt@W1+relu -> g_h fp16, else g_h@W2 -> g_y fp32)
// grid (64, Ntiles, NE), block 128. B native [k][n]; frags via ldsm.trans
// =======================================================================
template<bool G1>
__global__ __launch_bounds__(128) void moe_tc_kernel(
    const float* __restrict__ biasfull)
{
    const int e = blockIdx.z;
    const int cnt = g_cnt[e];
    const int m0 = blockIdx.x * 128;
    if (m0 >= cnt) return;
    const int col0 = blockIdx.y * 128;
    const int KTOT = G1 ? DD : DFF;
    const int LDB  = G1 ? DFF : DD;
    const int LDO  = G1 ? DFF : DD;
    const int NCH = KTOT / 64;

    extern __shared__ char dynraw[];
    char* p = (char*)(((uintptr_t)dynraw + 1023) & ~(uintptr_t)1023);
    const uint32_t sb = smem_u32(p);

    __shared__ int rowids[128];
    const int tid = threadIdx.x;
    {
        int m = m0 + tid;
        rowids[tid] = (m < cnt) ? g_rows[e * NTOK + m] : -1;
    }
    __syncthreads();

    const int wid = tid >> 5, lane = tid & 31;
    const int wm = (wid & 1) * 64, wn = (wid >> 1) * 64;
    const int quad = lane >> 3, lr = lane & 7;
    const uint32_t a_rowb = (uint32_t)(wm + (quad & 1) * 8 + lr) * 128;
    const uint32_t a_boff = (uint32_t)(quad >> 1) * 16;
    const uint32_t xv = (uint32_t)lr << 4;
    const uint32_t bt_row = (uint32_t)(((lane >> 3) & 1) * 8 + lr) * 128;

    float acc[4][8][4];
#pragma unroll
    for (int i = 0; i < 4; i++)
#pragma unroll
        for (int j = 0; j < 8; j++)
#pragma unroll
            for (int q = 0; q < 4; q++) acc[i][j][q] = 0.f;

    const __half* Wp = (G1 ? g_w1 : g_w2) + (size_t)e * ((size_t)DD * DFF);
    const float* bp = biasfull + (size_t)e * (G1 ? DFF : DD);

    auto issue = [&](int c) {
        int k0 = c * 64;
        int s = c % 3;
        uint32_t ab = sb + s * ST_BYTES;
        uint32_t bb = sb + 3 * ST_BYTES + s * ST_BYTES;
#pragma unroll
        for (int i = 0; i < 8; i++) {
            int idx = tid + i * 128;
            {
                int row = idx >> 3, c16 = idx & 7;
                int rid = rowids[row];
                const __half* asrc;
                if (G1) asrc = g_xt + (size_t)((rid >= 0) ? (rid >> 1) : 0) * DD + k0 + c16 * 8;
                else    asrc = g_h + (size_t)((rid >= 0) ? rid : 0) * DFF + k0 + c16 * 8;
                CP_ASYNC16(ab + SWZ(row * 128 + c16 * 16), asrc);
            }
            {
                int sub = idx >> 9, rem = idx & 511;
                int r = rem >> 3, c16 = rem & 7;
                const __half* bsrc = Wp + (size_t)(k0 + r) * LDB + col0 + sub * 64 + c16 * 8;
                CP_ASYNC16(bb + sub * 8192 + SWZ(r * 128 + c16 * 16), bsrc);
            }
        }
        CP_COMMIT();
    };
    issue(0); issue(1);

    for (int c = 0; c < NCH; c++) {
        CP_WAIT1();
        __syncthreads();
        if (c + 2 < NCH) issue(c + 2); else CP_COMMIT();
        const int s = c % 3;
        const uint32_t At = sb + s * ST_BYTES;
        const uint32_t Bt = sb + 3 * ST_BYTES + s * ST_BYTES;
#pragma unroll
        for (int ks = 0; ks < 4; ks++) {
            uint32_t akoff = (((uint32_t)ks * 32) + a_boff) ^ xv;
            uint32_t trow = (uint32_t)(ks * 16) * 128 + bt_row;
            uint32_t af[4][4], bf[8][2];
#pragma unroll
            for (int mt = 0; mt < 4; mt++)
                ldsm_x4(af[mt], At + a_rowb + mt * 2048 + akoff);
#pragma unroll
            for (int nt = 0; nt < 8; nt++) {
                int gn = wn + nt * 8;
                uint32_t sub = (uint32_t)(gn >> 6) * 8192;
                uint32_t cb = (uint32_t)((gn & 63) * 2);
                ldsm_x2t(bf[nt], Bt + sub + trow + (cb ^ xv));
            }
#pragma unroll
            for (int mt = 0; mt < 4; mt++)
#pragma unroll
                for (int nt = 0; nt < 8; nt++)
                    mma_f16(acc[mt][nt], af[mt][0], af[mt][1], af[mt][2], af[mt][3],
                            bf[nt][0], bf[nt][1]);
        }
        __syncthreads();
    }

#pragma unroll
    for (int mt = 0; mt < 4; mt++) {
        int ml = wm + mt * 16 + (lane >> 2);
        int rid0 = rowids[ml];
        int rid1 = rowids[ml + 8];
#pragma unroll
        for (int nt = 0; nt < 8; nt++) {
            int n = col0 + wn + nt * 8 + 2 * (lane & 3);
            float bx = __ldg(&bp[n]), by = __ldg(&bp[n + 1]);
            if (G1) {
                if (rid0 >= 0) {
                    float v0 = fmaxf(acc[mt][nt][0] + bx, 0.f);
                    float v1 = fmaxf(acc[mt][nt][1] + by, 0.f);
                    *(uint32_t*)(g_h + (size_t)rid0 * LDO + n) = h2u(v0, v1);
                }
                if (rid1 >= 0) {
                    float v2 = fmaxf(acc[mt][nt][2] + bx, 0.f);
                    float v3 = fmaxf(acc[mt][nt][3] + by, 0.f);
                    *(uint32_t*)(g_h + (size_t)rid1 * LDO + n) = h2u(v2, v3);
                }
            } else {
                if (rid0 >= 0)
                    *(float2*)(g_y + (size_t)rid0 * LDO + n) =
                        make_float2(acc[mt][nt][0] + bx, acc[mt][nt][1] + by);
                if (rid1 >= 0)
                    *(float2*)(g_y + (size_t)rid1 * LDO + n) =
                        make_float2(acc[mt][nt][2] + bx, acc[mt][nt][3] + by);
            }
        }
    }
}

// =======================================================================
// fp16 tensor-core causal flash attention, cp.async double-buffered K/V
// grid (16, 128), block 128. smem: P/Q 8KB + 2 stages x (K 8KB + V 8KB)
// =======================================================================
#define ATT_SMEM (8192 + 2 * 16384)

__global__ __launch_bounds__(128) void attn_tc_kernel()
{
    extern __shared__ char asc[];
    const uint32_t psb = smem_u32(asc);
    const uint32_t kvb = psb + 8192;

    const int bh = blockIdx.y;
    const int qt = 15 - blockIdx.x;
    const int tid = threadIdx.x;
    const int wid = tid >> 5, lane = tid & 31;
    const int gid = lane >> 2, tq = lane & 3;
    const int quad = lane >> 3, lr = lane & 7;
    const int qrow = wid * 16 + gid;
    const int qglob = qt * 64;

    const uint32_t a_rowb = (uint32_t)(wid * 16 + (quad & 1) * 8 + lr) * 128;
    const uint32_t a_boff = (uint32_t)(quad >> 1) * 16;
    const uint32_t b_boff = (uint32_t)((lane >> 3) & 1) * 16;
    const uint32_t xv = (uint32_t)lr << 4;
    const uint32_t v_rowb = (uint32_t)(((lane >> 3) & 1) * 8 + lr) * 128;
    const uint32_t xvq = (uint32_t)gid << 4;

    auto issue_kv = [&](int kt) {
        int s = kt & 1;
        uint32_t kb = kvb + s * 16384;
        uint32_t vb = kb + 8192;
        const __half* kp = g_k + ((size_t)bh * TT + kt * 64) * HS;
        const __half* vp = g_v + ((size_t)bh * TT + kt * 64) * HS;
#pragma unroll
        for (int i = 0; i < 4; i++) {
            int idx = tid + i * 128;
            int r = idx >> 3, c16 = idx & 7;
            CP_ASYNC16(kb + SWZ(r * 128 + c16 * 16), kp + (size_t)r * HS + c16 * 8);
            CP_ASYNC16(vb + SWZ(r * 128 + c16 * 16), vp + (size_t)r * HS + c16 * 8);
        }
        CP_COMMIT();
    };

    // Q into P buffer
    {
        const __half* qp = g_q + ((size_t)bh * TT + qglob) * HS;
#pragma unroll
        for (int i = 0; i < 4; i++) {
            int idx = tid + i * 128;
            int r = idx >> 3, c16 = idx & 7;
            CP_ASYNC16(psb + SWZ(r * 128 + c16 * 16), qp + (size_t)r * HS + c16 * 8);
        }
        CP_COMMIT();
    }
    issue_kv(0);
    CP_WAIT1();
    __syncthreads();

    uint32_t qf[4][4];
#pragma unroll
    for (int ks = 0; ks < 4; ks++)
        ldsm_x4(qf[ks], psb + a_rowb + ((((uint32_t)ks * 32) + a_boff) ^ xv));
    __syncthreads();

    float oacc[8][4];
#pragma unroll
    for (int i = 0; i < 8; i++)
#pragma unroll
        for (int j = 0; j < 4; j++) oacc[i][j] = 0.f;
    float m0 = -INFINITY, m1 = -INFINITY, l0 = 0.f, l1 = 0.f;

    for (int kt = 0; kt <= qt; kt++) {
        if (kt + 1 <= qt) issue_kv(kt + 1); else CP_COMMIT();
        CP_WAIT1();
        __syncthreads();
        const int s = kt & 1;
        const uint32_t Kb = kvb + s * 16384;
        const uint32_t Vb = Kb + 8192;

        float sacc[8][4];
#pragma unroll
        for (int nt = 0; nt < 8; nt++)
#pragma unroll
            for (int j = 0; j < 4; j++) sacc[nt][j] = 0.f;
#pragma unroll
        for (int ks = 0; ks < 4; ks++) {
            uint32_t bkoff = (((uint32_t)ks * 32) + b_boff) ^ xv;
#pragma unroll
            for (int nt = 0; nt < 8; nt++) {
                uint32_t bf[2];
                ldsm_x2(bf, Kb + (uint32_t)(nt * 8 + lr) * 128 + bkoff);
                mma_f16(sacc[nt], qf[ks][0], qf[ks][1], qf[ks][2], qf[ks][3], bf[0], bf[1]);
            }
        }
        if (kt == qt) {
#pragma unroll
            for (int nt = 0; nt < 8; nt++) {
                int col = nt * 8 + 2 * tq;
                if (col     > qrow)     sacc[nt][0] = -INFINITY;
                if (col + 1 > qrow)     sacc[nt][1] = -INFINITY;
                if (col     > qrow + 8) sacc[nt][2] = -INFINITY;
                if (col + 1 > qrow + 8) sacc[nt][3] = -INFINITY;
            }
        }
        float r0 = -INFINITY, r1 = -INFINITY;
#pragma unroll
        for (int nt = 0; nt < 8; nt++) {
            r0 = fmaxf(r0, fmaxf(sacc[nt][0], sacc[nt][1]));
            r1 = fmaxf(r1, fmaxf(sacc[nt][2], sacc[nt][3]));
        }
        r0 = fmaxf(r0, __shfl_xor_sync(0xffffffffu, r0, 1));
        r0 = fmaxf(r0, __shfl_xor_sync(0xffffffffu, r0, 2));
        r1 = fmaxf(r1, __shfl_xor_sync(0xffffffffu, r1, 1));
        r1 = fmaxf(r1, __shfl_xor_sync(0xffffffffu, r1, 2));
        float mn0 = fmaxf(m0, r0), mn1 = fmaxf(m1, r1);
        float c0 = __expf(m0 - mn0), c1 = __expf(m1 - mn1);
        float ps0 = 0.f, ps1 = 0.f;
#pragma unroll
        for (int nt = 0; nt < 8; nt++) {
            float p0 = __expf(sacc[nt][0] - mn0);
            float p1 = __expf(sacc[nt][1] - mn0);
            float p2 = __expf(sacc[nt][2] - mn1);
            float p3 = __expf(sacc[nt][3] - mn1);
            ps0 += p0 + p1; ps1 += p2 + p3;
            uint32_t boff = (uint32_t)(nt * 16 + 4 * tq) ^ xvq;
            *(uint32_t*)(asc + qrow * 128 + boff)       = h2u(p0, p1);
            *(uint32_t*)(asc + (qrow + 8) * 128 + boff) = h2u(p2, p3);
        }
        ps0 += __shfl_xor_sync(0xffffffffu, ps0, 1);
        ps0 += __shfl_xor_sync(0xffffffffu, ps0, 2);
        ps1 += __shfl_xor_sync(0xffffffffu, ps1, 1);
        ps1 += __shfl_xor_sync(0xffffffffu, ps1, 2);
        l0 = l0 * c0 + ps0;
        l1 = l1 * c1 + ps1;
#pragma unroll
        for (int dt = 0; dt < 8; dt++) {
            oacc[dt][0] *= c0; oacc[dt][1] *= c0;
            oacc[dt][2] *= c1; oacc[dt][3] *= c1;
        }
        m0 = mn0; m1 = mn1;
        __syncwarp();
        // O += P V  (P A-frags natural, V B-frags via ldmatrix.trans)
#pragma unroll
        for (int ks = 0; ks < 4; ks++) {
            uint32_t pa[4];
            ldsm_x4(pa, psb + a_rowb + ((((uint32_t)ks * 32) + a_boff) ^ xv));
            uint32_t vrow = (uint32_t)(ks * 16) * 128 + v_rowb;
#pragma unroll
            for (int dt = 0; dt < 8; dt++) {
                uint32_t bv[2];
                ldsm_x2t(bv, Vb + vrow + (((uint32_t)dt * 16) ^ xv));
                mma_f16(oacc[dt], pa[0], pa[1], pa[2], pa[3], bv[0], bv[1]);
            }
        }
        __syncthreads();
    }

    float i0 = 1.f / l0, i1 = 1.f / l1;
    int b = bh >> 4, h = bh & 15;
    int gq0 = qglob + qrow, gq1 = gq0 + 8;
#pragma unroll
    for (int dt = 0; dt < 8; dt++) {
        int d = h * HS + dt * 8 + 2 * tq;
        *(float2*)(g_attn + ((size_t)b * TT + gq0) * DD + d) =
            make_float2(oacc[dt][0] * i0, oacc[dt][1] * i0);
        *(float2*)(g_attn + ((size_t)b * TT + gq1) * DD + d) =
            make_float2(oacc[dt][2] * i1, oacc[dt][3] * i1);
    }
}

// ---------------- MoE routing (vectorized) ----------------
__global__ __launch_bounds__(256) void route_kernel(
    const float* __restrict__ X, const float* __restrict__ Wg)
{
    int tok = (blockIdx.x * blockDim.x + threadIdx.x) >> 5;
    int lane = threadIdx.x & 31;
    if (tok >= NTOK) return;
    const float* xr = X + (size_t)tok * DD;
    float p[NE];
#pragma unroll
    for (int e = 0; e < NE; e++) p[e] = 0.f;
#pragma unroll
    for (int it = 0; it < DD / 128; it++) {
        int d4 = lane + it * 32;
        float4 xv4 = *(const float4*)(xr + d4 * 4);
        const float* wr = Wg + (size_t)d4 * 4 * NE;
        float xs[4] = {xv4.x, xv4.y, xv4.z, xv4.w};
#pragma unroll
        for (int dd = 0; dd < 4; dd++) {
            float4 w0 = *(const float4*)(wr + dd * 8);
            float4 w1 = *(const float4*)(wr + dd * 8 + 4);
            p[0] += xs[dd] * w0.x; p[1] += xs[dd] * w0.y;
            p[2] += xs[dd] * w0.z; p[3] += xs[dd] * w0.w;
            p[4] += xs[dd] * w1.x; p[5] += xs[dd] * w1.y;
            p[6] += xs[dd] * w1.z; p[7] += xs[dd] * w1.w;
        }
    }
#pragma unroll
    for (int e = 0; e < NE; e++)
#pragma unroll
        for (int off = 16; off; off >>= 1)
            p[e] += __shfl_xor_sync(0xffffffffu, p[e], off);

    if (lane == 0) {
        int i0 = 0; float v0 = p[0];
#pragma unroll
        for (int e = 1; e < NE; e++) if (p[e] > v0) { v0 = p[e]; i0 = e; }
        int i1 = -1; float v1 = -INFINITY;
#pragma unroll
        for (int e = 0; e < NE; e++) if (e != i0 && p[e] > v1) { v1 = p[e]; i1 = e; }
        float e1v = expf(v1 - v0);
        float inv = 1.f / (1.f + e1v);
        g_wtok[tok * 2 + 0] = inv;
        g_wtok[tok * 2 + 1] = e1v * inv;
        int pos0 = atomicAdd(&g_cnt[i0], 1);
        g_rows[i0 * NTOK + pos0] = tok * 2;
        int pos1 = atomicAdd(&g_cnt[i1], 1);
        g_rows[i1 * NTOK + pos1] = tok * 2 + 1;
    }
}

// ---------------- final LN+residual ----------------
__device__ __forceinline__ float4 block_reduce4(float4 v) {
    __shared__ float4 sh[8];
    __shared__ float4 bc;
    int lane = threadIdx.x & 31, w = threadIdx.x >> 5;
#pragma unroll
    for (int off = 16; off; off >>= 1) {
        v.x += __shfl_xor_sync(0xffffffffu, v.x, off);
        v.y += __shfl_xor_sync(0xffffffffu, v.y, off);
        v.z += __shfl_xor_sync(0xffffffffu, v.z, off);
        v.w += __shfl_xor_sync(0xffffffffu, v.w, off);
    }
    if (lane == 0) sh[w] = v;
    __syncthreads();
    if (w == 0) {
        float4 t = (lane < 8) ? sh[lane] : make_float4(0, 0, 0, 0);
#pragma unroll
        for (int off = 4; off; off >>= 1) {
            t.x += __shfl_xor_sync(0xffffffffu, t.x, off);
            t.y += __shfl_xor_sync(0xffffffffu, t.y, off);
            t.z += __shfl_xor_sync(0xffffffffu, t.z, off);
            t.w += __shfl_xor_sync(0xffffffffu, t.w, off);
        }
        if (lane == 0) bc = t;
    }
    __syncthreads();
    return bc;
}

__global__ __launch_bounds__(256) void final_kernel(
    const float* __restrict__ X,
    const float* __restrict__ g1, const float* __restrict__ be1,
    const float* __restrict__ g2, const float* __restrict__ be2,
    float* __restrict__ out)
{
    int t = blockIdx.x;
    int tid = threadIdx.x;
    const float* ar = g_attn + (size_t)t * DD;
    const float* y0 = g_y + (size_t)(t * 2) * DD;
    const float* y1 = g_y + (size_t)(t * 2 + 1) * DD;
    float w0 = g_wtok[t * 2], w1 = g_wtok[t * 2 + 1];

    float4 a4 = ((const float4*)ar)[tid];
    float4 y04 = ((const float4*)y0)[tid];
    float4 y14 = ((const float4*)y1)[tid];
    float a[4] = {a4.x, a4.y, a4.z, a4.w};
    float m[4] = {w0 * y04.x + w1 * y14.x, w0 * y04.y + w1 * y14.y,
                  w0 * y04.z + w1 * y14.z, w0 * y04.w + w1 * y14.w};

    float4 s = make_float4(0, 0, 0, 0);
#pragma unroll
    for (int j = 0; j < 4; j++) {
        s.x += a[j]; s.y += a[j] * a[j];
        s.z += m[j]; s.w += m[j] * m[j];
    }
    s = block_reduce4(s);
    const float invD = 1.0f / (float)DD;
    float mua = s.x * invD;
    float vara = fmaxf(s.y * invD - mua * mua, 0.f);
    float rsa = rsqrtf(vara + LN_EPS);
    float mum = s.z * invD;
    float varm = fmaxf(s.w * invD - mum * mum, 0.f);
    float rsm = rsqrtf(varm + LN_EPS);

    float4 x4 = ((const float4*)(X + (size_t)t * DD))[tid];
    float4 g14 = ((const float4*)g1)[tid];
    float4 b14 = ((const float4*)be1)[tid];
    float4 g24 = ((const float4*)g2)[tid];
    float4 b24 = ((const float4*)be2)[tid];
    float xs[4] = {x4.x, x4.y, x4.z, x4.w};
    float g1s[4] = {g14.x, g14.y, g14.z, g14.w};
    float b1s[4] = {b14.x, b14.y, b14.z, b14.w};
    float g2s[4] = {g24.x, g24.y, g24.z, g24.w};
    float b2s[4] = {b24.x, b24.y, b24.z, b24.w};
    float o[4];
#pragma unroll
    for (int j = 0; j < 4; j++) {
        o[j] = xs[j]
             + (a[j] - mua) * rsa * g1s[j] + b1s[j]
             + (m[j] - mum) * rsm * g2s[j] + b2s[j];
    }
    ((float4*)(out + (size_t)t * DD))[tid] = make_float4(o[0], o[1], o[2], o[3]);
}

// ---------------- launch ----------------
extern "C" void kernel_launch(void* const* d_in, const int* in_sizes, int n_in,
                              void* d_out, int out_size)
{
    const float* x   = (const float*)d_in[0];
    const float* Wq  = (const float*)d_in[1];
    const float* Wk  = (const float*)d_in[2];
    const float* Wv  = (const float*)d_in[3];
    const float* Wg  = (const float*)d_in[4];
    const float* W1  = (const float*)d_in[5];
    const float* b1  = (const float*)d_in[6];
    const float* W2  = (const float*)d_in[7];
    const float* b2  = (const float*)d_in[8];
    const float* g1  = (const float*)d_in[9];
    const float* be1 = (const float*)d_in[10];
    const float* g2  = (const float*)d_in[11];
    const float* be2 = (const float*)d_in[12];
    float* out = (float*)d_out;

    cudaFuncSetAttribute(qkv_tc_kernel, cudaFuncAttributeMaxDynamicSharedMemorySize, GEMM_SMEM);
    cudaFuncSetAttribute(moe_tc_kernel<true>, cudaFuncAttributeMaxDynamicSharedMemorySize, GEMM_SMEM);
    cudaFuncSetAttribute(moe_tc_kernel<false>, cudaFuncAttributeMaxDynamicSharedMemorySize, GEMM_SMEM);
    cudaFuncSetAttribute(attn_tc_kernel, cudaFuncAttributeMaxDynamicSharedMemorySize, ATT_SMEM);

    __half* d_w1; cudaGetSymbolAddress((void**)&d_w1, g_w1);
    __half* d_w2; cudaGetSymbolAddress((void**)&d_w2, g_w2);
    __half* d_wqkv; cudaGetSymbolAddress((void**)&d_wqkv, g_wqkv);

    const size_t WQKV1 = (size_t)HH * DD * HS;              // 1M elems per part
    const size_t WEXP  = (size_t)NE * DD * DFF;             // 33.5M elems

    xcvt_kernel<<<NTOK * DD / 2048, 256>>>(x);
    wcvt_kernel<<<(int)(WQKV1 / 2048), 256>>>(Wq, d_wqkv);
    wcvt_kernel<<<(int)(WQKV1 / 2048), 256>>>(Wk, d_wqkv + WQKV1);
    wcvt_kernel<<<(int)(WQKV1 / 2048), 256>>>(Wv, d_wqkv + 2 * WQKV1);
    wcvt_kernel<<<(int)(WEXP / 2048), 256>>>(W1, d_w1);
    wcvt_kernel<<<(int)(WEXP / 2048), 256>>>(W2, d_w2);
    route_kernel<<<NTOK / 8, 256>>>(x, Wg);
    qkv_tc_kernel<<<dim3(NTOK / 128, 24), 128, GEMM_SMEM>>>();
    attn_tc_kernel<<<dim3(16, BB * HH), 128, ATT_SMEM>>>();
    moe_tc_kernel<true><<<dim3(64, DFF / 128, NE), 128, GEMM_SMEM>>>(b1);
    moe_tc_kernel<false><<<dim3(64, DD / 128, NE), 128, GEMM_SMEM>>>(b2);
    final_kernel<<<NTOK, 256>>>(x, g1, be1, g2, be2, out);
}

// round 10
// speedup vs baseline: 12.0397x; 1.0546x over previous
#include <cuda_runtime.h>
#include <cuda_fp16.h>
#include <cstdint>
#include <math.h>

#define BB 8
#define TT 1024
#define DD 1024
#define HH 16
#define HS 64
#define NE 8
#define NTOK (BB*TT)        // 8192
#define DFF 4096
#define LN_EPS 1e-5f

// ---------------- scratch (device globals; no runtime allocation) ----------------
__device__ __half g_q[(size_t)BB*HH*TT*HS];      // fp16, Q pre-scaled by 2^-5
__device__ __half g_k[(size_t)BB*HH*TT*HS];
__device__ __half g_v[(size_t)BB*HH*TT*HS];
__device__ float  g_attn[(size_t)NTOK*DD];       // fp32
__device__ __half g_h[(size_t)NTOK*2*DFF];       // fp16 (post-relu), rowid = tok*2+slot
__device__ float  g_y[(size_t)NTOK*2*DD];        // fp32
__device__ float  g_wtok[NTOK*2];
__device__ int    g_rows[NE*NTOK];
__device__ int    g_cnt[NE];
__device__ __half g_xt[(size_t)NTOK*DD];         // fp16 of x
__device__ __half g_w1[(size_t)NE*DD*DFF];       // W1 fp16, native [e][k][n]
__device__ __half g_w2[(size_t)NE*DFF*DD];       // W2 fp16, native [e][k][n]
__device__ __half g_wqkv[(size_t)3*HH*DD*HS];    // native [part][h][k][hs] fp16

// ---------------- helpers ----------------
__device__ __forceinline__ uint32_t smem_u32(const void* p) {
    uint32_t a;
    asm("{ .reg .u64 t; cvta.to.shared.u64 t, %1; cvt.u32.u64 %0, t; }" : "=r"(a) : "l"(p));
    return a;
}
#define SWZ(b) ((b) ^ (((b) >> 3) & 0x70))

__device__ __forceinline__ void mma_f16(float* c,
    uint32_t a0, uint32_t a1, uint32_t a2, uint32_t a3,
    uint32_t b0, uint32_t b1)
{
    asm volatile(
        "mma.sync.aligned.m16n8k16.row.col.f32.f16.f16.f32 "
        "{%0,%1,%2,%3}, {%4,%5,%6,%7}, {%8,%9}, {%0,%1,%2,%3};"
        : "+f"(c[0]), "+f"(c[1]), "+f"(c[2]), "+f"(c[3])
        : "r"(a0), "r"(a1), "r"(a2), "r"(a3), "r"(b0), "r"(b1));
}
__device__ __forceinline__ void ldsm_x4(uint32_t* r, uint32_t addr) {
    asm volatile("ldmatrix.sync.aligned.m8n8.x4.shared.b16 {%0,%1,%2,%3}, [%4];"
        : "=r"(r[0]), "=r"(r[1]), "=r"(r[2]), "=r"(r[3]) : "r"(addr));
}
__device__ __forceinline__ void ldsm_x2(uint32_t* r, uint32_t addr) {
    asm volatile("ldmatrix.sync.aligned.m8n8.x2.shared.b16 {%0,%1}, [%2];"
        : "=r"(r[0]), "=r"(r[1]) : "r"(addr));
}
__device__ __forceinline__ void ldsm_x2t(uint32_t* r, uint32_t addr) {
    asm volatile("ldmatrix.sync.aligned.m8n8.x2.trans.shared.b16 {%0,%1}, [%2];"
        : "=r"(r[0]), "=r"(r[1]) : "r"(addr));
}
#define CP_ASYNC16(dst, src) \
    asm volatile("cp.async.cg.shared.global [%0], [%1], 16;" :: "r"(dst), "l"((const void*)(src)))
#define CP_COMMIT() asm volatile("cp.async.commit_group;" ::: "memory")
#define CP_WAIT1() asm volatile("cp.async.wait_group 1;" ::: "memory")

__device__ __forceinline__ uint32_t h2u(float a, float b) {
    __half2 h = __floats2half2_rn(a, b);
    return *(uint32_t*)&h;
}

// GEMM smem: 3 stages x (A 16KB + B 16KB) = 96KB ; K-chunk = 64
#define ST_BYTES 16384
#define GEMM_SMEM (6 * ST_BYTES + 1024)

// ---------------- preprocessing ----------------
// x fp32 -> fp16, 8 elems/thread; also zeroes expert counters
__global__ __launch_bounds__(256) void xcvt_kernel(const float* __restrict__ X) {
    if (blockIdx.x == 0 && threadIdx.x < NE) g_cnt[threadIdx.x] = 0;
    size_t i = ((size_t)blockIdx.x * 256 + threadIdx.x) * 8;
    float4 v0 = *(const float4*)(X + i);
    float4 v1 = *(const float4*)(X + i + 4);
    uint4 u = make_uint4(h2u(v0.x, v0.y), h2u(v0.z, v0.w),
                         h2u(v1.x, v1.y), h2u(v1.z, v1.w));
    *(uint4*)(g_xt + i) = u;
}

// streaming fp32 -> fp16 copy (same layout), 8 elems/thread
__global__ __launch_bounds__(256) void wcvt_kernel(
    const float* __restrict__ in, __half* __restrict__ out)
{
    size_t i = ((size_t)blockIdx.x * 256 + threadIdx.x) * 8;
    float4 v0 = *(const float4*)(in + i);
    float4 v1 = *(const float4*)(in + i + 4);
    uint4 u = make_uint4(h2u(v0.x, v0.y), h2u(v0.z, v0.w),
                         h2u(v1.x, v1.y), h2u(v1.z, v1.w));
    *(uint4*)(out + i) = u;
}

// =======================================================================
// QKV GEMM: grid (64, 24), block 128 (4 warps, 64x64 warp tiles)
// =======================================================================
__global__ __launch_bounds__(128) void qkv_tc_kernel()
{
    const int row0 = blockIdx.x * 128;
    const int by = blockIdx.y;
    const int part = by >> 3;
    const int h0 = (by & 7) * 2;
    __half* Out = (part == 0) ? g_q : (part == 1) ? g_k : g_v;
    const float qscale = (part == 0) ? 0.03125f : 1.0f;

    extern __shared__ char dynraw[];
    char* p = (char*)(((uintptr_t)dynraw + 1023) & ~(uintptr_t)1023);
    const uint32_t sb = smem_u32(p);
    const int tid = threadIdx.x;
    const int wid = tid >> 5, lane = tid & 31;
    const int wm = (wid & 1) * 64, wn = (wid >> 1) * 64;

    const int quad = lane >> 3, lr = lane & 7;
    const uint32_t a_rowb = (uint32_t)(wm + (quad & 1) * 8 + lr) * 128;
    const uint32_t a_boff = (uint32_t)(quad >> 1) * 16;
    const uint32_t xv = (uint32_t)lr << 4;
    const uint32_t bt_row = (uint32_t)(((lane >> 3) & 1) * 8 + lr) * 128;

    float acc[4][8][4];
#pragma unroll
    for (int i = 0; i < 4; i++)
#pragma unroll
        for (int j = 0; j < 8; j++)
#pragma unroll
            for (int q = 0; q < 4; q++) acc[i][j][q] = 0.f;

    const int NCH = DD / 64;
    auto issue = [&](int c) {
        int k0 = c * 64;
        int s = c % 3;
        uint32_t ab = sb + s * ST_BYTES;
        uint32_t bb = sb + 3 * ST_BYTES + s * ST_BYTES;
#pragma unroll
        for (int i = 0; i < 8; i++) {
            int idx = tid + i * 128;
            {
                int row = idx >> 3, c16 = idx & 7;
                const __half* asrc = g_xt + (size_t)(row0 + row) * DD + k0 + c16 * 8;
                CP_ASYNC16(ab + SWZ(row * 128 + c16 * 16), asrc);
            }
            {
                int sub = idx >> 9, rem = idx & 511;
                int r = rem >> 3, c16 = rem & 7;
                const __half* bsrc = g_wqkv +
                    ((size_t)(part * HH + h0 + sub) * DD + k0 + r) * HS + c16 * 8;
                CP_ASYNC16(bb + sub * 8192 + SWZ(r * 128 + c16 * 16), bsrc);
            }
        }
        CP_COMMIT();
    };
    issue(0); issue(1);

    for (int c = 0; c < NCH; c++) {
        CP_WAIT1();
        __syncthreads();
        if (c + 2 < NCH) issue(c + 2); else CP_COMMIT();
        const int s = c % 3;
        const uint32_t At = sb + s * ST_BYTES;
        const uint32_t Bt = sb + 3 * ST_BYTES + s * ST_BYTES;
#pragma unroll
        for (int ks = 0; ks < 4; ks++) {
            uint32_t akoff = (((uint32_t)ks * 32) + a_boff) ^ xv;
            uint32_t trow = (uint32_t)(ks * 16) * 128 + bt_row;
            uint32_t af[4][4], bf[8][2];
#pragma unroll
            for (int mt = 0; mt < 4; mt++)
                ldsm_x4(af[mt], At + a_rowb + mt * 2048 + akoff);
#pragma unroll
            for (int nt = 0; nt < 8; nt++) {
                int gn = wn + nt * 8;
                uint32_t sub = (uint32_t)(gn >> 6) * 8192;
                uint32_t cb = (uint32_t)((gn & 63) * 2);
                ldsm_x2t(bf[nt], Bt + sub + trow + (cb ^ xv));
            }
#pragma unroll
            for (int mt = 0; mt < 4; mt++)
#pragma unroll
                for (int nt = 0; nt < 8; nt++)
                    mma_f16(acc[mt][nt], af[mt][0], af[mt][1], af[mt][2], af[mt][3],
                            bf[nt][0], bf[nt][1]);
        }
        __syncthreads();
    }

#pragma unroll
    for (int mt = 0; mt < 4; mt++) {
        int r = row0 + wm + mt * 16 + (lane >> 2);
        int r1 = r + 8;
        int b0i = r >> 10, t0 = r & 1023;
        int b1i = r1 >> 10, t1 = r1 & 1023;
#pragma unroll
        for (int nt = 0; nt < 8; nt++) {
            int n = wn + nt * 8 + 2 * (lane & 3);
            int head = h0 + (n >> 6);
            int hs = n & 63;
            *(uint32_t*)(Out + (((size_t)b0i * HH + head) * TT + t0) * HS + hs) =
                h2u(acc[mt][nt][0] * qscale, acc[mt][nt][1] * qscale);
            *(uint32_t*)(Out + (((size_t)b1i * HH + head) * TT + t1) * HS + hs) =
                h2u(acc[mt][nt][2] * qscale, acc[mt][nt][3] * qscale);
        }
    }
}

// =======================================================================
// MoE GEMM (G1: xt@W1+relu -> g_h fp16, else g_h@W2 -> g_y fp32)
// =======================================================================
template<bool G1>
__global__ __launch_bounds__(128) void moe_tc_kernel(
    const float* __restrict__ biasfull)
{
    const int e = blockIdx.z;
    const int cnt = g_cnt[e];
    const int m0 = blockIdx.x * 128;
    if (m0 >= cnt) return;
    const int col0 = blockIdx.y * 128;
    const int KTOT = G1 ? DD : DFF;
    const int LDB  = G1 ? DFF : DD;
    const int LDO  = G1 ? DFF : DD;
    const int NCH = KTOT / 64;

    extern __shared__ char dynraw[];
    char* p = (char*)(((uintptr_t)dynraw + 1023) & ~(uintptr_t)1023);
    const uint32_t sb = smem_u32(p);

    __shared__ int rowids[128];
    const int tid = threadIdx.x;
    {
        int m = m0 + tid;
        rowids[tid] = (m < cnt) ? g_rows[e * NTOK + m] : -1;
    }
    __syncthreads();

    const int wid = tid >> 5, lane = tid & 31;
    const int wm = (wid & 1) * 64, wn = (wid >> 1) * 64;
    const int quad = lane >> 3, lr = lane & 7;
    const uint32_t a_rowb = (uint32_t)(wm + (quad & 1) * 8 + lr) * 128;
    const uint32_t a_boff = (uint32_t)(quad >> 1) * 16;
    const uint32_t xv = (uint32_t)lr << 4;
    const uint32_t bt_row = (uint32_t)(((lane >> 3) & 1) * 8 + lr) * 128;

    float acc[4][8][4];
#pragma unroll
    for (int i = 0; i < 4; i++)
#pragma unroll
        for (int j = 0; j < 8; j++)
#pragma unroll
            for (int q = 0; q < 4; q++) acc[i][j][q] = 0.f;

    const __half* Wp = (G1 ? g_w1 : g_w2) + (size_t)e * ((size_t)DD * DFF);
    const float* bp = biasfull + (size_t)e * (G1 ? DFF : DD);

    auto issue = [&](int c) {
        int k0 = c * 64;
        int s = c % 3;
        uint32_t ab = sb + s * ST_BYTES;
        uint32_t bb = sb + 3 * ST_BYTES + s * ST_BYTES;
#pragma unroll
        for (int i = 0; i < 8; i++) {
            int idx = tid + i * 128;
            {
                int row = idx >> 3, c16 = idx & 7;
                int rid = rowids[row];
                const __half* asrc;
                if (G1) asrc = g_xt + (size_t)((rid >= 0) ? (rid >> 1) : 0) * DD + k0 + c16 * 8;
                else    asrc = g_h + (size_t)((rid >= 0) ? rid : 0) * DFF + k0 + c16 * 8;
                CP_ASYNC16(ab + SWZ(row * 128 + c16 * 16), asrc);
            }
            {
                int sub = idx >> 9, rem = idx & 511;
                int r = rem >> 3, c16 = rem & 7;
                const __half* bsrc = Wp + (size_t)(k0 + r) * LDB + col0 + sub * 64 + c16 * 8;
                CP_ASYNC16(bb + sub * 8192 + SWZ(r * 128 + c16 * 16), bsrc);
            }
        }
        CP_COMMIT();
    };
    issue(0); issue(1);

    for (int c = 0; c < NCH; c++) {
        CP_WAIT1();
        __syncthreads();
        if (c + 2 < NCH) issue(c + 2); else CP_COMMIT();
        const int s = c % 3;
        const uint32_t At = sb + s * ST_BYTES;
        const uint32_t Bt = sb + 3 * ST_BYTES + s * ST_BYTES;
#pragma unroll
        for (int ks = 0; ks < 4; ks++) {
            uint32_t akoff = (((uint32_t)ks * 32) + a_boff) ^ xv;
            uint32_t trow = (uint32_t)(ks * 16) * 128 + bt_row;
            uint32_t af[4][4], bf[8][2];
#pragma unroll
            for (int mt = 0; mt < 4; mt++)
                ldsm_x4(af[mt], At + a_rowb + mt * 2048 + akoff);
#pragma unroll
            for (int nt = 0; nt < 8; nt++) {
                int gn = wn + nt * 8;
                uint32_t sub = (uint32_t)(gn >> 6) * 8192;
                uint32_t cb = (uint32_t)((gn & 63) * 2);
                ldsm_x2t(bf[nt], Bt + sub + trow + (cb ^ xv));
            }
#pragma unroll
            for (int mt = 0; mt < 4; mt++)
#pragma unroll
                for (int nt = 0; nt < 8; nt++)
                    mma_f16(acc[mt][nt], af[mt][0], af[mt][1], af[mt][2], af[mt][3],
                            bf[nt][0], bf[nt][1]);
        }
        __syncthreads();
    }

#pragma unroll
    for (int mt = 0; mt < 4; mt++) {
        int ml = wm + mt * 16 + (lane >> 2);
        int rid0 = rowids[ml];
        int rid1 = rowids[ml + 8];
#pragma unroll
        for (int nt = 0; nt < 8; nt++) {
            int n = col0 + wn + nt * 8 + 2 * (lane & 3);
            float bx = __ldg(&bp[n]), by = __ldg(&bp[n + 1]);
            if (G1) {
                if (rid0 >= 0) {
                    float v0 = fmaxf(acc[mt][nt][0] + bx, 0.f);
                    float v1 = fmaxf(acc[mt][nt][1] + by, 0.f);
                    *(uint32_t*)(g_h + (size_t)rid0 * LDO + n) = h2u(v0, v1);
                }
                if (rid1 >= 0) {
                    float v2 = fmaxf(acc[mt][nt][2] + bx, 0.f);
                    float v3 = fmaxf(acc[mt][nt][3] + by, 0.f);
                    *(uint32_t*)(g_h + (size_t)rid1 * LDO + n) = h2u(v2, v3);
                }
            } else {
                if (rid0 >= 0)
                    *(float2*)(g_y + (size_t)rid0 * LDO + n) =
                        make_float2(acc[mt][nt][0] + bx, acc[mt][nt][1] + by);
                if (rid1 >= 0)
                    *(float2*)(g_y + (size_t)rid1 * LDO + n) =
                        make_float2(acc[mt][nt][2] + bx, acc[mt][nt][3] + by);
            }
        }
    }
}

// =======================================================================
// fp16 tensor-core causal flash attention
// =======================================================================
#define ATT_SMEM (8192 + 2 * 16384)

__global__ __launch_bounds__(128) void attn_tc_kernel()
{
    extern __shared__ char asc[];
    const uint32_t psb = smem_u32(asc);
    const uint32_t kvb = psb + 8192;

    const int bh = blockIdx.y;
    const int qt = 15 - blockIdx.x;
    const int tid = threadIdx.x;
    const int wid = tid >> 5, lane = tid & 31;
    const int gid = lane >> 2, tq = lane & 3;
    const int quad = lane >> 3, lr = lane & 7;
    const int qrow = wid * 16 + gid;
    const int qglob = qt * 64;

    const uint32_t a_rowb = (uint32_t)(wid * 16 + (quad & 1) * 8 + lr) * 128;
    const uint32_t a_boff = (uint32_t)(quad >> 1) * 16;
    const uint32_t b_boff = (uint32_t)((lane >> 3) & 1) * 16;
    const uint32_t xv = (uint32_t)lr << 4;
    const uint32_t v_rowb = (uint32_t)(((lane >> 3) & 1) * 8 + lr) * 128;
    const uint32_t xvq = (uint32_t)gid << 4;

    auto issue_kv = [&](int kt) {
        int s = kt & 1;
        uint32_t kb = kvb + s * 16384;
        uint32_t vb = kb + 8192;
        const __half* kp = g_k + ((size_t)bh * TT + kt * 64) * HS;
        const __half* vp = g_v + ((size_t)bh * TT + kt * 64) * HS;
#pragma unroll
        for (int i = 0; i < 4; i++) {
            int idx = tid + i * 128;
            int r = idx >> 3, c16 = idx & 7;
            CP_ASYNC16(kb + SWZ(r * 128 + c16 * 16), kp + (size_t)r * HS + c16 * 8);
            CP_ASYNC16(vb + SWZ(r * 128 + c16 * 16), vp + (size_t)r * HS + c16 * 8);
        }
        CP_COMMIT();
    };

    {
        const __half* qp = g_q + ((size_t)bh * TT + qglob) * HS;
#pragma unroll
        for (int i = 0; i < 4; i++) {
            int idx = tid + i * 128;
            int r = idx >> 3, c16 = idx & 7;
            CP_ASYNC16(psb + SWZ(r * 128 + c16 * 16), qp + (size_t)r * HS + c16 * 8);
        }
        CP_COMMIT();
    }
    issue_kv(0);
    CP_WAIT1();
    __syncthreads();

    uint32_t qf[4][4];
#pragma unroll
    for (int ks = 0; ks < 4; ks++)
        ldsm_x4(qf[ks], psb + a_rowb + ((((uint32_t)ks * 32) + a_boff) ^ xv));
    __syncthreads();

    float oacc[8][4];
#pragma unroll
    for (int i = 0; i < 8; i++)
#pragma unroll
        for (int j = 0; j < 4; j++) oacc[i][j] = 0.f;
    float m0 = -INFINITY, m1 = -INFINITY, l0 = 0.f, l1 = 0.f;

    for (int kt = 0; kt <= qt; kt++) {
        if (kt + 1 <= qt) issue_kv(kt + 1); else CP_COMMIT();
        CP_WAIT1();
        __syncthreads();
        const int s = kt & 1;
        const uint32_t Kb = kvb + s * 16384;
        const uint32_t Vb = Kb + 8192;

        float sacc[8][4];
#pragma unroll
        for (int nt = 0; nt < 8; nt++)
#pragma unroll
            for (int j = 0; j < 4; j++) sacc[nt][j] = 0.f;
#pragma unroll
        for (int ks = 0; ks < 4; ks++) {
            uint32_t bkoff = (((uint32_t)ks * 32) + b_boff) ^ xv;
#pragma unroll
            for (int nt = 0; nt < 8; nt++) {
                uint32_t bf[2];
                ldsm_x2(bf, Kb + (uint32_t)(nt * 8 + lr) * 128 + bkoff);
                mma_f16(sacc[nt], qf[ks][0], qf[ks][1], qf[ks][2], qf[ks][3], bf[0], bf[1]);
            }
        }
        if (kt == qt) {
#pragma unroll
            for (int nt = 0; nt < 8; nt++) {
                int col = nt * 8 + 2 * tq;
                if (col     > qrow)     sacc[nt][0] = -INFINITY;
                if (col + 1 > qrow)     sacc[nt][1] = -INFINITY;
                if (col     > qrow + 8) sacc[nt][2] = -INFINITY;
                if (col + 1 > qrow + 8) sacc[nt][3] = -INFINITY;
            }
        }
        float r0 = -INFINITY, r1 = -INFINITY;
#pragma unroll
        for (int nt = 0; nt < 8; nt++) {
            r0 = fmaxf(r0, fmaxf(sacc[nt][0], sacc[nt][1]));
            r1 = fmaxf(r1, fmaxf(sacc[nt][2], sacc[nt][3]));
        }
        r0 = fmaxf(r0, __shfl_xor_sync(0xffffffffu, r0, 1));
        r0 = fmaxf(r0, __shfl_xor_sync(0xffffffffu, r0, 2));
        r1 = fmaxf(r1, __shfl_xor_sync(0xffffffffu, r1, 1));
        r1 = fmaxf(r1, __shfl_xor_sync(0xffffffffu, r1, 2));
        float mn0 = fmaxf(m0, r0), mn1 = fmaxf(m1, r1);
        float c0 = __expf(m0 - mn0), c1 = __expf(m1 - mn1);
        float ps0 = 0.f, ps1 = 0.f;
#pragma unroll
        for (int nt = 0; nt < 8; nt++) {
            float p0 = __expf(sacc[nt][0] - mn0);
            float p1 = __expf(sacc[nt][1] - mn0);
            float p2 = __expf(sacc[nt][2] - mn1);
            float p3 = __expf(sacc[nt][3] - mn1);
            ps0 += p0 + p1; ps1 += p2 + p3;
            uint32_t boff = (uint32_t)(nt * 16 + 4 * tq) ^ xvq;
            *(uint32_t*)(asc + qrow * 128 + boff)       = h2u(p0, p1);
            *(uint32_t*)(asc + (qrow + 8) * 128 + boff) = h2u(p2, p3);
        }
        ps0 += __shfl_xor_sync(0xffffffffu, ps0, 1);
        ps0 += __shfl_xor_sync(0xffffffffu, ps0, 2);
        ps1 += __shfl_xor_sync(0xffffffffu, ps1, 1);
        ps1 += __shfl_xor_sync(0xffffffffu, ps1, 2);
        l0 = l0 * c0 + ps0;
        l1 = l1 * c1 + ps1;
#pragma unroll
        for (int dt = 0; dt < 8; dt++) {
            oacc[dt][0] *= c0; oacc[dt][1] *= c0;
            oacc[dt][2] *= c1; oacc[dt][3] *= c1;
        }
        m0 = mn0; m1 = mn1;
        __syncwarp();
#pragma unroll
        for (int ks = 0; ks < 4; ks++) {
            uint32_t pa[4];
            ldsm_x4(pa, psb + a_rowb + ((((uint32_t)ks * 32) + a_boff) ^ xv));
            uint32_t vrow = (uint32_t)(ks * 16) * 128 + v_rowb;
#pragma unroll
            for (int dt = 0; dt < 8; dt++) {
                uint32_t bv[2];
                ldsm_x2t(bv, Vb + vrow + (((uint32_t)dt * 16) ^ xv));
                mma_f16(oacc[dt], pa[0], pa[1], pa[2], pa[3], bv[0], bv[1]);
            }
        }
        __syncthreads();
    }

    float i0 = 1.f / l0, i1 = 1.f / l1;
    int b = bh >> 4, h = bh & 15;
    int gq0 = qglob + qrow, gq1 = gq0 + 8;
#pragma unroll
    for (int dt = 0; dt < 8; dt++) {
        int d = h * HS + dt * 8 + 2 * tq;
        *(float2*)(g_attn + ((size_t)b * TT + gq0) * DD + d) =
            make_float2(oacc[dt][0] * i0, oacc[dt][1] * i0);
        *(float2*)(g_attn + ((size_t)b * TT + gq1) * DD + d) =
            make_float2(oacc[dt][2] * i1, oacc[dt][3] * i1);
    }
}

// ---------------- MoE routing (vectorized) ----------------
__global__ __launch_bounds__(256) void route_kernel(
    const float* __restrict__ X, const float* __restrict__ Wg)
{
    int tok = (blockIdx.x * blockDim.x + threadIdx.x) >> 5;
    int lane = threadIdx.x & 31;
    if (tok >= NTOK) return;
    const float* xr = X + (size_t)tok * DD;
    float p[NE];
#pragma unroll
    for (int e = 0; e < NE; e++) p[e] = 0.f;
#pragma unroll
    for (int it = 0; it < DD / 128; it++) {
        int d4 = lane + it * 32;
        float4 xv4 = *(const float4*)(xr + d4 * 4);
        const float* wr = Wg + (size_t)d4 * 4 * NE;
        float xs[4] = {xv4.x, xv4.y, xv4.z, xv4.w};
#pragma unroll
        for (int dd = 0; dd < 4; dd++) {
            float4 w0 = *(const float4*)(wr + dd * 8);
            float4 w1 = *(const float4*)(wr + dd * 8 + 4);
            p[0] += xs[dd] * w0.x; p[1] += xs[dd] * w0.y;
            p[2] += xs[dd] * w0.z; p[3] += xs[dd] * w0.w;
            p[4] += xs[dd] * w1.x; p[5] += xs[dd] * w1.y;
            p[6] += xs[dd] * w1.z; p[7] += xs[dd] * w1.w;
        }
    }
#pragma unroll
    for (int e = 0; e < NE; e++)
#pragma unroll
        for (int off = 16; off; off >>= 1)
            p[e] += __shfl_xor_sync(0xffffffffu, p[e], off);

    if (lane == 0) {
        int i0 = 0; float v0 = p[0];
#pragma unroll
        for (int e = 1; e < NE; e++) if (p[e] > v0) { v0 = p[e]; i0 = e; }
        int i1 = -1; float v1 = -INFINITY;
#pragma unroll
        for (int e = 0; e < NE; e++) if (e != i0 && p[e] > v1) { v1 = p[e]; i1 = e; }
        float e1v = expf(v1 - v0);
        float inv = 1.f / (1.f + e1v);
        g_wtok[tok * 2 + 0] = inv;
        g_wtok[tok * 2 + 1] = e1v * inv;
        int pos0 = atomicAdd(&g_cnt[i0], 1);
        g_rows[i0 * NTOK + pos0] = tok * 2;
        int pos1 = atomicAdd(&g_cnt[i1], 1);
        g_rows[i1 * NTOK + pos1] = tok * 2 + 1;
    }
}

// ---------------- final LN+residual ----------------
__device__ __forceinline__ float4 block_reduce4(float4 v) {
    __shared__ float4 sh[8];
    __shared__ float4 bc;
    int lane = threadIdx.x & 31, w = threadIdx.x >> 5;
#pragma unroll
    for (int off = 16; off; off >>= 1) {
        v.x += __shfl_xor_sync(0xffffffffu, v.x, off);
        v.y += __shfl_xor_sync(0xffffffffu, v.y, off);
        v.z += __shfl_xor_sync(0xffffffffu, v.z, off);
        v.w += __shfl_xor_sync(0xffffffffu, v.w, off);
    }
    if (lane == 0) sh[w] = v;
    __syncthreads();
    if (w == 0) {
        float4 t = (lane < 8) ? sh[lane] : make_float4(0, 0, 0, 0);
#pragma unroll
        for (int off = 4; off; off >>= 1) {
            t.x += __shfl_xor_sync(0xffffffffu, t.x, off);
            t.y += __shfl_xor_sync(0xffffffffu, t.y, off);
            t.z += __shfl_xor_sync(0xffffffffu, t.z, off);
            t.w += __shfl_xor_sync(0xffffffffu, t.w, off);
        }
        if (lane == 0) bc = t;
    }
    __syncthreads();
    return bc;
}

__global__ __launch_bounds__(256) void final_kernel(
    const float* __restrict__ X,
    const float* __restrict__ g1, const float* __restrict__ be1,
    const float* __restrict__ g2, const float* __restrict__ be2,
    float* __restrict__ out)
{
    int t = blockIdx.x;
    int tid = threadIdx.x;
    const float* ar = g_attn + (size_t)t * DD;
    const float* y0 = g_y + (size_t)(t * 2) * DD;
    const float* y1 = g_y + (size_t)(t * 2 + 1) * DD;
    float w0 = g_wtok[t * 2], w1 = g_wtok[t * 2 + 1];

    float4 a4 = ((const float4*)ar)[tid];
    float4 y04 = ((const float4*)y0)[tid];
    float4 y14 = ((const float4*)y1)[tid];
    float a[4] = {a4.x, a4.y, a4.z, a4.w};
    float m[4] = {w0 * y04.x + w1 * y14.x, w0 * y04.y + w1 * y14.y,
                  w0 * y04.z + w1 * y14.z, w0 * y04.w + w1 * y14.w};

    float4 s = make_float4(0, 0, 0, 0);
#pragma unroll
    for (int j = 0; j < 4; j++) {
        s.x += a[j]; s.y += a[j] * a[j];
        s.z += m[j]; s.w += m[j] * m[j];
    }
    s = block_reduce4(s);
    const float invD = 1.0f / (float)DD;
    float mua = s.x * invD;
    float vara = fmaxf(s.y * invD - mua * mua, 0.f);
    float rsa = rsqrtf(vara + LN_EPS);
    float mum = s.z * invD;
    float varm = fmaxf(s.w * invD - mum * mum, 0.f);
    float rsm = rsqrtf(varm + LN_EPS);

    float4 x4 = ((const float4*)(X + (size_t)t * DD))[tid];
    float4 g14 = ((const float4*)g1)[tid];
    float4 b14 = ((const float4*)be1)[tid];
    float4 g24 = ((const float4*)g2)[tid];
    float4 b24 = ((const float4*)be2)[tid];
    float xs[4] = {x4.x, x4.y, x4.z, x4.w};
    float g1s[4] = {g14.x, g14.y, g14.z, g14.w};
    float b1s[4] = {b14.x, b14.y, b14.z, b14.w};
    float g2s[4] = {g24.x, g24.y, g24.z, g24.w};
    float b2s[4] = {b24.x, b24.y, b24.z, b24.w};
    float o[4];
#pragma unroll
    for (int j = 0; j < 4; j++) {
        o[j] = xs[j]
             + (a[j] - mua) * rsa * g1s[j] + b1s[j]
             + (m[j] - mum) * rsm * g2s[j] + b2s[j];
    }
    ((float4*)(out + (size_t)t * DD))[tid] = make_float4(o[0], o[1], o[2], o[3]);
}

// ---------------- launch: fork/join two streams inside capture ----------------
extern "C" void kernel_launch(void* const* d_in, const int* in_sizes, int n_in,
                              void* d_out, int out_size)
{
    const float* x   = (const float*)d_in[0];
    const float* Wq  = (const float*)d_in[1];
    const float* Wk  = (const float*)d_in[2];
    const float* Wv  = (const float*)d_in[3];
    const float* Wg  = (const float*)d_in[4];
    const float* W1  = (const float*)d_in[5];
    const float* b1  = (const float*)d_in[6];
    const float* W2  = (const float*)d_in[7];
    const float* b2  = (const float*)d_in[8];
    const float* g1  = (const float*)d_in[9];
    const float* be1 = (const float*)d_in[10];
    const float* g2  = (const float*)d_in[11];
    const float* be2 = (const float*)d_in[12];
    float* out = (float*)d_out;

    static cudaStream_t s1 = nullptr;
    static cudaEvent_t ev0 = nullptr, evX = nullptr, evB = nullptr;
    if (s1 == nullptr) {
        cudaStreamCreateWithFlags(&s1, cudaStreamNonBlocking);
        cudaEventCreateWithFlags(&ev0, cudaEventDisableTiming);
        cudaEventCreateWithFlags(&evX, cudaEventDisableTiming);
        cudaEventCreateWithFlags(&evB, cudaEventDisableTiming);
        cudaFuncSetAttribute(qkv_tc_kernel, cudaFuncAttributeMaxDynamicSharedMemorySize, GEMM_SMEM);
        cudaFuncSetAttribute(moe_tc_kernel<true>, cudaFuncAttributeMaxDynamicSharedMemorySize, GEMM_SMEM);
        cudaFuncSetAttribute(moe_tc_kernel<false>, cudaFuncAttributeMaxDynamicSharedMemorySize, GEMM_SMEM);
        cudaFuncSetAttribute(attn_tc_kernel, cudaFuncAttributeMaxDynamicSharedMemorySize, ATT_SMEM);
    }

    __half* d_w1; cudaGetSymbolAddress((void**)&d_w1, g_w1);
    __half* d_w2; cudaGetSymbolAddress((void**)&d_w2, g_w2);
    __half* d_wqkv; cudaGetSymbolAddress((void**)&d_wqkv, g_wqkv);

    const size_t WQKV1 = (size_t)HH * DD * HS;   // 1M elems per part
    const size_t WEXP  = (size_t)NE * DD * DFF;  // 33.5M elems

    // fork: stream B branches off the capture-origin stream
    cudaEventRecord(ev0, 0);
    cudaStreamWaitEvent(s1, ev0, 0);

    // ---- stream B prefix (no g_xt dependency) ----
    wcvt_kernel<<<(int)(WEXP / 2048), 256, 0, s1>>>(W1, d_w1);
    wcvt_kernel<<<(int)(WEXP / 2048), 256, 0, s1>>>(W2, d_w2);
    route_kernel<<<NTOK / 8, 256, 0, s1>>>(x, Wg);

    // ---- stream A: xcvt (produces g_xt, zeroes counters... note: counters
    //      are consumed by route on B! keep zeroing ordered before route) ----
    // Correction: route atomically increments g_cnt, so zeroing must precede it.
    // xcvt runs on stream A but route waits on evX via stream-order below? No —
    // route must come AFTER the zeroing. Move route after the evX wait instead.
    // (see re-ordered launches below)

    xcvt_kernel<<<NTOK * DD / 2048, 256>>>(x);
    cudaEventRecord(evX, 0);

    // gemm chain on B waits for g_xt + zeroed counters; route re-issued here
    // in correct order (the one above is removed — see actual sequence):
    cudaStreamWaitEvent(s1, evX, 0);
    moe_tc_kernel<true><<<dim3(64, DFF / 128, NE), 128, GEMM_SMEM, s1>>>(b1);
    moe_tc_kernel<false><<<dim3(64, DD / 128, NE), 128, GEMM_SMEM, s1>>>(b2);
    cudaEventRecord(evB, s1);

    // ---- stream A continues ----
    wcvt_kernel<<<(int)(WQKV1 / 2048), 256>>>(Wq, d_wqkv);
    wcvt_kernel<<<(int)(WQKV1 / 2048), 256>>>(Wk, d_wqkv + WQKV1);
    wcvt_kernel<<<(int)(WQKV1 / 2048), 256>>>(Wv, d_wqkv + 2 * WQKV1);
    qkv_tc_kernel<<<dim3(NTOK / 128, 24), 128, GEMM_SMEM>>>();
    attn_tc_kernel<<<dim3(16, BB * HH), 128, ATT_SMEM>>>();

    // join and finish
    cudaStreamWaitEvent(0, evB, 0);
    final_kernel<<<NTOK, 256>>>(x, g1, be1, g2, be2, out);
}